// round 12
// baseline (speedup 1.0000x reference)
#include <cuda_runtime.h>
#include <cuda_fp16.h>
#include <cstdint>

#define C      128
#define KNBR   27
#define TMW    256                    // GEMM tile rows (M per CTA)
#define NMAX   300000
#define N_WMAT 191                    // 162 W_res + 27 W_out + Wf1 + Wf2
#define CAP    16384                  // per-k pair list capacity (expect ~5.4k)
#define NSEG   27
#define SCR_ROWS (1 << 21)            // scratch rows (expect ~141k)
#define NBMAX  512
#define PSP    5                      // persistent CTAs per k (sparse): 135 CTAs
#define GDMAX  148                    // persistent CTAs (dense), 1 x 512t/SM

#define NT     512                    // threads per GEMM CTA (16 warps)
#define PITCH  80                     // A: bytes per 32-half row (16B padded)
#define PLANE2 20480                  // A: 256 * PITCH (lo-plane offset)
#define ASZ2   40960                  // A stage: hi+lo planes (256 rows)
#define BPITCH 528                    // B-full: 512B row + 16B pad (bank shift)
#define BFULL  67584                  // 128 * BPITCH
#define DN2_SMEM (BFULL + 3 * ASZ2)          // 190464
#define SP2_SMEM (BFULL + 4096 + 3 * ASZ2)   // 194560

// activations: per row 256 halfs, per 32-ci chunk: [hi32 | lo32] x4
__device__ __half g_actA[(size_t)NMAX * 256];
__device__ __half g_actB[(size_t)NMAX * 256];
// weights: per mat 32768 halfs, [co][ci chunks interleaved hi/lo]
__device__ __half g_Wt[(size_t)N_WMAT * 32768];
// sparse-pair machinery (m-sorted scratch slots, scan-based — no atomics)
__device__ float         g_scr[(size_t)SCR_ROWS * C];
__device__ unsigned      g_cnt[NSEG];
__device__ int           g_pairg[NSEG * CAP];   // source row per pair
__device__ int           g_slot[NSEG * CAP];    // scratch row per pair
__device__ int           g_mbase[NMAX];         // first scratch row of m
__device__ unsigned char g_mcnt[NMAX];          // valid non-self count of m
__device__ int           g_bsum[NBMAX];
__device__ int           g_boff[NBMAX];
__device__ int           g_kcnt[NSEG * NBMAX];  // [k][block] counts (transposed)
__device__ int           g_kbase[NSEG * NBMAX]; // [k][block] exclusive scan

// ---------------------------------------------------------------------------
static __device__ __forceinline__ void cp_async16_cg(uint32_t dst, const void* src, bool pred) {
    int sz = pred ? 16 : 0;
    asm volatile("cp.async.cg.shared.global [%0], [%1], 16, %2;"
                 :: "r"(dst), "l"(src), "r"(sz) : "memory");
}
static __device__ __forceinline__ void cp_async16_ca(uint32_t dst, const void* src, bool pred) {
    int sz = pred ? 16 : 0;
    asm volatile("cp.async.ca.shared.global [%0], [%1], 16, %2;"
                 :: "r"(dst), "l"(src), "r"(sz) : "memory");
}
#define CP_COMMIT() asm volatile("cp.async.commit_group;" ::: "memory")
template <int N> static __device__ __forceinline__ void cp_wait() {
    asm volatile("cp.async.wait_group %0;" :: "n"(N) : "memory");
}
static __device__ __forceinline__ uint32_t smem_u32(const void* p) {
    uint32_t a;
    asm("{ .reg .u64 t; cvta.to.shared.u64 t, %1; cvt.u32.u64 %0, t; }"
        : "=r"(a) : "l"(p));
    return a;
}
static __device__ __forceinline__ void mma_f16(float* c, const uint32_t* a,
                                               uint32_t b0, uint32_t b1) {
    asm volatile(
        "mma.sync.aligned.m16n8k16.row.col.f32.f16.f16.f32 "
        "{%0,%1,%2,%3}, {%4,%5,%6,%7}, {%8,%9}, {%0,%1,%2,%3};"
        : "+f"(c[0]), "+f"(c[1]), "+f"(c[2]), "+f"(c[3])
        : "r"(a[0]), "r"(a[1]), "r"(a[2]), "r"(a[3]), "r"(b0), "r"(b1));
}
static __device__ __forceinline__ void ldsm4(uint32_t* r, uint32_t addr) {
    asm volatile("ldmatrix.sync.aligned.m8n8.x4.shared.b16 {%0,%1,%2,%3}, [%4];"
                 : "=r"(r[0]), "=r"(r[1]), "=r"(r[2]), "=r"(r[3]) : "r"(addr));
}
static __device__ __forceinline__ void split2(float v, __half& h, __half& l) {
    h = __float2half_rn(v);
    l = __float2half_rn(v - __half2float(h));
}

// ---------------------------------------------------------------------------
// 3-term inner loop for one 32-ci chunk (M=256 tile, 16 warps).
// rg in 0..7 (32-row groups), cg in 0..1 (64-col groups).
// ---------------------------------------------------------------------------
static __device__ __forceinline__ void gemm_chunk_p(uint32_t smA, uint32_t smB, int cc,
                                                    int rg, int cg, int lane,
                                                    float acc[2][8][4])
{
    const int arow = lane & 15, asel = (lane >> 4) & 1;
    const int brow = (lane & 7) + ((lane >> 4) & 1) * 8;
    const int bsel = (lane >> 3) & 1;
#pragma unroll
    for (int ks = 0; ks < 2; ks++) {
        uint32_t aaddr = smA + (rg * 32 + arow) * PITCH + ks * 32 + asel * 16;
        uint32_t baddr = smB + (cg * 64 + brow) * BPITCH + cc * 128 + ks * 32 + bsel * 16;
        uint32_t ah[2][4], al[2][4], bf[4][4];
        ldsm4(ah[0], aaddr);
        ldsm4(ah[1], aaddr + 16 * PITCH);
        ldsm4(al[0], aaddr + PLANE2);
        ldsm4(al[1], aaddr + PLANE2 + 16 * PITCH);
#pragma unroll
        for (int t = 0; t < 4; t++) ldsm4(bf[t], baddr + t * 16 * BPITCH);
#pragma unroll
        for (int t = 0; t < 4; t++)
#pragma unroll
            for (int h = 0; h < 2; h++) {
                int nt = t * 2 + h;
                mma_f16(acc[0][nt], ah[0], bf[t][2 * h], bf[t][2 * h + 1]);
                mma_f16(acc[1][nt], ah[1], bf[t][2 * h], bf[t][2 * h + 1]);
                mma_f16(acc[0][nt], al[0], bf[t][2 * h], bf[t][2 * h + 1]);
                mma_f16(acc[1][nt], al[1], bf[t][2 * h], bf[t][2 * h + 1]);
            }
#pragma unroll
        for (int t = 0; t < 4; t++) ldsm4(bf[t], baddr + 64 + t * 16 * BPITCH);
#pragma unroll
        for (int t = 0; t < 4; t++)
#pragma unroll
            for (int h = 0; h < 2; h++) {
                int nt = t * 2 + h;
                mma_f16(acc[0][nt], ah[0], bf[t][2 * h], bf[t][2 * h + 1]);
                mma_f16(acc[1][nt], ah[1], bf[t][2 * h], bf[t][2 * h + 1]);
            }
    }
}

// ---------------------------------------------------------------------------
// Weight prepass: transpose [ci][co] -> [co][ci], split fp16 hi/lo interleaved
// ---------------------------------------------------------------------------
__global__ void prep_w_kernel(const float* __restrict__ W_res,
                              const float* __restrict__ W_out,
                              const float* __restrict__ Wf1,
                              const float* __restrict__ Wf2)
{
    __shared__ float t[32][33];
    const int b = blockIdx.x;
    const float* src;
    if (b < 162)       src = W_res + (size_t)b * C * C;
    else if (b < 189)  src = W_out + (size_t)(b - 162) * C * C;
    else if (b == 189) src = Wf1;
    else               src = Wf2;
    __half* dst = g_Wt + ((size_t)b << 15);

    const int j = threadIdx.x & 31, i0 = threadIdx.x >> 5;
    for (int tile = 0; tile < 16; tile++) {
        const int tr = tile >> 2, tc = tile & 3;
        __syncthreads();
#pragma unroll
        for (int p = 0; p < 4; p++)
            t[i0 + p * 8][j] = src[(tr * 32 + i0 + p * 8) * C + tc * 32 + j];
        __syncthreads();
#pragma unroll
        for (int p = 0; p < 4; p++) {
            int co = tc * 32 + i0 + p * 8;
            float w = t[j][i0 + p * 8];
            __half h, l; split2(w, h, l);
            size_t o = (size_t)co * 256 + tr * 64 + j;
            dst[o] = h;
            dst[o + 32] = l;
        }
    }
}

// ---------------------------------------------------------------------------
// Pair prepass (atomic-free)
// ---------------------------------------------------------------------------
__global__ __launch_bounds__(1024)
void count_scan_kernel(const int* __restrict__ nbr, int n)
{
    __shared__ int wsum[32];
    __shared__ int s_wk[NSEG * 32];
    const int tid = threadIdx.x, lane = tid & 31, wid = tid >> 5;
    const int m = blockIdx.x * 1024 + tid;

    unsigned valid27 = 0;
    if (m < n) {
        const int* np = nbr + (size_t)m * KNBR;
#pragma unroll
        for (int k = 0; k < KNBR; k++)
            if (k != 13 && np[k] >= 0) valid27 |= (1u << k);
    }
    int cnt = __popc(valid27);

#pragma unroll
    for (int k = 0; k < KNBR; k++) {
        if (k == 13) continue;
        unsigned ball = __ballot_sync(0xFFFFFFFFu, (valid27 >> k) & 1u);
        if (lane == 0) s_wk[k * 32 + wid] = __popc(ball);
    }

    int v = cnt;
#pragma unroll
    for (int o = 1; o < 32; o <<= 1) {
        int u = __shfl_up_sync(0xFFFFFFFFu, v, o);
        if (lane >= o) v += u;
    }
    if (lane == 31) wsum[wid] = v;
    __syncthreads();
    if (wid == 0) {
        int w = wsum[lane], iv = w;
#pragma unroll
        for (int o = 1; o < 32; o <<= 1) {
            int u = __shfl_up_sync(0xFFFFFFFFu, iv, o);
            if (lane >= o) iv += u;
        }
        wsum[lane] = iv - w;
    }
    __syncthreads();
    int pre = wsum[wid] + v - cnt;
    if (m < n) {
        g_mcnt[m] = (unsigned char)cnt;
        g_mbase[m] = pre;
    }
    if (tid == 1023) g_bsum[blockIdx.x] = pre + cnt;

    if (wid < NSEG && wid != 13) {
        int t = s_wk[wid * 32 + lane];
#pragma unroll
        for (int o = 16; o > 0; o >>= 1) t += __shfl_down_sync(0xFFFFFFFFu, t, o);
        if (lane == 0) g_kcnt[wid * NBMAX + blockIdx.x] = t;
    }
}

__global__ __launch_bounds__(1024)
void scan_bsum_kernel(int nb)
{
    __shared__ int s[512];
    const int tid = threadIdx.x, lane = tid & 31, w = tid >> 5;
    int v = 0;
    if (tid < 512) {
        v = (tid < nb) ? g_bsum[tid] : 0;
        s[tid] = v;
    }
    __syncthreads();
    for (int off = 1; off < 512; off <<= 1) {
        int u = (tid < 512 && tid >= off) ? s[tid - off] : 0;
        __syncthreads();
        if (tid < 512) s[tid] += u;
        __syncthreads();
    }
    if (tid < 512 && tid < nb) g_boff[tid] = s[tid] - v;

    if (w < NSEG && w != 13) {
        int run = 0;
        for (int b0 = 0; b0 < nb; b0 += 32) {
            int b = b0 + lane;
            int x = (b < nb) ? g_kcnt[w * NBMAX + b] : 0;
            int inc = x;
#pragma unroll
            for (int o = 1; o < 32; o <<= 1) {
                int u = __shfl_up_sync(0xFFFFFFFFu, inc, o);
                if (lane >= o) inc += u;
            }
            if (b < nb) g_kbase[w * NBMAX + b] = run + inc - x;
            run += __shfl_sync(0xFFFFFFFFu, inc, 31);
        }
        if (lane == 0) g_cnt[w] = (unsigned)run;
    }
    if (tid == 0) g_cnt[13] = 0;
}

__global__ __launch_bounds__(1024)
void emit_pairs_kernel(const int* __restrict__ nbr, int n)
{
    __shared__ int s_wk[NSEG * 32];
    __shared__ int s_kb[NSEG];
    const int tid = threadIdx.x, lane = tid & 31, wid = tid >> 5;
    const int m = blockIdx.x * 1024 + tid;

    unsigned valid27 = 0;
    if (m < n) {
        const int* np = nbr + (size_t)m * KNBR;
#pragma unroll
        for (int k = 0; k < KNBR; k++)
            if (k != 13 && np[k] >= 0) valid27 |= (1u << k);
    }
#pragma unroll
    for (int k = 0; k < KNBR; k++) {
        if (k == 13) continue;
        unsigned ball = __ballot_sync(0xFFFFFFFFu, (valid27 >> k) & 1u);
        if (lane == 0) s_wk[k * 32 + wid] = __popc(ball);
    }
    if (tid < NSEG) s_kb[tid] = (tid != 13) ? g_kbase[tid * NBMAX + blockIdx.x] : 0;
    __syncthreads();

    if (wid < NSEG && wid != 13) {
        int v = s_wk[wid * 32 + lane], orig = v;
#pragma unroll
        for (int o = 1; o < 32; o <<= 1) {
            int u = __shfl_up_sync(0xFFFFFFFFu, v, o);
            if (lane >= o) v += u;
        }
        s_wk[wid * 32 + lane] = v - orig;
    }
    __syncthreads();

    int base = 0;
    if (m < n) base = g_boff[m >> 10] + g_mbase[m];
    const unsigned lt = (1u << lane) - 1u;
    int j = 0;
#pragma unroll
    for (int k = 0; k < KNBR; k++) {
        if (k == 13) continue;
        bool valid = (valid27 >> k) & 1u;
        unsigned ball = __ballot_sync(0xFFFFFFFFu, valid);
        if (valid) {
            int pos = s_kb[k] + s_wk[k * 32 + wid] + __popc(ball & lt);
            if (pos < CAP && base + j < SCR_ROWS) {
                g_pairg[k * CAP + pos] = nbr[(size_t)m * KNBR + k];
                g_slot[k * CAP + pos] = base + j;
            }
            j++;
        }
    }
    if (m < n) g_mbase[m] = base;
}

// ---------------------------------------------------------------------------
// Phase 1 (persistent, B-stationary, M=256, 3-stage single-barrier, 16 warps):
// per-k pair GEMM -> fp32 scratch rows (m-sorted slots)
// ---------------------------------------------------------------------------
__global__ __launch_bounds__(NT, 1)
void sparse_mma_p(const __half* __restrict__ in, const __half* __restrict__ WtLayer)
{
    const int k = blockIdx.x % NSEG;
    const int c = blockIdx.x / NSEG;
    unsigned cnt = g_cnt[k];
    if (cnt > CAP) cnt = CAP;
    const int ntk = (int)((cnt + TMW - 1) / TMW);
    const int mytiles = (ntk - c + PSP - 1) / PSP;
    if (mytiles <= 0) return;
    const int total = 4 * mytiles;

    extern __shared__ char smem[];
    const uint32_t sb = smem_u32(smem);
    const int tid = threadIdx.x, wid = tid >> 5, lane = tid & 31;
    const int lr = lane >> 2, lc = lane & 3;
    const int rg = wid & 7, cg = wid >> 3;

    int (*s_g)[TMW] = (int(*)[TMW])(smem + BFULL);
    int (*s_s)[TMW] = (int(*)[TMW])(smem + BFULL + 2048);
    const uint32_t ABASE = sb + BFULL + 4096;
    const __half* Wk = WtLayer + ((size_t)k << 15);

    auto load_idx = [&](int tl) {
        if (tid < TMW) {
            int p = (c + tl * PSP) * TMW + tid;
            int buf = tl & 1;
            s_g[buf][tid] = (p < (int)cnt) ? g_pairg[k * CAP + p] : -1;
            s_s[buf][tid] = (p < (int)cnt) ? g_slot[k * CAP + p] : -1;
        }
    };

    auto produce = [&](int q) {
        const int tl = q >> 2, cc = q & 3, buf = tl & 1;
        const uint32_t stA = ABASE + (q % 3) * ASZ2;
#pragma unroll
        for (int i = 0; i < 4; i++) {          // A: 2048 x 16B
            int u = tid + NT * i;
            int r = u >> 3, qq = u & 7;
            int idx = s_g[buf][r];
            const __half* src = in + (size_t)(idx < 0 ? 0 : idx) * 256 + cc * 64 + qq * 8;
            uint32_t dst = stA + ((qq & 4) ? PLANE2 : 0) + r * PITCH + (qq & 3) * 16;
            cp_async16_ca(dst, src, idx >= 0);
        }
        if (q == 0) {
#pragma unroll
            for (int i = 0; i < 8; i++) {      // B: 4096 x 16B
                int u = tid + NT * i;
                int r = u >> 5, qq = u & 31;
                cp_async16_cg(sb + r * BPITCH + qq * 16, Wk + (size_t)r * 256 + qq * 8, true);
            }
        }
        CP_COMMIT();
    };

    float acc[2][8][4];
#pragma unroll
    for (int mt = 0; mt < 2; mt++)
#pragma unroll
        for (int nt = 0; nt < 8; nt++)
#pragma unroll
            for (int j = 0; j < 4; j++) acc[mt][nt][j] = 0.f;

    load_idx(0);
    __syncthreads();
    produce(0);
    if (total > 1) produce(1);

    for (int jj = 0; jj < total; jj++) {
        if (jj == total - 1) cp_wait<0>(); else cp_wait<1>();
        __syncthreads();
        if (jj + 2 < total) produce(jj + 2);
        gemm_chunk_p(ABASE + (jj % 3) * ASZ2, sb, jj & 3, rg, cg, lane, acc);
        if ((jj & 3) == 0 && (jj >> 2) + 1 < mytiles) load_idx((jj >> 2) + 1);

        if ((jj & 3) == 3) {
            const int tl = jj >> 2, buf = tl & 1;
            const int base = (c + tl * PSP) * TMW;
#pragma unroll
            for (int mt = 0; mt < 2; mt++) {
#pragma unroll
                for (int hf = 0; hf < 2; hf++) {
                    int pr = rg * 32 + mt * 16 + hf * 8 + lr;
                    if (base + pr < (int)cnt) {
                        int slot = s_s[buf][pr];
                        if (slot >= 0) {
                            float* op = g_scr + (size_t)slot * C + cg * 64 + lc * 2;
#pragma unroll
                            for (int nt = 0; nt < 8; nt++)
                                *(float2*)(op + nt * 8) =
                                    make_float2(acc[mt][nt][hf * 2 + 0],
                                                acc[mt][nt][hf * 2 + 1]);
                        }
                    }
                }
            }
#pragma unroll
            for (int mt = 0; mt < 2; mt++)
#pragma unroll
                for (int nt = 0; nt < 8; nt++)
#pragma unroll
                    for (int j = 0; j < 4; j++) acc[mt][nt][j] = 0.f;
        }
    }
}

// ---------------------------------------------------------------------------
// Phase 2 (persistent, B-stationary, M=256, 3-stage single-barrier, 16 warps):
// dense self-term GEMM + fused combine epilogue
// ---------------------------------------------------------------------------
__global__ __launch_bounds__(NT, 1)
void dense_mma_p(const __half* __restrict__ in, __half* __restrict__ outAct,
                 const __half* __restrict__ Wk, const float* __restrict__ bias,
                 const __half* __restrict__ resid, int relu, int sparse,
                 int n, int ntiles)
{
    const int mytiles = (ntiles - (int)blockIdx.x + (int)gridDim.x - 1) / (int)gridDim.x;
    if (mytiles <= 0) return;
    const int total = 4 * mytiles;

    extern __shared__ char smem[];
    const uint32_t sb = smem_u32(smem);
    const int tid = threadIdx.x, wid = tid >> 5, lane = tid & 31;
    const int lr = lane >> 2, lc = lane & 3;
    const int rg = wid & 7, cg = wid >> 3;
    const uint32_t ABASE = sb + BFULL;

    auto produce = [&](int q) {
        const int tl = q >> 2, cc = q & 3;
        const int row0 = ((int)blockIdx.x + tl * (int)gridDim.x) * TMW;
        const uint32_t stA = ABASE + (q % 3) * ASZ2;
#pragma unroll
        for (int i = 0; i < 4; i++) {
            int u = tid + NT * i;
            int r = u >> 3, qq = u & 7;
            int idx = (row0 + r < n) ? row0 + r : -1;
            const __half* src = in + (size_t)(idx < 0 ? 0 : idx) * 256 + cc * 64 + qq * 8;
            uint32_t dst = stA + ((qq & 4) ? PLANE2 : 0) + r * PITCH + (qq & 3) * 16;
            cp_async16_cg(dst, src, idx >= 0);
        }
        if (q == 0) {
#pragma unroll
            for (int i = 0; i < 8; i++) {
                int u = tid + NT * i;
                int r = u >> 5, qq = u & 31;
                cp_async16_cg(sb + r * BPITCH + qq * 16, Wk + (size_t)r * 256 + qq * 8, true);
            }
        }
        CP_COMMIT();
    };

    float acc[2][8][4];
#pragma unroll
    for (int mt = 0; mt < 2; mt++)
#pragma unroll
        for (int nt = 0; nt < 8; nt++)
#pragma unroll
            for (int j = 0; j < 4; j++) acc[mt][nt][j] = 0.f;

    float2 bv[8];
#pragma unroll
    for (int nt = 0; nt < 8; nt++)
        bv[nt] = *(const float2*)(bias + cg * 64 + nt * 8 + lc * 2);

    produce(0);
    if (total > 1) produce(1);

    for (int jj = 0; jj < total; jj++) {
        if (jj == total - 1) cp_wait<0>(); else cp_wait<1>();
        __syncthreads();
        if (jj + 2 < total) produce(jj + 2);
        gemm_chunk_p(ABASE + (jj % 3) * ASZ2, sb, jj & 3, rg, cg, lane, acc);

        if ((jj & 3) == 3) {
            const int row0 = ((int)blockIdx.x + (jj >> 2) * (int)gridDim.x) * TMW;
#pragma unroll
            for (int mt = 0; mt < 2; mt++) {
#pragma unroll
                for (int hf = 0; hf < 2; hf++) {
                    int row = row0 + rg * 32 + mt * 16 + hf * 8 + lr;
                    if (row >= n) continue;
                    float v[8][2];
#pragma unroll
                    for (int nt = 0; nt < 8; nt++) {
                        v[nt][0] = acc[mt][nt][hf * 2 + 0] + bv[nt].x;
                        v[nt][1] = acc[mt][nt][hf * 2 + 1] + bv[nt].y;
                    }
                    if (sparse) {
                        int basem = g_mbase[row];
                        int mc = g_mcnt[row];
                        const float* sp = g_scr + (size_t)basem * C + cg * 64 + lc * 2;
                        for (int j = 0; j < mc; j++) {
#pragma unroll
                            for (int nt = 0; nt < 8; nt++) {
                                float2 sv = *(const float2*)(sp + nt * 8);
                                v[nt][0] += sv.x;
                                v[nt][1] += sv.y;
                            }
                            sp += C;
                        }
                    }
#pragma unroll
                    for (int nt = 0; nt < 8; nt++) {
                        int col = cg * 64 + nt * 8 + lc * 2;
                        size_t o = (size_t)row * 256 + (col >> 5) * 64 + (col & 31);
                        float v0 = v[nt][0], v1 = v[nt][1];
                        if (resid) {
                            __half2 rh = *(const __half2*)(resid + o);
                            __half2 rl = *(const __half2*)(resid + o + 32);
                            v0 += __half2float(__low2half(rh)) + __half2float(__low2half(rl));
                            v1 += __half2float(__high2half(rh)) + __half2float(__high2half(rl));
                        }
                        if (relu) { v0 = fmaxf(v0, 0.f); v1 = fmaxf(v1, 0.f); }
                        __half h0, l0, h1, l1;
                        split2(v0, h0, l0);
                        split2(v1, h1, l1);
                        *(__half2*)(outAct + o)      = __halves2half2(h0, h1);
                        *(__half2*)(outAct + o + 32) = __halves2half2(l0, l1);
                    }
                }
            }
#pragma unroll
            for (int mt = 0; mt < 2; mt++)
#pragma unroll
                for (int nt = 0; nt < 8; nt++)
#pragma unroll
                    for (int j = 0; j < 4; j++) acc[mt][nt][j] = 0.f;
        }
    }
}

// ---------------------------------------------------------------------------
// Input layer (Cin = 1), sparsity-compacted
// ---------------------------------------------------------------------------
__global__ __launch_bounds__(256)
void layer_in_kernel(const float* __restrict__ x, __half* __restrict__ outAct,
                     const float* __restrict__ Win, const float* __restrict__ bin,
                     const int* __restrict__ nbr, int n)
{
    __shared__ float ws[KNBR][C];
    __shared__ float s_val[128][28];
    __shared__ unsigned char s_kk[128][28];
    __shared__ int s_cnt[128];
    const int tid  = threadIdx.x;
    const int row0 = blockIdx.x * 128;

    for (int f = tid; f < KNBR * C; f += 256) ws[f / C][f & (C - 1)] = Win[f];
    if (tid < 128) {
        int row = row0 + tid;
        int j = 0;
        if (row < n) {
            const int* np = nbr + (size_t)row * KNBR;
#pragma unroll
            for (int k = 0; k < KNBR; k++) {
                int g = np[k];
                if (g >= 0) {
                    s_kk[tid][j] = (unsigned char)k;
                    s_val[tid][j] = x[g];
                    j++;
                }
            }
        }
        s_cnt[tid] = j;
    }
    __syncthreads();

    const int c  = tid & (C - 1);
    const int rg = tid >> 7;
    const float b = bin[c];
    const size_t co = (size_t)(c >> 5) * 64 + (c & 31);
    for (int r = rg; r < 128; r += 2) {
        int row = row0 + r;
        if (row >= n) continue;
        float acc = b;
        int cnt = s_cnt[r];
        for (int j = 0; j < cnt; j++)
            acc += s_val[r][j] * ws[s_kk[r][j]][c];
        acc = fmaxf(acc, 0.f);
        __half h, l; split2(acc, h, l);
        outAct[(size_t)row * 256 + co] = h;
        outAct[(size_t)row * 256 + co + 32] = l;
    }
}

// ---------------------------------------------------------------------------
// Final layer
// ---------------------------------------------------------------------------
__global__ __launch_bounds__(256)
void final_kernel(const __half* __restrict__ act, float* __restrict__ out,
                  const float* __restrict__ Wf3, const float* __restrict__ bf3, int n)
{
    __shared__ float hs[64][C + 1];
    __shared__ float wl[C * 3];
    __shared__ float bl[3];
    const int tid  = threadIdx.x;
    const int row0 = blockIdx.x * 64;

    for (int flat = tid; flat < 64 * C / 2; flat += 256) {
        int r = flat >> 6, q = flat & 63;
        int row = row0 + r;
        int col = (q >> 4) * 32 + (q & 15) * 2;
        float v0 = 0.f, v1 = 0.f;
        if (row < n) {
            size_t o = (size_t)row * 256 + (col >> 5) * 64 + (col & 31);
            __half2 rh = *(const __half2*)(act + o);
            __half2 rl = *(const __half2*)(act + o + 32);
            v0 = __half2float(__low2half(rh)) + __half2float(__low2half(rl));
            v1 = __half2float(__high2half(rh)) + __half2float(__high2half(rl));
        }
        hs[r][col] = v0;
        hs[r][col + 1] = v1;
    }
    for (int flat = tid; flat < C * 3; flat += 256) wl[flat] = Wf3[flat];
    if (tid < 3) bl[tid] = bf3[tid];
    __syncthreads();

    if (tid < 192) {
        int r = tid / 3, j = tid % 3;
        int row = row0 + r;
        if (row < n) {
            float acc = bl[j];
#pragma unroll 4
            for (int ci = 0; ci < C; ci++) acc += hs[r][ci] * wl[ci * 3 + j];
            out[(size_t)row * 3 + j] = acc;
        }
    }
}

// ---------------------------------------------------------------------------
extern "C" void kernel_launch(void* const* d_in, const int* in_sizes, int n_in,
                              void* d_out, int out_size)
{
    const float* x_feat = (const float*)d_in[0];
    const float* W_in   = (const float*)d_in[1];
    const float* b_in   = (const float*)d_in[2];
    const float* W_res  = (const float*)d_in[3];
    const float* b_res  = (const float*)d_in[4];
    const float* W_out  = (const float*)d_in[5];
    const float* b_out  = (const float*)d_in[6];
    const float* Wf1    = (const float*)d_in[7];
    const float* bf1    = (const float*)d_in[8];
    const float* Wf2    = (const float*)d_in[9];
    const float* bf2    = (const float*)d_in[10];
    const float* Wf3    = (const float*)d_in[11];
    const float* bf3    = (const float*)d_in[12];
    const int*   nbr    = (const int*)d_in[13];
    float* out = (float*)d_out;

    const int n = in_sizes[0];

    __half *actA, *actB, *Wt;
    cudaGetSymbolAddress((void**)&actA, g_actA);
    cudaGetSymbolAddress((void**)&actB, g_actB);
    cudaGetSymbolAddress((void**)&Wt, g_Wt);

    cudaFuncSetAttribute(sparse_mma_p, cudaFuncAttributeMaxDynamicSharedMemorySize, SP2_SMEM);
    cudaFuncSetAttribute(dense_mma_p, cudaFuncAttributeMaxDynamicSharedMemorySize, DN2_SMEM);

    const int ntiles = (n + TMW - 1) / TMW;
    const int gridM  = (n + 127) / 128;
    const int gridD  = ntiles < GDMAX ? ntiles : GDMAX;
    const int gridS  = NSEG * PSP;
    const int nb     = (n + 1023) / 1024;

    prep_w_kernel<<<N_WMAT, 256>>>(W_res, W_out, Wf1, Wf2);
    count_scan_kernel<<<nb, 1024>>>(nbr, n);
    scan_bsum_kernel<<<1, 1024>>>(nb);
    emit_pairs_kernel<<<nb, 1024>>>(nbr, n);

    layer_in_kernel<<<gridM, 256>>>(x_feat, actA, W_in, b_in, nbr, n);

    for (int i = 0; i < 3; i++) {
        const __half* W0 = Wt + ((size_t)((i * 2 + 0) * KNBR) << 15);
        const __half* W1 = Wt + ((size_t)((i * 2 + 1) * KNBR) << 15);
        const float* b0 = b_res + (size_t)(i * 2 + 0) * C;
        const float* b1 = b_res + (size_t)(i * 2 + 1) * C;
        sparse_mma_p<<<gridS, NT, SP2_SMEM>>>(actA, W0);
        dense_mma_p<<<gridD, NT, DN2_SMEM>>>(actA, actB, W0 + ((size_t)13 << 15),
                                             b0, nullptr, 1, 1, n, ntiles);
        sparse_mma_p<<<gridS, NT, SP2_SMEM>>>(actB, W1);
        dense_mma_p<<<gridD, NT, DN2_SMEM>>>(actB, actA, W1 + ((size_t)13 << 15),
                                             b1, actA, 0, 1, n, ntiles);
    }

    const __half* Wo = Wt + ((size_t)(6 * KNBR) << 15);
    sparse_mma_p<<<gridS, NT, SP2_SMEM>>>(actA, Wo);
    dense_mma_p<<<gridD, NT, DN2_SMEM>>>(actA, actB, Wo + ((size_t)13 << 15),
                                         b_out, nullptr, 0, 1, n, ntiles);

    dense_mma_p<<<gridD, NT, DN2_SMEM>>>(actB, actA, Wt + ((size_t)189 << 15),
                                         bf1, nullptr, 1, 0, n, ntiles);
    dense_mma_p<<<gridD, NT, DN2_SMEM>>>(actA, actB, Wt + ((size_t)190 << 15),
                                         bf2, nullptr, 1, 0, n, ntiles);

    final_kernel<<<(n + 63) / 64, 256>>>(actB, out, Wf3, bf3, n);
}

// round 13
// speedup vs baseline: 1.1485x; 1.1485x over previous
#include <cuda_runtime.h>
#include <cuda_fp16.h>
#include <cstdint>

#define C      128
#define KNBR   27
#define TM     128
#define NMAX   300000
#define NMAXP  300032                 // padded rows (dense bulk tail overread)
#define N_WMAT 191
#define CAP    16384
#define NSEG   27
#define SCR_ROWS (1 << 21)
#define NBMAX  512
#define PSP    11                     // sparse persistent CTAs per k
#define GDMAX  296                    // dense persistent CTAs, 2/SM

#define ASTG   16384                  // A stage: 128 rows x 128 B (swizzled)
#define BPITCH 528
#define BFULL  67584
#define DN3_SMEM (BFULL + 64 + 2 * ASTG)    // 100416
#define SP3_SMEM (BFULL + 2048 + 2 * ASTG)  // 102400

#define PLSTR ((size_t)NMAXP * 64)    // plane stride in halfs
#define ACT_OFF(row, cc) ((size_t)(cc) * PLSTR + (size_t)(row) * 64)

// activations: 4 chunk-planes; per row 128 B = [hi32|lo32] halfs, bytes
// swizzled within the row: blk16 ^= (row & 7)
__device__ __half g_actA[(size_t)NMAXP * 256];
__device__ __half g_actB[(size_t)NMAXP * 256];
__device__ __half g_Wt[(size_t)N_WMAT * 32768];
__device__ float         g_scr[(size_t)SCR_ROWS * C];
__device__ unsigned      g_cnt[NSEG];
__device__ int           g_pairg[NSEG * CAP];
__device__ int           g_slot[NSEG * CAP];
__device__ int           g_mbase[NMAX];
__device__ unsigned char g_mcnt[NMAX];
__device__ int           g_bsum[NBMAX];
__device__ int           g_boff[NBMAX];
__device__ int           g_kcnt[NSEG * NBMAX];
__device__ int           g_kbase[NSEG * NBMAX];

// ---------------------------------------------------------------------------
static __device__ __forceinline__ void cp_async16_cg(uint32_t dst, const void* src, bool pred) {
    int sz = pred ? 16 : 0;
    asm volatile("cp.async.cg.shared.global [%0], [%1], 16, %2;"
                 :: "r"(dst), "l"(src), "r"(sz) : "memory");
}
static __device__ __forceinline__ void cp_async16_ca(uint32_t dst, const void* src, bool pred) {
    int sz = pred ? 16 : 0;
    asm volatile("cp.async.ca.shared.global [%0], [%1], 16, %2;"
                 :: "r"(dst), "l"(src), "r"(sz) : "memory");
}
#define CP_COMMIT() asm volatile("cp.async.commit_group;" ::: "memory")
template <int N> static __device__ __forceinline__ void cp_wait() {
    asm volatile("cp.async.wait_group %0;" :: "n"(N) : "memory");
}
static __device__ __forceinline__ uint32_t smem_u32(const void* p) {
    uint32_t a;
    asm("{ .reg .u64 t; cvta.to.shared.u64 t, %1; cvt.u32.u64 %0, t; }"
        : "=r"(a) : "l"(p));
    return a;
}
#define MBAR_INIT(a, c) \
    asm volatile("mbarrier.init.shared.b64 [%0], %1;" :: "r"(a), "r"((uint32_t)(c)) : "memory")
#define MBAR_EXPECT_TX(a, b) \
    asm volatile("mbarrier.arrive.expect_tx.shared.b64 _, [%0], %1;" \
                 :: "r"(a), "r"((uint32_t)(b)) : "memory")
static __device__ __forceinline__ void bulk_g2s(uint32_t dst, const void* src,
                                                uint32_t bytes, uint32_t mbar) {
    asm volatile(
        "cp.async.bulk.shared::cluster.global.mbarrier::complete_tx::bytes "
        "[%0], [%1], %2, [%3];"
        :: "r"(dst), "l"(src), "r"(bytes), "r"(mbar) : "memory");
}
static __device__ __forceinline__ void mbar_wait(uint32_t mbar, uint32_t parity) {
    asm volatile(
        "{\n\t.reg .pred P;\n\t"
        "WL%=:\n\t"
        "mbarrier.try_wait.parity.shared.b64 P, [%0], %1, 0x989680;\n\t"
        "@P bra WD%=;\n\t"
        "bra WL%=;\n\t"
        "WD%=:\n\t}"
        :: "r"(mbar), "r"(parity) : "memory");
}
static __device__ __forceinline__ void mma_f16(float* c, const uint32_t* a,
                                               uint32_t b0, uint32_t b1) {
    asm volatile(
        "mma.sync.aligned.m16n8k16.row.col.f32.f16.f16.f32 "
        "{%0,%1,%2,%3}, {%4,%5,%6,%7}, {%8,%9}, {%0,%1,%2,%3};"
        : "+f"(c[0]), "+f"(c[1]), "+f"(c[2]), "+f"(c[3])
        : "r"(a[0]), "r"(a[1]), "r"(a[2]), "r"(a[3]), "r"(b0), "r"(b1));
}
static __device__ __forceinline__ void ldsm4(uint32_t* r, uint32_t addr) {
    asm volatile("ldmatrix.sync.aligned.m8n8.x4.shared.b16 {%0,%1,%2,%3}, [%4];"
                 : "=r"(r[0]), "=r"(r[1]), "=r"(r[2]), "=r"(r[3]) : "r"(addr));
}
static __device__ __forceinline__ void split2(float v, __half& h, __half& l) {
    h = __float2half_rn(v);
    l = __float2half_rn(v - __half2float(h));
}

// ---------------------------------------------------------------------------
// 3-term inner loop, one 32-ci chunk. A stage: 128 rows x 128 B, in-row
// swizzle blk16 ^= row&7 (hi blks 0-3, lo blks 4-7). B resident (BPITCH).
// ---------------------------------------------------------------------------
static __device__ __forceinline__ void gemm_chunk_p(uint32_t smA, uint32_t smB, int cc,
                                                    int rg, int cg, int lane,
                                                    float acc[2][8][4])
{
    const int arow = lane & 15, asel = (lane >> 4) & 1;
    const int sw = arow & 7;
    const int brow = (lane & 7) + ((lane >> 4) & 1) * 8;
    const int bsel = (lane >> 3) & 1;
#pragma unroll
    for (int ks = 0; ks < 2; ks++) {
        uint32_t arowb = smA + (rg * 32 + arow) * 128;
        uint32_t ah0 = arowb + 16 * ((2 * ks + asel) ^ sw);
        uint32_t al0 = arowb + 16 * ((4 + 2 * ks + asel) ^ sw);
        uint32_t baddr = smB + (cg * 64 + brow) * BPITCH + cc * 128 + ks * 32 + bsel * 16;
        uint32_t ah[2][4], al[2][4], bf[4][4];
        ldsm4(ah[0], ah0);
        ldsm4(ah[1], ah0 + 16 * 128);
        ldsm4(al[0], al0);
        ldsm4(al[1], al0 + 16 * 128);
#pragma unroll
        for (int t = 0; t < 4; t++) ldsm4(bf[t], baddr + t * 16 * BPITCH);
#pragma unroll
        for (int t = 0; t < 4; t++)
#pragma unroll
            for (int h = 0; h < 2; h++) {
                int nt = t * 2 + h;
                mma_f16(acc[0][nt], ah[0], bf[t][2 * h], bf[t][2 * h + 1]);
                mma_f16(acc[1][nt], ah[1], bf[t][2 * h], bf[t][2 * h + 1]);
                mma_f16(acc[0][nt], al[0], bf[t][2 * h], bf[t][2 * h + 1]);
                mma_f16(acc[1][nt], al[1], bf[t][2 * h], bf[t][2 * h + 1]);
            }
#pragma unroll
        for (int t = 0; t < 4; t++) ldsm4(bf[t], baddr + 64 + t * 16 * BPITCH);
#pragma unroll
        for (int t = 0; t < 4; t++)
#pragma unroll
            for (int h = 0; h < 2; h++) {
                int nt = t * 2 + h;
                mma_f16(acc[0][nt], ah[0], bf[t][2 * h], bf[t][2 * h + 1]);
                mma_f16(acc[1][nt], ah[1], bf[t][2 * h], bf[t][2 * h + 1]);
            }
    }
}

// ---------------------------------------------------------------------------
// Weight prepass (unchanged layout)
// ---------------------------------------------------------------------------
__global__ void prep_w_kernel(const float* __restrict__ W_res,
                              const float* __restrict__ W_out,
                              const float* __restrict__ Wf1,
                              const float* __restrict__ Wf2)
{
    __shared__ float t[32][33];
    const int b = blockIdx.x;
    const float* src;
    if (b < 162)       src = W_res + (size_t)b * C * C;
    else if (b < 189)  src = W_out + (size_t)(b - 162) * C * C;
    else if (b == 189) src = Wf1;
    else               src = Wf2;
    __half* dst = g_Wt + ((size_t)b << 15);

    const int j = threadIdx.x & 31, i0 = threadIdx.x >> 5;
    for (int tile = 0; tile < 16; tile++) {
        const int tr = tile >> 2, tc = tile & 3;
        __syncthreads();
#pragma unroll
        for (int p = 0; p < 4; p++)
            t[i0 + p * 8][j] = src[(tr * 32 + i0 + p * 8) * C + tc * 32 + j];
        __syncthreads();
#pragma unroll
        for (int p = 0; p < 4; p++) {
            int co = tc * 32 + i0 + p * 8;
            float w = t[j][i0 + p * 8];
            __half h, l; split2(w, h, l);
            size_t o = (size_t)co * 256 + tr * 64 + j;
            dst[o] = h;
            dst[o + 32] = l;
        }
    }
}

// ---------------------------------------------------------------------------
// Pair prepass (atomic-free), unchanged from round 11
// ---------------------------------------------------------------------------
__global__ __launch_bounds__(1024)
void count_scan_kernel(const int* __restrict__ nbr, int n)
{
    __shared__ int wsum[32];
    __shared__ int s_wk[NSEG * 32];
    const int tid = threadIdx.x, lane = tid & 31, wid = tid >> 5;
    const int m = blockIdx.x * 1024 + tid;

    unsigned valid27 = 0;
    if (m < n) {
        const int* np = nbr + (size_t)m * KNBR;
#pragma unroll
        for (int k = 0; k < KNBR; k++)
            if (k != 13 && np[k] >= 0) valid27 |= (1u << k);
    }
    int cnt = __popc(valid27);

#pragma unroll
    for (int k = 0; k < KNBR; k++) {
        if (k == 13) continue;
        unsigned ball = __ballot_sync(0xFFFFFFFFu, (valid27 >> k) & 1u);
        if (lane == 0) s_wk[k * 32 + wid] = __popc(ball);
    }

    int v = cnt;
#pragma unroll
    for (int o = 1; o < 32; o <<= 1) {
        int u = __shfl_up_sync(0xFFFFFFFFu, v, o);
        if (lane >= o) v += u;
    }
    if (lane == 31) wsum[wid] = v;
    __syncthreads();
    if (wid == 0) {
        int w = wsum[lane], iv = w;
#pragma unroll
        for (int o = 1; o < 32; o <<= 1) {
            int u = __shfl_up_sync(0xFFFFFFFFu, iv, o);
            if (lane >= o) iv += u;
        }
        wsum[lane] = iv - w;
    }
    __syncthreads();
    int pre = wsum[wid] + v - cnt;
    if (m < n) {
        g_mcnt[m] = (unsigned char)cnt;
        g_mbase[m] = pre;
    }
    if (tid == 1023) g_bsum[blockIdx.x] = pre + cnt;

    if (wid < NSEG && wid != 13) {
        int t = s_wk[wid * 32 + lane];
#pragma unroll
        for (int o = 16; o > 0; o >>= 1) t += __shfl_down_sync(0xFFFFFFFFu, t, o);
        if (lane == 0) g_kcnt[wid * NBMAX + blockIdx.x] = t;
    }
}

__global__ __launch_bounds__(1024)
void scan_bsum_kernel(int nb)
{
    __shared__ int s[512];
    const int tid = threadIdx.x, lane = tid & 31, w = tid >> 5;
    int v = 0;
    if (tid < 512) {
        v = (tid < nb) ? g_bsum[tid] : 0;
        s[tid] = v;
    }
    __syncthreads();
    for (int off = 1; off < 512; off <<= 1) {
        int u = (tid < 512 && tid >= off) ? s[tid - off] : 0;
        __syncthreads();
        if (tid < 512) s[tid] += u;
        __syncthreads();
    }
    if (tid < 512 && tid < nb) g_boff[tid] = s[tid] - v;

    if (w < NSEG && w != 13) {
        int run = 0;
        for (int b0 = 0; b0 < nb; b0 += 32) {
            int b = b0 + lane;
            int x = (b < nb) ? g_kcnt[w * NBMAX + b] : 0;
            int inc = x;
#pragma unroll
            for (int o = 1; o < 32; o <<= 1) {
                int u = __shfl_up_sync(0xFFFFFFFFu, inc, o);
                if (lane >= o) inc += u;
            }
            if (b < nb) g_kbase[w * NBMAX + b] = run + inc - x;
            run += __shfl_sync(0xFFFFFFFFu, inc, 31);
        }
        if (lane == 0) g_cnt[w] = (unsigned)run;
    }
    if (tid == 0) g_cnt[13] = 0;
}

__global__ __launch_bounds__(1024)
void emit_pairs_kernel(const int* __restrict__ nbr, int n)
{
    __shared__ int s_wk[NSEG * 32];
    __shared__ int s_kb[NSEG];
    const int tid = threadIdx.x, lane = tid & 31, wid = tid >> 5;
    const int m = blockIdx.x * 1024 + tid;

    unsigned valid27 = 0;
    if (m < n) {
        const int* np = nbr + (size_t)m * KNBR;
#pragma unroll
        for (int k = 0; k < KNBR; k++)
            if (k != 13 && np[k] >= 0) valid27 |= (1u << k);
    }
#pragma unroll
    for (int k = 0; k < KNBR; k++) {
        if (k == 13) continue;
        unsigned ball = __ballot_sync(0xFFFFFFFFu, (valid27 >> k) & 1u);
        if (lane == 0) s_wk[k * 32 + wid] = __popc(ball);
    }
    if (tid < NSEG) s_kb[tid] = (tid != 13) ? g_kbase[tid * NBMAX + blockIdx.x] : 0;
    __syncthreads();

    if (wid < NSEG && wid != 13) {
        int v = s_wk[wid * 32 + lane], orig = v;
#pragma unroll
        for (int o = 1; o < 32; o <<= 1) {
            int u = __shfl_up_sync(0xFFFFFFFFu, v, o);
            if (lane >= o) v += u;
        }
        s_wk[wid * 32 + lane] = v - orig;
    }
    __syncthreads();

    int base = 0;
    if (m < n) base = g_boff[m >> 10] + g_mbase[m];
    const unsigned lt = (1u << lane) - 1u;
    int j = 0;
#pragma unroll
    for (int k = 0; k < KNBR; k++) {
        if (k == 13) continue;
        bool valid = (valid27 >> k) & 1u;
        unsigned ball = __ballot_sync(0xFFFFFFFFu, valid);
        if (valid) {
            int pos = s_kb[k] + s_wk[k * 32 + wid] + __popc(ball & lt);
            if (pos < CAP && base + j < SCR_ROWS) {
                g_pairg[k * CAP + pos] = nbr[(size_t)m * KNBR + k];
                g_slot[k * CAP + pos] = base + j;
            }
            j++;
        }
    }
    if (m < n) g_mbase[m] = base;
}

// ---------------------------------------------------------------------------
// Phase 1 (persistent, B-stationary, 2-stage, 2 CTA/SM): per-k pair GEMM.
// A gathered via LDGSTS into swizzled unpadded stage.
// ---------------------------------------------------------------------------
__global__ __launch_bounds__(256, 2)
void sparse_mma_p(const __half* __restrict__ in, const __half* __restrict__ WtLayer)
{
    const int k = blockIdx.x % NSEG;
    const int c = blockIdx.x / NSEG;
    unsigned cnt = g_cnt[k];
    if (cnt > CAP) cnt = CAP;
    const int ntk = (int)((cnt + TM - 1) / TM);
    const int mytiles = (ntk - c + PSP - 1) / PSP;
    if (mytiles <= 0) return;
    const int total = 4 * mytiles;

    extern __shared__ char smem[];
    const uint32_t sb = smem_u32(smem);
    const int tid = threadIdx.x, wid = tid >> 5, lane = tid & 31;
    const int lr = lane >> 2, lc = lane & 3;
    const int rg = wid & 3, cg = wid >> 2;

    int (*s_g)[TM] = (int(*)[TM])(smem + BFULL);
    int (*s_s)[TM] = (int(*)[TM])(smem + BFULL + 1024);
    const uint32_t ABASE = sb + BFULL + 2048;
    const __half* Wk = WtLayer + ((size_t)k << 15);

    auto load_idx = [&](int tl) {
        if (tid < TM) {
            int p = (c + tl * PSP) * TM + tid;
            int buf = tl & 1;
            s_g[buf][tid] = (p < (int)cnt) ? g_pairg[k * CAP + p] : -1;
            s_s[buf][tid] = (p < (int)cnt) ? g_slot[k * CAP + p] : -1;
        }
    };

    auto produce = [&](int jj) {
        const int tl = jj >> 2, cc = jj & 3, buf = tl & 1;
        const uint32_t stA = ABASE + (jj & 1) * ASTG;
#pragma unroll
        for (int i = 0; i < 4; i++) {
            int u = tid + 256 * i;
            int r = u >> 3, qq = u & 7;
            int idx = s_g[buf][r];
            int ix = idx < 0 ? 0 : idx;
            const __half* src = in + ACT_OFF(ix, cc) + 8 * (qq ^ (ix & 7));
            uint32_t dst = stA + r * 128 + 16 * (qq ^ (r & 7));
            cp_async16_ca(dst, src, idx >= 0);
        }
        if (jj == 0) {
#pragma unroll
            for (int i = 0; i < 16; i++) {
                int u = tid + 256 * i;
                int r = u >> 5, q = u & 31;
                cp_async16_cg(sb + r * BPITCH + q * 16, Wk + (size_t)r * 256 + q * 8, true);
            }
        }
        CP_COMMIT();
    };

    float acc[2][8][4];
#pragma unroll
    for (int mt = 0; mt < 2; mt++)
#pragma unroll
        for (int nt = 0; nt < 8; nt++)
#pragma unroll
            for (int j = 0; j < 4; j++) acc[mt][nt][j] = 0.f;

    load_idx(0);
    __syncthreads();
    produce(0);
    if (total > 1) produce(1);

    for (int jj = 0; jj < total; jj++) {
        if (jj == total - 1) cp_wait<0>(); else cp_wait<1>();
        __syncthreads();
        gemm_chunk_p(ABASE + (jj & 1) * ASTG, sb, jj & 3, rg, cg, lane, acc);
        if ((jj & 3) == 0 && (jj >> 2) + 1 < mytiles) load_idx((jj >> 2) + 1);
        __syncthreads();
        if (jj + 2 < total) produce(jj + 2);

        if ((jj & 3) == 3) {
            const int tl = jj >> 2, buf = tl & 1;
            const int base = (c + tl * PSP) * TM;
#pragma unroll
            for (int mt = 0; mt < 2; mt++) {
#pragma unroll
                for (int hf = 0; hf < 2; hf++) {
                    int pr = rg * 32 + mt * 16 + hf * 8 + lr;
                    if (base + pr < (int)cnt) {
                        int slot = s_s[buf][pr];
                        if (slot >= 0) {
                            float* op = g_scr + (size_t)slot * C + cg * 64 + lc * 2;
#pragma unroll
                            for (int nt = 0; nt < 8; nt++)
                                *(float2*)(op + nt * 8) =
                                    make_float2(acc[mt][nt][hf * 2 + 0],
                                                acc[mt][nt][hf * 2 + 1]);
                        }
                    }
                }
            }
#pragma unroll
            for (int mt = 0; mt < 2; mt++)
#pragma unroll
                for (int nt = 0; nt < 8; nt++)
#pragma unroll
                    for (int j = 0; j < 4; j++) acc[mt][nt][j] = 0.f;
        }
    }
}

// ---------------------------------------------------------------------------
// Phase 2 (persistent, B-stationary, bulk-copy A, single barrier per chunk):
// dense self-term GEMM + fused combine epilogue
// ---------------------------------------------------------------------------
__global__ __launch_bounds__(256, 2)
void dense_mma_p(const __half* __restrict__ in, __half* __restrict__ outAct,
                 const __half* __restrict__ Wk, const float* __restrict__ bias,
                 const __half* __restrict__ resid, int relu, int sparse,
                 int n, int ntiles)
{
    const int mytiles = (ntiles - (int)blockIdx.x + (int)gridDim.x - 1) / (int)gridDim.x;
    if (mytiles <= 0) return;
    const int total = 4 * mytiles;

    extern __shared__ char smem[];
    const uint32_t sb = smem_u32(smem);
    const int tid = threadIdx.x, wid = tid >> 5, lane = tid & 31;
    const int lr = lane >> 2, lc = lane & 3;
    const int rg = wid & 3, cg = wid >> 2;
    const uint32_t MB = sb + BFULL;
    const uint32_t ABASE = sb + BFULL + 64;

    if (tid == 0) { MBAR_INIT(MB, 1); MBAR_INIT(MB + 8, 1); }
    __syncthreads();

    auto produceA = [&](int jj) {
        if (tid == 0) {
            const int tl = jj >> 2, cc = jj & 3;
            const int row0 = ((int)blockIdx.x + tl * (int)gridDim.x) * TM;
            uint32_t mb = MB + (jj & 1) * 8;
            MBAR_EXPECT_TX(mb, ASTG);
            bulk_g2s(ABASE + (jj & 1) * ASTG, in + ACT_OFF(row0, cc), ASTG, mb);
        }
    };

    // B load (once)
#pragma unroll
    for (int i = 0; i < 16; i++) {
        int u = tid + 256 * i;
        int r = u >> 5, q = u & 31;
        cp_async16_cg(sb + r * BPITCH + q * 16, Wk + (size_t)r * 256 + q * 8, true);
    }
    CP_COMMIT();

    float acc[2][8][4];
#pragma unroll
    for (int mt = 0; mt < 2; mt++)
#pragma unroll
        for (int nt = 0; nt < 8; nt++)
#pragma unroll
            for (int j = 0; j < 4; j++) acc[mt][nt][j] = 0.f;

    float2 bv[8];
#pragma unroll
    for (int nt = 0; nt < 8; nt++)
        bv[nt] = *(const float2*)(bias + cg * 64 + nt * 8 + lc * 2);

    produceA(0);
    produceA(1);

    for (int jj = 0; jj < total; jj++) {
        mbar_wait(MB + (jj & 1) * 8, (jj >> 1) & 1);
        if (jj == 0) { cp_wait<0>(); __syncthreads(); }
        gemm_chunk_p(ABASE + (jj & 1) * ASTG, sb, jj & 3, rg, cg, lane, acc);

        if ((jj & 3) == 3) {
            const int row0 = ((int)blockIdx.x + (jj >> 2) * (int)gridDim.x) * TM;
#pragma unroll
            for (int mt = 0; mt < 2; mt++) {
#pragma unroll
                for (int hf = 0; hf < 2; hf++) {
                    int row = row0 + rg * 32 + mt * 16 + hf * 8 + lr;
                    if (row >= n) continue;
                    const int sw = row & 7;
                    float v[8][2];
#pragma unroll
                    for (int nt = 0; nt < 8; nt++) {
                        v[nt][0] = acc[mt][nt][hf * 2 + 0] + bv[nt].x;
                        v[nt][1] = acc[mt][nt][hf * 2 + 1] + bv[nt].y;
                    }
                    if (sparse) {
                        int basem = g_mbase[row];
                        int mc = g_mcnt[row];
                        const float* sp = g_scr + (size_t)basem * C + cg * 64 + lc * 2;
                        for (int j = 0; j < mc; j++) {
#pragma unroll
                            for (int nt = 0; nt < 8; nt++) {
                                float2 sv = *(const float2*)(sp + nt * 8);
                                v[nt][0] += sv.x;
                                v[nt][1] += sv.y;
                            }
                            sp += C;
                        }
                    }
#pragma unroll
                    for (int nt = 0; nt < 8; nt++) {
                        size_t pb = ACT_OFF(row, 2 * cg + (nt >> 2));
                        size_t oh = pb + 8 * ((nt & 3) ^ sw) + lc * 2;
                        size_t ol = pb + 8 * ((4 + (nt & 3)) ^ sw) + lc * 2;
                        float v0 = v[nt][0], v1 = v[nt][1];
                        if (resid) {
                            __half2 rh = *(const __half2*)(resid + oh);
                            __half2 rl = *(const __half2*)(resid + ol);
                            v0 += __half2float(__low2half(rh)) + __half2float(__low2half(rl));
                            v1 += __half2float(__high2half(rh)) + __half2float(__high2half(rl));
                        }
                        if (relu) { v0 = fmaxf(v0, 0.f); v1 = fmaxf(v1, 0.f); }
                        __half h0, l0, h1, l1;
                        split2(v0, h0, l0);
                        split2(v1, h1, l1);
                        *(__half2*)(outAct + oh) = __halves2half2(h0, h1);
                        *(__half2*)(outAct + ol) = __halves2half2(l0, l1);
                    }
                }
            }
#pragma unroll
            for (int mt = 0; mt < 2; mt++)
#pragma unroll
                for (int nt = 0; nt < 8; nt++)
#pragma unroll
                    for (int j = 0; j < 4; j++) acc[mt][nt][j] = 0.f;
        }
        __syncthreads();
        if (jj + 2 < total) produceA(jj + 2);
    }
}

// ---------------------------------------------------------------------------
// Input layer (Cin = 1), sparsity-compacted, swizzled chunk-plane store
// ---------------------------------------------------------------------------
__global__ __launch_bounds__(256)
void layer_in_kernel(const float* __restrict__ x, __half* __restrict__ outAct,
                     const float* __restrict__ Win, const float* __restrict__ bin,
                     const int* __restrict__ nbr, int n)
{
    __shared__ float ws[KNBR][C];
    __shared__ float s_val[128][28];
    __shared__ unsigned char s_kk[128][28];
    __shared__ int s_cnt[128];
    const int tid  = threadIdx.x;
    const int row0 = blockIdx.x * 128;

    for (int f = tid; f < KNBR * C; f += 256) ws[f / C][f & (C - 1)] = Win[f];
    if (tid < 128) {
        int row = row0 + tid;
        int j = 0;
        if (row < n) {
            const int* np = nbr + (size_t)row * KNBR;
#pragma unroll
            for (int k = 0; k < KNBR; k++) {
                int g = np[k];
                if (g >= 0) {
                    s_kk[tid][j] = (unsigned char)k;
                    s_val[tid][j] = x[g];
                    j++;
                }
            }
        }
        s_cnt[tid] = j;
    }
    __syncthreads();

    const int c  = tid & (C - 1);
    const int rg = tid >> 7;
    const float b = bin[c];
    const int cc = c >> 5, ci = c & 31;
    for (int r = rg; r < 128; r += 2) {
        int row = row0 + r;
        if (row >= n) continue;
        float acc = b;
        int cnt = s_cnt[r];
        for (int j = 0; j < cnt; j++)
            acc += s_val[r][j] * ws[s_kk[r][j]][c];
        acc = fmaxf(acc, 0.f);
        __half h, l; split2(acc, h, l);
        const int sw = row & 7;
        size_t pb = ACT_OFF(row, cc);
        outAct[pb + 8 * ((ci >> 3) ^ sw) + (ci & 7)] = h;
        outAct[pb + 8 * ((4 + (ci >> 3)) ^ sw) + (ci & 7)] = l;
    }
}

// ---------------------------------------------------------------------------
// Final layer (reads swizzled act)
// ---------------------------------------------------------------------------
__global__ __launch_bounds__(256)
void final_kernel(const __half* __restrict__ act, float* __restrict__ out,
                  const float* __restrict__ Wf3, const float* __restrict__ bf3, int n)
{
    __shared__ float hs[64][C + 1];
    __shared__ float wl[C * 3];
    __shared__ float bl[3];
    const int tid  = threadIdx.x;
    const int row0 = blockIdx.x * 64;

    for (int flat = tid; flat < 64 * C / 2; flat += 256) {
        int r = flat >> 6, q = flat & 63;
        int row = row0 + r;
        int col = q * 2;
        float v0 = 0.f, v1 = 0.f;
        if (row < n) {
            const int sw = row & 7;
            const int cc = col >> 5, ci = col & 31;
            size_t pb = ACT_OFF(row, cc);
            __half2 rh = *(const __half2*)(act + pb + 8 * ((ci >> 3) ^ sw) + (ci & 7));
            __half2 rl = *(const __half2*)(act + pb + 8 * ((4 + (ci >> 3)) ^ sw) + (ci & 7));
            v0 = __half2float(__low2half(rh)) + __half2float(__low2half(rl));
            v1 = __half2float(__high2half(rh)) + __half2float(__high2half(rl));
        }
        hs[r][col] = v0;
        hs[r][col + 1] = v1;
    }
    for (int flat = tid; flat < C * 3; flat += 256) wl[flat] = Wf3[flat];
    if (tid < 3) bl[tid] = bf3[tid];
    __syncthreads();

    if (tid < 192) {
        int r = tid / 3, j = tid % 3;
        int row = row0 + r;
        if (row < n) {
            float acc = bl[j];
#pragma unroll 4
            for (int ci = 0; ci < C; ci++) acc += hs[r][ci] * wl[ci * 3 + j];
            out[(size_t)row * 3 + j] = acc;
        }
    }
}

// ---------------------------------------------------------------------------
extern "C" void kernel_launch(void* const* d_in, const int* in_sizes, int n_in,
                              void* d_out, int out_size)
{
    const float* x_feat = (const float*)d_in[0];
    const float* W_in   = (const float*)d_in[1];
    const float* b_in   = (const float*)d_in[2];
    const float* W_res  = (const float*)d_in[3];
    const float* b_res  = (const float*)d_in[4];
    const float* W_out  = (const float*)d_in[5];
    const float* b_out  = (const float*)d_in[6];
    const float* Wf1    = (const float*)d_in[7];
    const float* bf1    = (const float*)d_in[8];
    const float* Wf2    = (const float*)d_in[9];
    const float* bf2    = (const float*)d_in[10];
    const float* Wf3    = (const float*)d_in[11];
    const float* bf3    = (const float*)d_in[12];
    const int*   nbr    = (const int*)d_in[13];
    float* out = (float*)d_out;

    const int n = in_sizes[0];

    __half *actA, *actB, *Wt;
    cudaGetSymbolAddress((void**)&actA, g_actA);
    cudaGetSymbolAddress((void**)&actB, g_actB);
    cudaGetSymbolAddress((void**)&Wt, g_Wt);

    cudaFuncSetAttribute(sparse_mma_p, cudaFuncAttributeMaxDynamicSharedMemorySize, SP3_SMEM);
    cudaFuncSetAttribute(dense_mma_p, cudaFuncAttributeMaxDynamicSharedMemorySize, DN3_SMEM);

    const int ntiles = (n + TM - 1) / TM;
    const int gridM  = (n + 127) / 128;
    const int gridD  = ntiles < GDMAX ? ntiles : GDMAX;
    const int gridS  = NSEG * PSP;
    const int nb     = (n + 1023) / 1024;

    prep_w_kernel<<<N_WMAT, 256>>>(W_res, W_out, Wf1, Wf2);
    count_scan_kernel<<<nb, 1024>>>(nbr, n);
    scan_bsum_kernel<<<1, 1024>>>(nb);
    emit_pairs_kernel<<<nb, 1024>>>(nbr, n);

    layer_in_kernel<<<gridM, 256>>>(x_feat, actA, W_in, b_in, nbr, n);

    for (int i = 0; i < 3; i++) {
        const __half* W0 = Wt + ((size_t)((i * 2 + 0) * KNBR) << 15);
        const __half* W1 = Wt + ((size_t)((i * 2 + 1) * KNBR) << 15);
        const float* b0 = b_res + (size_t)(i * 2 + 0) * C;
        const float* b1 = b_res + (size_t)(i * 2 + 1) * C;
        sparse_mma_p<<<gridS, 256, SP3_SMEM>>>(actA, W0);
        dense_mma_p<<<gridD, 256, DN3_SMEM>>>(actA, actB, W0 + ((size_t)13 << 15),
                                              b0, nullptr, 1, 1, n, ntiles);
        sparse_mma_p<<<gridS, 256, SP3_SMEM>>>(actB, W1);
        dense_mma_p<<<gridD, 256, DN3_SMEM>>>(actB, actA, W1 + ((size_t)13 << 15),
                                              b1, actA, 0, 1, n, ntiles);
    }

    const __half* Wo = Wt + ((size_t)(6 * KNBR) << 15);
    sparse_mma_p<<<gridS, 256, SP3_SMEM>>>(actA, Wo);
    dense_mma_p<<<gridD, 256, DN3_SMEM>>>(actA, actB, Wo + ((size_t)13 << 15),
                                          b_out, nullptr, 0, 1, n, ntiles);

    dense_mma_p<<<gridD, 256, DN3_SMEM>>>(actB, actA, Wt + ((size_t)189 << 15),
                                          bf1, nullptr, 1, 0, n, ntiles);
    dense_mma_p<<<gridD, 256, DN3_SMEM>>>(actA, actB, Wt + ((size_t)190 << 15),
                                          bf2, nullptr, 1, 0, n, ntiles);

    final_kernel<<<(n + 63) / 64, 256>>>(actB, out, Wf3, bf3, n);
}

// round 14
// speedup vs baseline: 1.1558x; 1.0063x over previous
#include <cuda_runtime.h>
#include <cuda_fp16.h>
#include <cstdint>

#define C      128
#define KNBR   27
#define TM     128
#define NMAX   300000
#define NMAXP  300032                 // padded rows (dense bulk tail overread)
#define N_WMAT 191
#define CAP    16384
#define NSEG   27
#define SCR_ROWS (1 << 21)
#define NBMAX  512
#define PSP    11                     // sparse persistent CTAs per k
#define GDMAX  296                    // dense persistent CTAs, 2/SM

#define ASTG   16384                  // A stage: 128 rows x 128 B (swizzled)
#define BPITCH 528
#define BFULL  67584
#define DN3_SMEM (BFULL + 64 + 2 * ASTG)          // 100416
#define SP4_SMEM (BFULL + 64 + 1024 + 2 * ASTG)   // 101440

#define PLSTR ((size_t)NMAXP * 64)    // plane stride in halfs
#define ACT_OFF(row, cc) ((size_t)(cc) * PLSTR + (size_t)(row) * 64)

// activations: 4 chunk-planes; per row 128 B = [hi32|lo32] halfs, bytes
// swizzled within the row: blk16 ^= (row & 7)
__device__ __half g_actA[(size_t)NMAXP * 256];
__device__ __half g_actB[(size_t)NMAXP * 256];
__device__ __half g_Wt[(size_t)N_WMAT * 32768];
__device__ float         g_scr[(size_t)SCR_ROWS * C];
__device__ unsigned      g_cnt[NSEG];
__device__ int           g_pairg[NSEG * CAP];
__device__ int           g_slot[NSEG * CAP];
__device__ int           g_mbase[NMAX];
__device__ unsigned char g_mcnt[NMAX];
__device__ int           g_bsum[NBMAX];
__device__ int           g_boff[NBMAX];
__device__ int           g_kcnt[NSEG * NBMAX];
__device__ int           g_kbase[NSEG * NBMAX];

// ---------------------------------------------------------------------------
static __device__ __forceinline__ void cp_async16_cg(uint32_t dst, const void* src, bool pred) {
    int sz = pred ? 16 : 0;
    asm volatile("cp.async.cg.shared.global [%0], [%1], 16, %2;"
                 :: "r"(dst), "l"(src), "r"(sz) : "memory");
}
#define CP_COMMIT() asm volatile("cp.async.commit_group;" ::: "memory")
template <int N> static __device__ __forceinline__ void cp_wait() {
    asm volatile("cp.async.wait_group %0;" :: "n"(N) : "memory");
}
static __device__ __forceinline__ uint32_t smem_u32(const void* p) {
    uint32_t a;
    asm("{ .reg .u64 t; cvta.to.shared.u64 t, %1; cvt.u32.u64 %0, t; }"
        : "=r"(a) : "l"(p));
    return a;
}
#define MBAR_INIT(a, c) \
    asm volatile("mbarrier.init.shared.b64 [%0], %1;" :: "r"(a), "r"((uint32_t)(c)) : "memory")
#define MBAR_EXPECT_TX(a, b) \
    asm volatile("mbarrier.arrive.expect_tx.shared.b64 _, [%0], %1;" \
                 :: "r"(a), "r"((uint32_t)(b)) : "memory")
static __device__ __forceinline__ void bulk_g2s(uint32_t dst, const void* src,
                                                uint32_t bytes, uint32_t mbar) {
    asm volatile(
        "cp.async.bulk.shared::cluster.global.mbarrier::complete_tx::bytes "
        "[%0], [%1], %2, [%3];"
        :: "r"(dst), "l"(src), "r"(bytes), "r"(mbar) : "memory");
}
static __device__ __forceinline__ void mbar_wait(uint32_t mbar, uint32_t parity) {
    asm volatile(
        "{\n\t.reg .pred P;\n\t"
        "WL%=:\n\t"
        "mbarrier.try_wait.parity.shared.b64 P, [%0], %1, 0x989680;\n\t"
        "@P bra WD%=;\n\t"
        "bra WL%=;\n\t"
        "WD%=:\n\t}"
        :: "r"(mbar), "r"(parity) : "memory");
}
static __device__ __forceinline__ void mma_f16(float* c, const uint32_t* a,
                                               uint32_t b0, uint32_t b1) {
    asm volatile(
        "mma.sync.aligned.m16n8k16.row.col.f32.f16.f16.f32 "
        "{%0,%1,%2,%3}, {%4,%5,%6,%7}, {%8,%9}, {%0,%1,%2,%3};"
        : "+f"(c[0]), "+f"(c[1]), "+f"(c[2]), "+f"(c[3])
        : "r"(a[0]), "r"(a[1]), "r"(a[2]), "r"(a[3]), "r"(b0), "r"(b1));
}
static __device__ __forceinline__ void ldsm4(uint32_t* r, uint32_t addr) {
    asm volatile("ldmatrix.sync.aligned.m8n8.x4.shared.b16 {%0,%1,%2,%3}, [%4];"
                 : "=r"(r[0]), "=r"(r[1]), "=r"(r[2]), "=r"(r[3]) : "r"(addr));
}
static __device__ __forceinline__ void split2(float v, __half& h, __half& l) {
    h = __float2half_rn(v);
    l = __float2half_rn(v - __half2float(h));
}

// ---------------------------------------------------------------------------
// 3-term inner loop, one 32-ci chunk. A stage: 128 rows x 128 B, per-row
// swizzle passed in (sw0 = swizzle of lane's row, sw1 = of row+16).
// B resident (BPITCH).
// ---------------------------------------------------------------------------
static __device__ __forceinline__ void gemm_chunk_p(uint32_t smA, uint32_t smB, int cc,
                                                    int rg, int cg, int lane,
                                                    int sw0, int sw1,
                                                    float acc[2][8][4])
{
    const int arow = lane & 15, asel = (lane >> 4) & 1;
    const int brow = (lane & 7) + ((lane >> 4) & 1) * 8;
    const int bsel = (lane >> 3) & 1;
#pragma unroll
    for (int ks = 0; ks < 2; ks++) {
        uint32_t ar0 = smA + (rg * 32 + arow) * 128;
        uint32_t ar1 = smA + (rg * 32 + 16 + arow) * 128;
        uint32_t baddr = smB + (cg * 64 + brow) * BPITCH + cc * 128 + ks * 32 + bsel * 16;
        uint32_t ah[2][4], al[2][4], bf[4][4];
        ldsm4(ah[0], ar0 + 16 * ((2 * ks + asel) ^ sw0));
        ldsm4(ah[1], ar1 + 16 * ((2 * ks + asel) ^ sw1));
        ldsm4(al[0], ar0 + 16 * ((4 + 2 * ks + asel) ^ sw0));
        ldsm4(al[1], ar1 + 16 * ((4 + 2 * ks + asel) ^ sw1));
#pragma unroll
        for (int t = 0; t < 4; t++) ldsm4(bf[t], baddr + t * 16 * BPITCH);
#pragma unroll
        for (int t = 0; t < 4; t++)
#pragma unroll
            for (int h = 0; h < 2; h++) {
                int nt = t * 2 + h;
                mma_f16(acc[0][nt], ah[0], bf[t][2 * h], bf[t][2 * h + 1]);
                mma_f16(acc[1][nt], ah[1], bf[t][2 * h], bf[t][2 * h + 1]);
                mma_f16(acc[0][nt], al[0], bf[t][2 * h], bf[t][2 * h + 1]);
                mma_f16(acc[1][nt], al[1], bf[t][2 * h], bf[t][2 * h + 1]);
            }
#pragma unroll
        for (int t = 0; t < 4; t++) ldsm4(bf[t], baddr + 64 + t * 16 * BPITCH);
#pragma unroll
        for (int t = 0; t < 4; t++)
#pragma unroll
            for (int h = 0; h < 2; h++) {
                int nt = t * 2 + h;
                mma_f16(acc[0][nt], ah[0], bf[t][2 * h], bf[t][2 * h + 1]);
                mma_f16(acc[1][nt], ah[1], bf[t][2 * h], bf[t][2 * h + 1]);
            }
    }
}

// ---------------------------------------------------------------------------
// Weight prepass (unchanged layout)
// ---------------------------------------------------------------------------
__global__ void prep_w_kernel(const float* __restrict__ W_res,
                              const float* __restrict__ W_out,
                              const float* __restrict__ Wf1,
                              const float* __restrict__ Wf2)
{
    __shared__ float t[32][33];
    const int b = blockIdx.x;
    const float* src;
    if (b < 162)       src = W_res + (size_t)b * C * C;
    else if (b < 189)  src = W_out + (size_t)(b - 162) * C * C;
    else if (b == 189) src = Wf1;
    else               src = Wf2;
    __half* dst = g_Wt + ((size_t)b << 15);

    const int j = threadIdx.x & 31, i0 = threadIdx.x >> 5;
    for (int tile = 0; tile < 16; tile++) {
        const int tr = tile >> 2, tc = tile & 3;
        __syncthreads();
#pragma unroll
        for (int p = 0; p < 4; p++)
            t[i0 + p * 8][j] = src[(tr * 32 + i0 + p * 8) * C + tc * 32 + j];
        __syncthreads();
#pragma unroll
        for (int p = 0; p < 4; p++) {
            int co = tc * 32 + i0 + p * 8;
            float w = t[j][i0 + p * 8];
            __half h, l; split2(w, h, l);
            size_t o = (size_t)co * 256 + tr * 64 + j;
            dst[o] = h;
            dst[o + 32] = l;
        }
    }
}

// ---------------------------------------------------------------------------
// Pair prepass (atomic-free), unchanged
// ---------------------------------------------------------------------------
__global__ __launch_bounds__(1024)
void count_scan_kernel(const int* __restrict__ nbr, int n)
{
    __shared__ int wsum[32];
    __shared__ int s_wk[NSEG * 32];
    const int tid = threadIdx.x, lane = tid & 31, wid = tid >> 5;
    const int m = blockIdx.x * 1024 + tid;

    unsigned valid27 = 0;
    if (m < n) {
        const int* np = nbr + (size_t)m * KNBR;
#pragma unroll
        for (int k = 0; k < KNBR; k++)
            if (k != 13 && np[k] >= 0) valid27 |= (1u << k);
    }
    int cnt = __popc(valid27);

#pragma unroll
    for (int k = 0; k < KNBR; k++) {
        if (k == 13) continue;
        unsigned ball = __ballot_sync(0xFFFFFFFFu, (valid27 >> k) & 1u);
        if (lane == 0) s_wk[k * 32 + wid] = __popc(ball);
    }

    int v = cnt;
#pragma unroll
    for (int o = 1; o < 32; o <<= 1) {
        int u = __shfl_up_sync(0xFFFFFFFFu, v, o);
        if (lane >= o) v += u;
    }
    if (lane == 31) wsum[wid] = v;
    __syncthreads();
    if (wid == 0) {
        int w = wsum[lane], iv = w;
#pragma unroll
        for (int o = 1; o < 32; o <<= 1) {
            int u = __shfl_up_sync(0xFFFFFFFFu, iv, o);
            if (lane >= o) iv += u;
        }
        wsum[lane] = iv - w;
    }
    __syncthreads();
    int pre = wsum[wid] + v - cnt;
    if (m < n) {
        g_mcnt[m] = (unsigned char)cnt;
        g_mbase[m] = pre;
    }
    if (tid == 1023) g_bsum[blockIdx.x] = pre + cnt;

    if (wid < NSEG && wid != 13) {
        int t = s_wk[wid * 32 + lane];
#pragma unroll
        for (int o = 16; o > 0; o >>= 1) t += __shfl_down_sync(0xFFFFFFFFu, t, o);
        if (lane == 0) g_kcnt[wid * NBMAX + blockIdx.x] = t;
    }
}

__global__ __launch_bounds__(1024)
void scan_bsum_kernel(int nb)
{
    __shared__ int s[512];
    const int tid = threadIdx.x, lane = tid & 31, w = tid >> 5;
    int v = 0;
    if (tid < 512) {
        v = (tid < nb) ? g_bsum[tid] : 0;
        s[tid] = v;
    }
    __syncthreads();
    for (int off = 1; off < 512; off <<= 1) {
        int u = (tid < 512 && tid >= off) ? s[tid - off] : 0;
        __syncthreads();
        if (tid < 512) s[tid] += u;
        __syncthreads();
    }
    if (tid < 512 && tid < nb) g_boff[tid] = s[tid] - v;

    if (w < NSEG && w != 13) {
        int run = 0;
        for (int b0 = 0; b0 < nb; b0 += 32) {
            int b = b0 + lane;
            int x = (b < nb) ? g_kcnt[w * NBMAX + b] : 0;
            int inc = x;
#pragma unroll
            for (int o = 1; o < 32; o <<= 1) {
                int u = __shfl_up_sync(0xFFFFFFFFu, inc, o);
                if (lane >= o) inc += u;
            }
            if (b < nb) g_kbase[w * NBMAX + b] = run + inc - x;
            run += __shfl_sync(0xFFFFFFFFu, inc, 31);
        }
        if (lane == 0) g_cnt[w] = (unsigned)run;
    }
    if (tid == 0) g_cnt[13] = 0;
}

__global__ __launch_bounds__(1024)
void emit_pairs_kernel(const int* __restrict__ nbr, int n)
{
    __shared__ int s_wk[NSEG * 32];
    __shared__ int s_kb[NSEG];
    const int tid = threadIdx.x, lane = tid & 31, wid = tid >> 5;
    const int m = blockIdx.x * 1024 + tid;

    unsigned valid27 = 0;
    if (m < n) {
        const int* np = nbr + (size_t)m * KNBR;
#pragma unroll
        for (int k = 0; k < KNBR; k++)
            if (k != 13 && np[k] >= 0) valid27 |= (1u << k);
    }
#pragma unroll
    for (int k = 0; k < KNBR; k++) {
        if (k == 13) continue;
        unsigned ball = __ballot_sync(0xFFFFFFFFu, (valid27 >> k) & 1u);
        if (lane == 0) s_wk[k * 32 + wid] = __popc(ball);
    }
    if (tid < NSEG) s_kb[tid] = (tid != 13) ? g_kbase[tid * NBMAX + blockIdx.x] : 0;
    __syncthreads();

    if (wid < NSEG && wid != 13) {
        int v = s_wk[wid * 32 + lane], orig = v;
#pragma unroll
        for (int o = 1; o < 32; o <<= 1) {
            int u = __shfl_up_sync(0xFFFFFFFFu, v, o);
            if (lane >= o) v += u;
        }
        s_wk[wid * 32 + lane] = v - orig;
    }
    __syncthreads();

    int base = 0;
    if (m < n) base = g_boff[m >> 10] + g_mbase[m];
    const unsigned lt = (1u << lane) - 1u;
    int j = 0;
#pragma unroll
    for (int k = 0; k < KNBR; k++) {
        if (k == 13) continue;
        bool valid = (valid27 >> k) & 1u;
        unsigned ball = __ballot_sync(0xFFFFFFFFu, valid);
        if (valid) {
            int pos = s_kb[k] + s_wk[k * 32 + wid] + __popc(ball & lt);
            if (pos < CAP && base + j < SCR_ROWS) {
                g_pairg[k * CAP + pos] = nbr[(size_t)m * KNBR + k];
                g_slot[k * CAP + pos] = base + j;
            }
            j++;
        }
    }
    if (m < n) g_mbase[m] = base;
}

// ---------------------------------------------------------------------------
// Phase 1 (persistent, B-stationary, row-bulk TMA gather, single barrier):
// per-k pair GEMM -> fp32 scratch rows (m-sorted slots)
// ---------------------------------------------------------------------------
__global__ __launch_bounds__(256, 2)
void sparse_mma_p(const __half* __restrict__ in, const __half* __restrict__ WtLayer)
{
    const int k = blockIdx.x % NSEG;
    const int c = blockIdx.x / NSEG;
    unsigned cnt = g_cnt[k];
    if (cnt > CAP) cnt = CAP;
    const int ntk = (int)((cnt + TM - 1) / TM);
    const int mytiles = (ntk - c + PSP - 1) / PSP;
    if (mytiles <= 0) return;
    const int total = 4 * mytiles;

    extern __shared__ char smem[];
    const uint32_t sb = smem_u32(smem);
    const int tid = threadIdx.x, wid = tid >> 5, lane = tid & 31;
    const int lr = lane >> 2, lc = lane & 3;
    const int rg = wid & 3, cg = wid >> 2;
    const int arow = lane & 15;

    const uint32_t MB = sb + BFULL;
    int (*s_g)[TM] = (int(*)[TM])(smem + BFULL + 64);
    const uint32_t ABASE = sb + BFULL + 64 + 1024;
    const __half* Wk = WtLayer + ((size_t)k << 15);

    auto tile_base = [&](int tl) { return (c + tl * PSP) * TM; };
    auto vrows = [&](int tl) {
        int v = (int)cnt - tile_base(tl);
        return v > TM ? TM : v;
    };
    auto load_idx = [&](int tl) {
        if (tid < TM) {
            int p = tile_base(tl) + tid;
            s_g[tl & 1][tid] = (p < (int)cnt) ? g_pairg[k * CAP + p] : -1;
        }
    };
    auto issue_bulks = [&](int q) {
        const int tl = q >> 2, cc = q & 3;
        const uint32_t stA = ABASE + (q & 1) * ASTG;
        if (tid < TM) {
            int g = s_g[tl & 1][tid];
            if (g >= 0) {
                bulk_g2s(stA + tid * 128, in + ACT_OFF(g, cc), 128, MB + (q & 1) * 8);
            } else {
                uint4 z = make_uint4(0, 0, 0, 0);
                uint4* row = (uint4*)(smem + BFULL + 64 + 1024 + (q & 1) * ASTG + tid * 128);
#pragma unroll
                for (int i = 0; i < 8; i++) row[i] = z;
            }
        }
    };

    if (tid == 0) { MBAR_INIT(MB, 1); MBAR_INIT(MB + 8, 1); }

    // B load (once)
#pragma unroll
    for (int i = 0; i < 16; i++) {
        int u = tid + 256 * i;
        int r = u >> 5, q = u & 31;
        cp_async16_cg(sb + r * BPITCH + q * 16, Wk + (size_t)r * 256 + q * 8, true);
    }
    CP_COMMIT();

    load_idx(0);
    if (tid == 0) {
        int vr0 = vrows(0);
        MBAR_EXPECT_TX(MB, (uint32_t)vr0 * 128);
        MBAR_EXPECT_TX(MB + 8, (uint32_t)vr0 * 128);
    }
    __syncthreads();
    issue_bulks(0);
    issue_bulks(1);
    cp_wait<0>();
    __syncthreads();

    float acc[2][8][4];
#pragma unroll
    for (int mt = 0; mt < 2; mt++)
#pragma unroll
        for (int nt = 0; nt < 8; nt++)
#pragma unroll
            for (int j = 0; j < 4; j++) acc[mt][nt][j] = 0.f;

    int sw0 = 0, sw1 = 0;

    for (int jj = 0; jj < total; jj++) {
        const int tl = jj >> 2, buf = tl & 1;
        mbar_wait(MB + (jj & 1) * 8, (jj >> 1) & 1);
        if ((jj & 3) == 0) {
            sw0 = s_g[buf][rg * 32 + arow] & 7;
            sw1 = s_g[buf][rg * 32 + 16 + arow] & 7;
        }
        gemm_chunk_p(ABASE + (jj & 1) * ASTG, sb, jj & 3, rg, cg, lane, sw0, sw1, acc);
        if ((jj & 3) == 0 && tl + 1 < mytiles) load_idx(tl + 1);

        if ((jj & 3) == 3) {
            const int base = tile_base(tl);
#pragma unroll
            for (int mt = 0; mt < 2; mt++) {
#pragma unroll
                for (int hf = 0; hf < 2; hf++) {
                    int pr = rg * 32 + mt * 16 + hf * 8 + lr;
                    if (base + pr < (int)cnt) {
                        int slot = g_slot[k * CAP + base + pr];
                        if (slot >= 0) {
                            float* op = g_scr + (size_t)slot * C + cg * 64 + lc * 2;
#pragma unroll
                            for (int nt = 0; nt < 8; nt++)
                                *(float2*)(op + nt * 8) =
                                    make_float2(acc[mt][nt][hf * 2 + 0],
                                                acc[mt][nt][hf * 2 + 1]);
                        }
                    }
                }
            }
#pragma unroll
            for (int mt = 0; mt < 2; mt++)
#pragma unroll
                for (int nt = 0; nt < 8; nt++)
#pragma unroll
                    for (int j = 0; j < 4; j++) acc[mt][nt][j] = 0.f;
        }

        if (jj + 2 < total && tid == 0)
            MBAR_EXPECT_TX(MB + (jj & 1) * 8, (uint32_t)vrows((jj + 2) >> 2) * 128);
        __syncthreads();
        if (jj + 2 < total) issue_bulks(jj + 2);
    }
}

// ---------------------------------------------------------------------------
// Phase 2 (persistent, B-stationary, bulk-copy A, single barrier per chunk):
// dense self-term GEMM + fused combine epilogue  (round-13 champion)
// ---------------------------------------------------------------------------
__global__ __launch_bounds__(256, 2)
void dense_mma_p(const __half* __restrict__ in, __half* __restrict__ outAct,
                 const __half* __restrict__ Wk, const float* __restrict__ bias,
                 const __half* __restrict__ resid, int relu, int sparse,
                 int n, int ntiles)
{
    const int mytiles = (ntiles - (int)blockIdx.x + (int)gridDim.x - 1) / (int)gridDim.x;
    if (mytiles <= 0) return;
    const int total = 4 * mytiles;

    extern __shared__ char smem[];
    const uint32_t sb = smem_u32(smem);
    const int tid = threadIdx.x, wid = tid >> 5, lane = tid & 31;
    const int lr = lane >> 2, lc = lane & 3;
    const int rg = wid & 3, cg = wid >> 2;
    const int arow = lane & 15;
    const int swd = arow & 7;
    const uint32_t MB = sb + BFULL;
    const uint32_t ABASE = sb + BFULL + 64;

    if (tid == 0) { MBAR_INIT(MB, 1); MBAR_INIT(MB + 8, 1); }
    __syncthreads();

    auto produceA = [&](int jj) {
        if (tid == 0) {
            const int tl = jj >> 2, cc = jj & 3;
            const int row0 = ((int)blockIdx.x + tl * (int)gridDim.x) * TM;
            uint32_t mb = MB + (jj & 1) * 8;
            MBAR_EXPECT_TX(mb, ASTG);
            bulk_g2s(ABASE + (jj & 1) * ASTG, in + ACT_OFF(row0, cc), ASTG, mb);
        }
    };

    // B load (once)
#pragma unroll
    for (int i = 0; i < 16; i++) {
        int u = tid + 256 * i;
        int r = u >> 5, q = u & 31;
        cp_async16_cg(sb + r * BPITCH + q * 16, Wk + (size_t)r * 256 + q * 8, true);
    }
    CP_COMMIT();

    float acc[2][8][4];
#pragma unroll
    for (int mt = 0; mt < 2; mt++)
#pragma unroll
        for (int nt = 0; nt < 8; nt++)
#pragma unroll
            for (int j = 0; j < 4; j++) acc[mt][nt][j] = 0.f;

    float2 bv[8];
#pragma unroll
    for (int nt = 0; nt < 8; nt++)
        bv[nt] = *(const float2*)(bias + cg * 64 + nt * 8 + lc * 2);

    produceA(0);
    produceA(1);

    for (int jj = 0; jj < total; jj++) {
        mbar_wait(MB + (jj & 1) * 8, (jj >> 1) & 1);
        if (jj == 0) { cp_wait<0>(); __syncthreads(); }
        gemm_chunk_p(ABASE + (jj & 1) * ASTG, sb, jj & 3, rg, cg, lane, swd, swd, acc);

        if ((jj & 3) == 3) {
            const int row0 = ((int)blockIdx.x + (jj >> 2) * (int)gridDim.x) * TM;
#pragma unroll
            for (int mt = 0; mt < 2; mt++) {
#pragma unroll
                for (int hf = 0; hf < 2; hf++) {
                    int row = row0 + rg * 32 + mt * 16 + hf * 8 + lr;
                    if (row >= n) continue;
                    const int sw = row & 7;
                    float v[8][2];
#pragma unroll
                    for (int nt = 0; nt < 8; nt++) {
                        v[nt][0] = acc[mt][nt][hf * 2 + 0] + bv[nt].x;
                        v[nt][1] = acc[mt][nt][hf * 2 + 1] + bv[nt].y;
                    }
                    if (sparse) {
                        int basem = g_mbase[row];
                        int mc = g_mcnt[row];
                        const float* sp = g_scr + (size_t)basem * C + cg * 64 + lc * 2;
                        for (int j = 0; j < mc; j++) {
#pragma unroll
                            for (int nt = 0; nt < 8; nt++) {
                                float2 sv = *(const float2*)(sp + nt * 8);
                                v[nt][0] += sv.x;
                                v[nt][1] += sv.y;
                            }
                            sp += C;
                        }
                    }
#pragma unroll
                    for (int nt = 0; nt < 8; nt++) {
                        size_t pb = ACT_OFF(row, 2 * cg + (nt >> 2));
                        size_t oh = pb + 8 * ((nt & 3) ^ sw) + lc * 2;
                        size_t ol = pb + 8 * ((4 + (nt & 3)) ^ sw) + lc * 2;
                        float v0 = v[nt][0], v1 = v[nt][1];
                        if (resid) {
                            __half2 rh = *(const __half2*)(resid + oh);
                            __half2 rl = *(const __half2*)(resid + ol);
                            v0 += __half2float(__low2half(rh)) + __half2float(__low2half(rl));
                            v1 += __half2float(__high2half(rh)) + __half2float(__high2half(rl));
                        }
                        if (relu) { v0 = fmaxf(v0, 0.f); v1 = fmaxf(v1, 0.f); }
                        __half h0, l0, h1, l1;
                        split2(v0, h0, l0);
                        split2(v1, h1, l1);
                        *(__half2*)(outAct + oh) = __halves2half2(h0, h1);
                        *(__half2*)(outAct + ol) = __halves2half2(l0, l1);
                    }
                }
            }
#pragma unroll
            for (int mt = 0; mt < 2; mt++)
#pragma unroll
                for (int nt = 0; nt < 8; nt++)
#pragma unroll
                    for (int j = 0; j < 4; j++) acc[mt][nt][j] = 0.f;
        }
        __syncthreads();
        if (jj + 2 < total) produceA(jj + 2);
    }
}

// ---------------------------------------------------------------------------
// Input layer (Cin = 1), sparsity-compacted, swizzled chunk-plane store
// ---------------------------------------------------------------------------
__global__ __launch_bounds__(256)
void layer_in_kernel(const float* __restrict__ x, __half* __restrict__ outAct,
                     const float* __restrict__ Win, const float* __restrict__ bin,
                     const int* __restrict__ nbr, int n)
{
    __shared__ float ws[KNBR][C];
    __shared__ float s_val[128][28];
    __shared__ unsigned char s_kk[128][28];
    __shared__ int s_cnt[128];
    const int tid  = threadIdx.x;
    const int row0 = blockIdx.x * 128;

    for (int f = tid; f < KNBR * C; f += 256) ws[f / C][f & (C - 1)] = Win[f];
    if (tid < 128) {
        int row = row0 + tid;
        int j = 0;
        if (row < n) {
            const int* np = nbr + (size_t)row * KNBR;
#pragma unroll
            for (int k = 0; k < KNBR; k++) {
                int g = np[k];
                if (g >= 0) {
                    s_kk[tid][j] = (unsigned char)k;
                    s_val[tid][j] = x[g];
                    j++;
                }
            }
        }
        s_cnt[tid] = j;
    }
    __syncthreads();

    const int c  = tid & (C - 1);
    const int rg = tid >> 7;
    const float b = bin[c];
    const int cc = c >> 5, ci = c & 31;
    for (int r = rg; r < 128; r += 2) {
        int row = row0 + r;
        if (row >= n) continue;
        float acc = b;
        int cnt = s_cnt[r];
        for (int j = 0; j < cnt; j++)
            acc += s_val[r][j] * ws[s_kk[r][j]][c];
        acc = fmaxf(acc, 0.f);
        __half h, l; split2(acc, h, l);
        const int sw = row & 7;
        size_t pb = ACT_OFF(row, cc);
        outAct[pb + 8 * ((ci >> 3) ^ sw) + (ci & 7)] = h;
        outAct[pb + 8 * ((4 + (ci >> 3)) ^ sw) + (ci & 7)] = l;
    }
}

// ---------------------------------------------------------------------------
// Final layer (reads swizzled act)
// ---------------------------------------------------------------------------
__global__ __launch_bounds__(256)
void final_kernel(const __half* __restrict__ act, float* __restrict__ out,
                  const float* __restrict__ Wf3, const float* __restrict__ bf3, int n)
{
    __shared__ float hs[64][C + 1];
    __shared__ float wl[C * 3];
    __shared__ float bl[3];
    const int tid  = threadIdx.x;
    const int row0 = blockIdx.x * 64;

    for (int flat = tid; flat < 64 * C / 2; flat += 256) {
        int r = flat >> 6, q = flat & 63;
        int row = row0 + r;
        int col = q * 2;
        float v0 = 0.f, v1 = 0.f;
        if (row < n) {
            const int sw = row & 7;
            const int cc = col >> 5, ci = col & 31;
            size_t pb = ACT_OFF(row, cc);
            __half2 rh = *(const __half2*)(act + pb + 8 * ((ci >> 3) ^ sw) + (ci & 7));
            __half2 rl = *(const __half2*)(act + pb + 8 * ((4 + (ci >> 3)) ^ sw) + (ci & 7));
            v0 = __half2float(__low2half(rh)) + __half2float(__low2half(rl));
            v1 = __half2float(__high2half(rh)) + __half2float(__high2half(rl));
        }
        hs[r][col] = v0;
        hs[r][col + 1] = v1;
    }
    for (int flat = tid; flat < C * 3; flat += 256) wl[flat] = Wf3[flat];
    if (tid < 3) bl[tid] = bf3[tid];
    __syncthreads();

    if (tid < 192) {
        int r = tid / 3, j = tid % 3;
        int row = row0 + r;
        if (row < n) {
            float acc = bl[j];
#pragma unroll 4
            for (int ci = 0; ci < C; ci++) acc += hs[r][ci] * wl[ci * 3 + j];
            out[(size_t)row * 3 + j] = acc;
        }
    }
}

// ---------------------------------------------------------------------------
extern "C" void kernel_launch(void* const* d_in, const int* in_sizes, int n_in,
                              void* d_out, int out_size)
{
    const float* x_feat = (const float*)d_in[0];
    const float* W_in   = (const float*)d_in[1];
    const float* b_in   = (const float*)d_in[2];
    const float* W_res  = (const float*)d_in[3];
    const float* b_res  = (const float*)d_in[4];
    const float* W_out  = (const float*)d_in[5];
    const float* b_out  = (const float*)d_in[6];
    const float* Wf1    = (const float*)d_in[7];
    const float* bf1    = (const float*)d_in[8];
    const float* Wf2    = (const float*)d_in[9];
    const float* bf2    = (const float*)d_in[10];
    const float* Wf3    = (const float*)d_in[11];
    const float* bf3    = (const float*)d_in[12];
    const int*   nbr    = (const int*)d_in[13];
    float* out = (float*)d_out;

    const int n = in_sizes[0];

    __half *actA, *actB, *Wt;
    cudaGetSymbolAddress((void**)&actA, g_actA);
    cudaGetSymbolAddress((void**)&actB, g_actB);
    cudaGetSymbolAddress((void**)&Wt, g_Wt);

    cudaFuncSetAttribute(sparse_mma_p, cudaFuncAttributeMaxDynamicSharedMemorySize, SP4_SMEM);
    cudaFuncSetAttribute(dense_mma_p, cudaFuncAttributeMaxDynamicSharedMemorySize, DN3_SMEM);

    const int ntiles = (n + TM - 1) / TM;
    const int gridM  = (n + 127) / 128;
    const int gridD  = ntiles < GDMAX ? ntiles : GDMAX;
    const int gridS  = NSEG * PSP;
    const int nb     = (n + 1023) / 1024;

    prep_w_kernel<<<N_WMAT, 256>>>(W_res, W_out, Wf1, Wf2);
    count_scan_kernel<<<nb, 1024>>>(nbr, n);
    scan_bsum_kernel<<<1, 1024>>>(nb);
    emit_pairs_kernel<<<nb, 1024>>>(nbr, n);

    layer_in_kernel<<<gridM, 256>>>(x_feat, actA, W_in, b_in, nbr, n);

    for (int i = 0; i < 3; i++) {
        const __half* W0 = Wt + ((size_t)((i * 2 + 0) * KNBR) << 15);
        const __half* W1 = Wt + ((size_t)((i * 2 + 1) * KNBR) << 15);
        const float* b0 = b_res + (size_t)(i * 2 + 0) * C;
        const float* b1 = b_res + (size_t)(i * 2 + 1) * C;
        sparse_mma_p<<<gridS, 256, SP4_SMEM>>>(actA, W0);
        dense_mma_p<<<gridD, 256, DN3_SMEM>>>(actA, actB, W0 + ((size_t)13 << 15),
                                              b0, nullptr, 1, 1, n, ntiles);
        sparse_mma_p<<<gridS, 256, SP4_SMEM>>>(actB, W1);
        dense_mma_p<<<gridD, 256, DN3_SMEM>>>(actB, actA, W1 + ((size_t)13 << 15),
                                              b1, actA, 0, 1, n, ntiles);
    }

    const __half* Wo = Wt + ((size_t)(6 * KNBR) << 15);
    sparse_mma_p<<<gridS, 256, SP4_SMEM>>>(actA, Wo);
    dense_mma_p<<<gridD, 256, DN3_SMEM>>>(actA, actB, Wo + ((size_t)13 << 15),
                                          b_out, nullptr, 0, 1, n, ntiles);

    dense_mma_p<<<gridD, 256, DN3_SMEM>>>(actB, actA, Wt + ((size_t)189 << 15),
                                          bf1, nullptr, 1, 0, n, ntiles);
    dense_mma_p<<<gridD, 256, DN3_SMEM>>>(actA, actB, Wt + ((size_t)190 << 15),
                                          bf2, nullptr, 1, 0, n, ntiles);

    final_kernel<<<(n + 63) / 64, 256>>>(actB, out, Wf3, bf3, n);
}

// round 15
// speedup vs baseline: 1.1683x; 1.0109x over previous
#include <cuda_runtime.h>
#include <cuda_fp16.h>
#include <cstdint>

#define C      128
#define KNBR   27
#define TM     128
#define NMAX   300000
#define NMAXP  300032                 // padded rows (dense bulk tail overread)
#define N_WMAT 191
#define CAP    16384
#define NSEG   27
#define SCR_ROWS (1 << 21)
#define NBMAX  512
#define PSP    11                     // sparse persistent CTAs per k
#define GDMAX  296                    // dense persistent CTAs, 2/SM

#define ASTG   16384                  // A stage: 128 rows x 128 B (swizzled)
#define BPITCH 528
#define BFULL  67584
#define DN3_SMEM (BFULL + 64 + 2 * ASTG)          // 100416
#define SP4_SMEM (BFULL + 64 + 1024 + 2 * ASTG)   // 101440

#define PLSTR ((size_t)NMAXP * 64)    // plane stride in halfs
#define ACT_OFF(row, cc) ((size_t)(cc) * PLSTR + (size_t)(row) * 64)

// activations: 4 chunk-planes; per row 128 B = [hi32|lo32] halfs, bytes
// swizzled within the row: blk16 ^= (row & 7)
__device__ __half g_actA[(size_t)NMAXP * 256];
__device__ __half g_actB[(size_t)NMAXP * 256];
__device__ __half g_Wt[(size_t)N_WMAT * 32768];
__device__ float         g_scr[(size_t)SCR_ROWS * C];
__device__ unsigned      g_cnt[NSEG];
__device__ int           g_pairg[NSEG * CAP];
__device__ int           g_slot[NSEG * CAP];
__device__ int           g_mbase[NMAX];
__device__ unsigned char g_mcnt[NMAX];
__device__ int           g_bsum[NBMAX];
__device__ int           g_boff[NBMAX];
__device__ int           g_kcnt[NSEG * NBMAX];
__device__ int           g_kbase[NSEG * NBMAX];

// ---------------------------------------------------------------------------
static __device__ __forceinline__ void cp_async16_cg(uint32_t dst, const void* src, bool pred) {
    int sz = pred ? 16 : 0;
    asm volatile("cp.async.cg.shared.global [%0], [%1], 16, %2;"
                 :: "r"(dst), "l"(src), "r"(sz) : "memory");
}
#define CP_COMMIT() asm volatile("cp.async.commit_group;" ::: "memory")
template <int N> static __device__ __forceinline__ void cp_wait() {
    asm volatile("cp.async.wait_group %0;" :: "n"(N) : "memory");
}
static __device__ __forceinline__ uint32_t smem_u32(const void* p) {
    uint32_t a;
    asm("{ .reg .u64 t; cvta.to.shared.u64 t, %1; cvt.u32.u64 %0, t; }"
        : "=r"(a) : "l"(p));
    return a;
}
#define MBAR_INIT(a, c) \
    asm volatile("mbarrier.init.shared.b64 [%0], %1;" :: "r"(a), "r"((uint32_t)(c)) : "memory")
#define MBAR_EXPECT_TX(a, b) \
    asm volatile("mbarrier.arrive.expect_tx.shared.b64 _, [%0], %1;" \
                 :: "r"(a), "r"((uint32_t)(b)) : "memory")
static __device__ __forceinline__ void bulk_g2s(uint32_t dst, const void* src,
                                                uint32_t bytes, uint32_t mbar) {
    asm volatile(
        "cp.async.bulk.shared::cluster.global.mbarrier::complete_tx::bytes "
        "[%0], [%1], %2, [%3];"
        :: "r"(dst), "l"(src), "r"(bytes), "r"(mbar) : "memory");
}
static __device__ __forceinline__ void mbar_wait(uint32_t mbar, uint32_t parity) {
    asm volatile(
        "{\n\t.reg .pred P;\n\t"
        "WL%=:\n\t"
        "mbarrier.try_wait.parity.shared.b64 P, [%0], %1, 0x989680;\n\t"
        "@P bra WD%=;\n\t"
        "bra WL%=;\n\t"
        "WD%=:\n\t}"
        :: "r"(mbar), "r"(parity) : "memory");
}
static __device__ __forceinline__ void mma_f16(float* c, const uint32_t* a,
                                               uint32_t b0, uint32_t b1) {
    asm volatile(
        "mma.sync.aligned.m16n8k16.row.col.f32.f16.f16.f32 "
        "{%0,%1,%2,%3}, {%4,%5,%6,%7}, {%8,%9}, {%0,%1,%2,%3};"
        : "+f"(c[0]), "+f"(c[1]), "+f"(c[2]), "+f"(c[3])
        : "r"(a[0]), "r"(a[1]), "r"(a[2]), "r"(a[3]), "r"(b0), "r"(b1));
}
static __device__ __forceinline__ void ldsm4(uint32_t* r, uint32_t addr) {
    asm volatile("ldmatrix.sync.aligned.m8n8.x4.shared.b16 {%0,%1,%2,%3}, [%4];"
                 : "=r"(r[0]), "=r"(r[1]), "=r"(r[2]), "=r"(r[3]) : "r"(addr));
}
static __device__ __forceinline__ void split2(float v, __half& h, __half& l) {
    h = __float2half_rn(v);
    l = __float2half_rn(v - __half2float(h));
}

// ---------------------------------------------------------------------------
// Compensated inner loop, one 32-ci chunk. FULL=true: 3 terms (ah*bh + al*bh
// + ah*bl). FULL=false: 2 terms (drop weight-lo correction; used for the
// sparse neighbor contributions where the precision margin allows it).
// A stage: 128 rows x 128 B, per-row swizzle (sw0 / sw1). B resident.
// ---------------------------------------------------------------------------
template <bool FULL>
static __device__ __forceinline__ void gemm_chunk_p(uint32_t smA, uint32_t smB, int cc,
                                                    int rg, int cg, int lane,
                                                    int sw0, int sw1,
                                                    float acc[2][8][4])
{
    const int arow = lane & 15, asel = (lane >> 4) & 1;
    const int brow = (lane & 7) + ((lane >> 4) & 1) * 8;
    const int bsel = (lane >> 3) & 1;
#pragma unroll
    for (int ks = 0; ks < 2; ks++) {
        uint32_t ar0 = smA + (rg * 32 + arow) * 128;
        uint32_t ar1 = smA + (rg * 32 + 16 + arow) * 128;
        uint32_t baddr = smB + (cg * 64 + brow) * BPITCH + cc * 128 + ks * 32 + bsel * 16;
        uint32_t ah[2][4], al[2][4], bf[4][4];
        ldsm4(ah[0], ar0 + 16 * ((2 * ks + asel) ^ sw0));
        ldsm4(ah[1], ar1 + 16 * ((2 * ks + asel) ^ sw1));
        ldsm4(al[0], ar0 + 16 * ((4 + 2 * ks + asel) ^ sw0));
        ldsm4(al[1], ar1 + 16 * ((4 + 2 * ks + asel) ^ sw1));
#pragma unroll
        for (int t = 0; t < 4; t++) ldsm4(bf[t], baddr + t * 16 * BPITCH);
#pragma unroll
        for (int t = 0; t < 4; t++)
#pragma unroll
            for (int h = 0; h < 2; h++) {
                int nt = t * 2 + h;
                mma_f16(acc[0][nt], ah[0], bf[t][2 * h], bf[t][2 * h + 1]);
                mma_f16(acc[1][nt], ah[1], bf[t][2 * h], bf[t][2 * h + 1]);
                mma_f16(acc[0][nt], al[0], bf[t][2 * h], bf[t][2 * h + 1]);
                mma_f16(acc[1][nt], al[1], bf[t][2 * h], bf[t][2 * h + 1]);
            }
        if (FULL) {
#pragma unroll
            for (int t = 0; t < 4; t++) ldsm4(bf[t], baddr + 64 + t * 16 * BPITCH);
#pragma unroll
            for (int t = 0; t < 4; t++)
#pragma unroll
                for (int h = 0; h < 2; h++) {
                    int nt = t * 2 + h;
                    mma_f16(acc[0][nt], ah[0], bf[t][2 * h], bf[t][2 * h + 1]);
                    mma_f16(acc[1][nt], ah[1], bf[t][2 * h], bf[t][2 * h + 1]);
                }
        }
    }
}

// ---------------------------------------------------------------------------
// Weight prepass (unchanged layout)
// ---------------------------------------------------------------------------
__global__ void prep_w_kernel(const float* __restrict__ W_res,
                              const float* __restrict__ W_out,
                              const float* __restrict__ Wf1,
                              const float* __restrict__ Wf2)
{
    __shared__ float t[32][33];
    const int b = blockIdx.x;
    const float* src;
    if (b < 162)       src = W_res + (size_t)b * C * C;
    else if (b < 189)  src = W_out + (size_t)(b - 162) * C * C;
    else if (b == 189) src = Wf1;
    else               src = Wf2;
    __half* dst = g_Wt + ((size_t)b << 15);

    const int j = threadIdx.x & 31, i0 = threadIdx.x >> 5;
    for (int tile = 0; tile < 16; tile++) {
        const int tr = tile >> 2, tc = tile & 3;
        __syncthreads();
#pragma unroll
        for (int p = 0; p < 4; p++)
            t[i0 + p * 8][j] = src[(tr * 32 + i0 + p * 8) * C + tc * 32 + j];
        __syncthreads();
#pragma unroll
        for (int p = 0; p < 4; p++) {
            int co = tc * 32 + i0 + p * 8;
            float w = t[j][i0 + p * 8];
            __half h, l; split2(w, h, l);
            size_t o = (size_t)co * 256 + tr * 64 + j;
            dst[o] = h;
            dst[o + 32] = l;
        }
    }
}

// ---------------------------------------------------------------------------
// Pair prepass (atomic-free), unchanged
// ---------------------------------------------------------------------------
__global__ __launch_bounds__(1024)
void count_scan_kernel(const int* __restrict__ nbr, int n)
{
    __shared__ int wsum[32];
    __shared__ int s_wk[NSEG * 32];
    const int tid = threadIdx.x, lane = tid & 31, wid = tid >> 5;
    const int m = blockIdx.x * 1024 + tid;

    unsigned valid27 = 0;
    if (m < n) {
        const int* np = nbr + (size_t)m * KNBR;
#pragma unroll
        for (int k = 0; k < KNBR; k++)
            if (k != 13 && np[k] >= 0) valid27 |= (1u << k);
    }
    int cnt = __popc(valid27);

#pragma unroll
    for (int k = 0; k < KNBR; k++) {
        if (k == 13) continue;
        unsigned ball = __ballot_sync(0xFFFFFFFFu, (valid27 >> k) & 1u);
        if (lane == 0) s_wk[k * 32 + wid] = __popc(ball);
    }

    int v = cnt;
#pragma unroll
    for (int o = 1; o < 32; o <<= 1) {
        int u = __shfl_up_sync(0xFFFFFFFFu, v, o);
        if (lane >= o) v += u;
    }
    if (lane == 31) wsum[wid] = v;
    __syncthreads();
    if (wid == 0) {
        int w = wsum[lane], iv = w;
#pragma unroll
        for (int o = 1; o < 32; o <<= 1) {
            int u = __shfl_up_sync(0xFFFFFFFFu, iv, o);
            if (lane >= o) iv += u;
        }
        wsum[lane] = iv - w;
    }
    __syncthreads();
    int pre = wsum[wid] + v - cnt;
    if (m < n) {
        g_mcnt[m] = (unsigned char)cnt;
        g_mbase[m] = pre;
    }
    if (tid == 1023) g_bsum[blockIdx.x] = pre + cnt;

    if (wid < NSEG && wid != 13) {
        int t = s_wk[wid * 32 + lane];
#pragma unroll
        for (int o = 16; o > 0; o >>= 1) t += __shfl_down_sync(0xFFFFFFFFu, t, o);
        if (lane == 0) g_kcnt[wid * NBMAX + blockIdx.x] = t;
    }
}

__global__ __launch_bounds__(1024)
void scan_bsum_kernel(int nb)
{
    __shared__ int s[512];
    const int tid = threadIdx.x, lane = tid & 31, w = tid >> 5;
    int v = 0;
    if (tid < 512) {
        v = (tid < nb) ? g_bsum[tid] : 0;
        s[tid] = v;
    }
    __syncthreads();
    for (int off = 1; off < 512; off <<= 1) {
        int u = (tid < 512 && tid >= off) ? s[tid - off] : 0;
        __syncthreads();
        if (tid < 512) s[tid] += u;
        __syncthreads();
    }
    if (tid < 512 && tid < nb) g_boff[tid] = s[tid] - v;

    if (w < NSEG && w != 13) {
        int run = 0;
        for (int b0 = 0; b0 < nb; b0 += 32) {
            int b = b0 + lane;
            int x = (b < nb) ? g_kcnt[w * NBMAX + b] : 0;
            int inc = x;
#pragma unroll
            for (int o = 1; o < 32; o <<= 1) {
                int u = __shfl_up_sync(0xFFFFFFFFu, inc, o);
                if (lane >= o) inc += u;
            }
            if (b < nb) g_kbase[w * NBMAX + b] = run + inc - x;
            run += __shfl_sync(0xFFFFFFFFu, inc, 31);
        }
        if (lane == 0) g_cnt[w] = (unsigned)run;
    }
    if (tid == 0) g_cnt[13] = 0;
}

__global__ __launch_bounds__(1024)
void emit_pairs_kernel(const int* __restrict__ nbr, int n)
{
    __shared__ int s_wk[NSEG * 32];
    __shared__ int s_kb[NSEG];
    const int tid = threadIdx.x, lane = tid & 31, wid = tid >> 5;
    const int m = blockIdx.x * 1024 + tid;

    unsigned valid27 = 0;
    if (m < n) {
        const int* np = nbr + (size_t)m * KNBR;
#pragma unroll
        for (int k = 0; k < KNBR; k++)
            if (k != 13 && np[k] >= 0) valid27 |= (1u << k);
    }
#pragma unroll
    for (int k = 0; k < KNBR; k++) {
        if (k == 13) continue;
        unsigned ball = __ballot_sync(0xFFFFFFFFu, (valid27 >> k) & 1u);
        if (lane == 0) s_wk[k * 32 + wid] = __popc(ball);
    }
    if (tid < NSEG) s_kb[tid] = (tid != 13) ? g_kbase[tid * NBMAX + blockIdx.x] : 0;
    __syncthreads();

    if (wid < NSEG && wid != 13) {
        int v = s_wk[wid * 32 + lane], orig = v;
#pragma unroll
        for (int o = 1; o < 32; o <<= 1) {
            int u = __shfl_up_sync(0xFFFFFFFFu, v, o);
            if (lane >= o) v += u;
        }
        s_wk[wid * 32 + lane] = v - orig;
    }
    __syncthreads();

    int base = 0;
    if (m < n) base = g_boff[m >> 10] + g_mbase[m];
    const unsigned lt = (1u << lane) - 1u;
    int j = 0;
#pragma unroll
    for (int k = 0; k < KNBR; k++) {
        if (k == 13) continue;
        bool valid = (valid27 >> k) & 1u;
        unsigned ball = __ballot_sync(0xFFFFFFFFu, valid);
        if (valid) {
            int pos = s_kb[k] + s_wk[k * 32 + wid] + __popc(ball & lt);
            if (pos < CAP && base + j < SCR_ROWS) {
                g_pairg[k * CAP + pos] = nbr[(size_t)m * KNBR + k];
                g_slot[k * CAP + pos] = base + j;
            }
            j++;
        }
    }
    if (m < n) g_mbase[m] = base;
}

// ---------------------------------------------------------------------------
// Phase 1 (persistent, B-stationary, row-bulk TMA gather, 2-term compensated):
// per-k pair GEMM -> fp32 scratch rows (m-sorted slots)
// ---------------------------------------------------------------------------
__global__ __launch_bounds__(256, 2)
void sparse_mma_p(const __half* __restrict__ in, const __half* __restrict__ WtLayer)
{
    const int k = blockIdx.x % NSEG;
    const int c = blockIdx.x / NSEG;
    unsigned cnt = g_cnt[k];
    if (cnt > CAP) cnt = CAP;
    const int ntk = (int)((cnt + TM - 1) / TM);
    const int mytiles = (ntk - c + PSP - 1) / PSP;
    if (mytiles <= 0) return;
    const int total = 4 * mytiles;

    extern __shared__ char smem[];
    const uint32_t sb = smem_u32(smem);
    const int tid = threadIdx.x, wid = tid >> 5, lane = tid & 31;
    const int lr = lane >> 2, lc = lane & 3;
    const int rg = wid & 3, cg = wid >> 2;
    const int arow = lane & 15;

    const uint32_t MB = sb + BFULL;
    int (*s_g)[TM] = (int(*)[TM])(smem + BFULL + 64);
    const uint32_t ABASE = sb + BFULL + 64 + 1024;
    const __half* Wk = WtLayer + ((size_t)k << 15);

    auto tile_base = [&](int tl) { return (c + tl * PSP) * TM; };
    auto vrows = [&](int tl) {
        int v = (int)cnt - tile_base(tl);
        return v > TM ? TM : v;
    };
    auto load_idx = [&](int tl) {
        if (tid < TM) {
            int p = tile_base(tl) + tid;
            s_g[tl & 1][tid] = (p < (int)cnt) ? g_pairg[k * CAP + p] : -1;
        }
    };
    auto issue_bulks = [&](int q) {
        const int tl = q >> 2, cc = q & 3;
        const uint32_t stA = ABASE + (q & 1) * ASTG;
        if (tid < TM) {
            int g = s_g[tl & 1][tid];
            if (g >= 0) {
                bulk_g2s(stA + tid * 128, in + ACT_OFF(g, cc), 128, MB + (q & 1) * 8);
            } else {
                uint4 z = make_uint4(0, 0, 0, 0);
                uint4* row = (uint4*)(smem + BFULL + 64 + 1024 + (q & 1) * ASTG + tid * 128);
#pragma unroll
                for (int i = 0; i < 8; i++) row[i] = z;
            }
        }
    };

    if (tid == 0) { MBAR_INIT(MB, 1); MBAR_INIT(MB + 8, 1); }

    // B load (once)
#pragma unroll
    for (int i = 0; i < 16; i++) {
        int u = tid + 256 * i;
        int r = u >> 5, q = u & 31;
        cp_async16_cg(sb + r * BPITCH + q * 16, Wk + (size_t)r * 256 + q * 8, true);
    }
    CP_COMMIT();

    load_idx(0);
    if (tid == 0) {
        int vr0 = vrows(0);
        MBAR_EXPECT_TX(MB, (uint32_t)vr0 * 128);
        MBAR_EXPECT_TX(MB + 8, (uint32_t)vr0 * 128);
    }
    __syncthreads();
    issue_bulks(0);
    issue_bulks(1);
    cp_wait<0>();
    __syncthreads();

    float acc[2][8][4];
#pragma unroll
    for (int mt = 0; mt < 2; mt++)
#pragma unroll
        for (int nt = 0; nt < 8; nt++)
#pragma unroll
            for (int j = 0; j < 4; j++) acc[mt][nt][j] = 0.f;

    int sw0 = 0, sw1 = 0;

    for (int jj = 0; jj < total; jj++) {
        const int tl = jj >> 2, buf = tl & 1;
        mbar_wait(MB + (jj & 1) * 8, (jj >> 1) & 1);
        if ((jj & 3) == 0) {
            sw0 = s_g[buf][rg * 32 + arow] & 7;
            sw1 = s_g[buf][rg * 32 + 16 + arow] & 7;
        }
        gemm_chunk_p<false>(ABASE + (jj & 1) * ASTG, sb, jj & 3, rg, cg, lane,
                            sw0, sw1, acc);
        if ((jj & 3) == 0 && tl + 1 < mytiles) load_idx(tl + 1);

        if ((jj & 3) == 3) {
            const int base = tile_base(tl);
#pragma unroll
            for (int mt = 0; mt < 2; mt++) {
#pragma unroll
                for (int hf = 0; hf < 2; hf++) {
                    int pr = rg * 32 + mt * 16 + hf * 8 + lr;
                    if (base + pr < (int)cnt) {
                        int slot = g_slot[k * CAP + base + pr];
                        if (slot >= 0) {
                            float* op = g_scr + (size_t)slot * C + cg * 64 + lc * 2;
#pragma unroll
                            for (int nt = 0; nt < 8; nt++)
                                *(float2*)(op + nt * 8) =
                                    make_float2(acc[mt][nt][hf * 2 + 0],
                                                acc[mt][nt][hf * 2 + 1]);
                        }
                    }
                }
            }
#pragma unroll
            for (int mt = 0; mt < 2; mt++)
#pragma unroll
                for (int nt = 0; nt < 8; nt++)
#pragma unroll
                    for (int j = 0; j < 4; j++) acc[mt][nt][j] = 0.f;
        }

        if (jj + 2 < total && tid == 0)
            MBAR_EXPECT_TX(MB + (jj & 1) * 8, (uint32_t)vrows((jj + 2) >> 2) * 128);
        __syncthreads();
        if (jj + 2 < total) issue_bulks(jj + 2);
    }
}

// ---------------------------------------------------------------------------
// Phase 2 (persistent, B-stationary, bulk-copy A, 3-term):
// dense self-term GEMM + fused combine epilogue
// ---------------------------------------------------------------------------
__global__ __launch_bounds__(256, 2)
void dense_mma_p(const __half* __restrict__ in, __half* __restrict__ outAct,
                 const __half* __restrict__ Wk, const float* __restrict__ bias,
                 const __half* __restrict__ resid, int relu, int sparse,
                 int n, int ntiles)
{
    const int mytiles = (ntiles - (int)blockIdx.x + (int)gridDim.x - 1) / (int)gridDim.x;
    if (mytiles <= 0) return;
    const int total = 4 * mytiles;

    extern __shared__ char smem[];
    const uint32_t sb = smem_u32(smem);
    const int tid = threadIdx.x, wid = tid >> 5, lane = tid & 31;
    const int lr = lane >> 2, lc = lane & 3;
    const int rg = wid & 3, cg = wid >> 2;
    const int arow = lane & 15;
    const int swd = arow & 7;
    const uint32_t MB = sb + BFULL;
    const uint32_t ABASE = sb + BFULL + 64;

    if (tid == 0) { MBAR_INIT(MB, 1); MBAR_INIT(MB + 8, 1); }
    __syncthreads();

    auto produceA = [&](int jj) {
        if (tid == 0) {
            const int tl = jj >> 2, cc = jj & 3;
            const int row0 = ((int)blockIdx.x + tl * (int)gridDim.x) * TM;
            uint32_t mb = MB + (jj & 1) * 8;
            MBAR_EXPECT_TX(mb, ASTG);
            bulk_g2s(ABASE + (jj & 1) * ASTG, in + ACT_OFF(row0, cc), ASTG, mb);
        }
    };

    // B load (once)
#pragma unroll
    for (int i = 0; i < 16; i++) {
        int u = tid + 256 * i;
        int r = u >> 5, q = u & 31;
        cp_async16_cg(sb + r * BPITCH + q * 16, Wk + (size_t)r * 256 + q * 8, true);
    }
    CP_COMMIT();

    float acc[2][8][4];
#pragma unroll
    for (int mt = 0; mt < 2; mt++)
#pragma unroll
        for (int nt = 0; nt < 8; nt++)
#pragma unroll
            for (int j = 0; j < 4; j++) acc[mt][nt][j] = 0.f;

    float2 bv[8];
#pragma unroll
    for (int nt = 0; nt < 8; nt++)
        bv[nt] = *(const float2*)(bias + cg * 64 + nt * 8 + lc * 2);

    produceA(0);
    produceA(1);

    for (int jj = 0; jj < total; jj++) {
        mbar_wait(MB + (jj & 1) * 8, (jj >> 1) & 1);
        if (jj == 0) { cp_wait<0>(); __syncthreads(); }
        gemm_chunk_p<true>(ABASE + (jj & 1) * ASTG, sb, jj & 3, rg, cg, lane,
                           swd, swd, acc);

        if ((jj & 3) == 3) {
            const int row0 = ((int)blockIdx.x + (jj >> 2) * (int)gridDim.x) * TM;
#pragma unroll
            for (int mt = 0; mt < 2; mt++) {
#pragma unroll
                for (int hf = 0; hf < 2; hf++) {
                    int row = row0 + rg * 32 + mt * 16 + hf * 8 + lr;
                    if (row >= n) continue;
                    const int sw = row & 7;
                    float v[8][2];
#pragma unroll
                    for (int nt = 0; nt < 8; nt++) {
                        v[nt][0] = acc[mt][nt][hf * 2 + 0] + bv[nt].x;
                        v[nt][1] = acc[mt][nt][hf * 2 + 1] + bv[nt].y;
                    }
                    if (sparse) {
                        int basem = g_mbase[row];
                        int mc = g_mcnt[row];
                        const float* sp = g_scr + (size_t)basem * C + cg * 64 + lc * 2;
                        for (int j = 0; j < mc; j++) {
#pragma unroll
                            for (int nt = 0; nt < 8; nt++) {
                                float2 sv = *(const float2*)(sp + nt * 8);
                                v[nt][0] += sv.x;
                                v[nt][1] += sv.y;
                            }
                            sp += C;
                        }
                    }
#pragma unroll
                    for (int nt = 0; nt < 8; nt++) {
                        size_t pb = ACT_OFF(row, 2 * cg + (nt >> 2));
                        size_t oh = pb + 8 * ((nt & 3) ^ sw) + lc * 2;
                        size_t ol = pb + 8 * ((4 + (nt & 3)) ^ sw) + lc * 2;
                        float v0 = v[nt][0], v1 = v[nt][1];
                        if (resid) {
                            __half2 rh = *(const __half2*)(resid + oh);
                            __half2 rl = *(const __half2*)(resid + ol);
                            v0 += __half2float(__low2half(rh)) + __half2float(__low2half(rl));
                            v1 += __half2float(__high2half(rh)) + __half2float(__high2half(rl));
                        }
                        if (relu) { v0 = fmaxf(v0, 0.f); v1 = fmaxf(v1, 0.f); }
                        __half h0, l0, h1, l1;
                        split2(v0, h0, l0);
                        split2(v1, h1, l1);
                        *(__half2*)(outAct + oh) = __halves2half2(h0, h1);
                        *(__half2*)(outAct + ol) = __halves2half2(l0, l1);
                    }
                }
            }
#pragma unroll
            for (int mt = 0; mt < 2; mt++)
#pragma unroll
                for (int nt = 0; nt < 8; nt++)
#pragma unroll
                    for (int j = 0; j < 4; j++) acc[mt][nt][j] = 0.f;
        }
        __syncthreads();
        if (jj + 2 < total) produceA(jj + 2);
    }
}

// ---------------------------------------------------------------------------
// Input layer (Cin = 1), sparsity-compacted, swizzled chunk-plane store
// ---------------------------------------------------------------------------
__global__ __launch_bounds__(256)
void layer_in_kernel(const float* __restrict__ x, __half* __restrict__ outAct,
                     const float* __restrict__ Win, const float* __restrict__ bin,
                     const int* __restrict__ nbr, int n)
{
    __shared__ float ws[KNBR][C];
    __shared__ float s_val[128][28];
    __shared__ unsigned char s_kk[128][28];
    __shared__ int s_cnt[128];
    const int tid  = threadIdx.x;
    const int row0 = blockIdx.x * 128;

    for (int f = tid; f < KNBR * C; f += 256) ws[f / C][f & (C - 1)] = Win[f];
    if (tid < 128) {
        int row = row0 + tid;
        int j = 0;
        if (row < n) {
            const int* np = nbr + (size_t)row * KNBR;
#pragma unroll
            for (int k = 0; k < KNBR; k++) {
                int g = np[k];
                if (g >= 0) {
                    s_kk[tid][j] = (unsigned char)k;
                    s_val[tid][j] = x[g];
                    j++;
                }
            }
        }
        s_cnt[tid] = j;
    }
    __syncthreads();

    const int c  = tid & (C - 1);
    const int rg = tid >> 7;
    const float b = bin[c];
    const int cc = c >> 5, ci = c & 31;
    for (int r = rg; r < 128; r += 2) {
        int row = row0 + r;
        if (row >= n) continue;
        float acc = b;
        int cnt = s_cnt[r];
        for (int j = 0; j < cnt; j++)
            acc += s_val[r][j] * ws[s_kk[r][j]][c];
        acc = fmaxf(acc, 0.f);
        __half h, l; split2(acc, h, l);
        const int sw = row & 7;
        size_t pb = ACT_OFF(row, cc);
        outAct[pb + 8 * ((ci >> 3) ^ sw) + (ci & 7)] = h;
        outAct[pb + 8 * ((4 + (ci >> 3)) ^ sw) + (ci & 7)] = l;
    }
}

// ---------------------------------------------------------------------------
// Final layer (reads swizzled act)
// ---------------------------------------------------------------------------
__global__ __launch_bounds__(256)
void final_kernel(const __half* __restrict__ act, float* __restrict__ out,
                  const float* __restrict__ Wf3, const float* __restrict__ bf3, int n)
{
    __shared__ float hs[64][C + 1];
    __shared__ float wl[C * 3];
    __shared__ float bl[3];
    const int tid  = threadIdx.x;
    const int row0 = blockIdx.x * 64;

    for (int flat = tid; flat < 64 * C / 2; flat += 256) {
        int r = flat >> 6, q = flat & 63;
        int row = row0 + r;
        int col = q * 2;
        float v0 = 0.f, v1 = 0.f;
        if (row < n) {
            const int sw = row & 7;
            const int cc = col >> 5, ci = col & 31;
            size_t pb = ACT_OFF(row, cc);
            __half2 rh = *(const __half2*)(act + pb + 8 * ((ci >> 3) ^ sw) + (ci & 7));
            __half2 rl = *(const __half2*)(act + pb + 8 * ((4 + (ci >> 3)) ^ sw) + (ci & 7));
            v0 = __half2float(__low2half(rh)) + __half2float(__low2half(rl));
            v1 = __half2float(__high2half(rh)) + __half2float(__high2half(rl));
        }
        hs[r][col] = v0;
        hs[r][col + 1] = v1;
    }
    for (int flat = tid; flat < C * 3; flat += 256) wl[flat] = Wf3[flat];
    if (tid < 3) bl[tid] = bf3[tid];
    __syncthreads();

    if (tid < 192) {
        int r = tid / 3, j = tid % 3;
        int row = row0 + r;
        if (row < n) {
            float acc = bl[j];
#pragma unroll 4
            for (int ci = 0; ci < C; ci++) acc += hs[r][ci] * wl[ci * 3 + j];
            out[(size_t)row * 3 + j] = acc;
        }
    }
}

// ---------------------------------------------------------------------------
extern "C" void kernel_launch(void* const* d_in, const int* in_sizes, int n_in,
                              void* d_out, int out_size)
{
    const float* x_feat = (const float*)d_in[0];
    const float* W_in   = (const float*)d_in[1];
    const float* b_in   = (const float*)d_in[2];
    const float* W_res  = (const float*)d_in[3];
    const float* b_res  = (const float*)d_in[4];
    const float* W_out  = (const float*)d_in[5];
    const float* b_out  = (const float*)d_in[6];
    const float* Wf1    = (const float*)d_in[7];
    const float* bf1    = (const float*)d_in[8];
    const float* Wf2    = (const float*)d_in[9];
    const float* bf2    = (const float*)d_in[10];
    const float* Wf3    = (const float*)d_in[11];
    const float* bf3    = (const float*)d_in[12];
    const int*   nbr    = (const int*)d_in[13];
    float* out = (float*)d_out;

    const int n = in_sizes[0];

    __half *actA, *actB, *Wt;
    cudaGetSymbolAddress((void**)&actA, g_actA);
    cudaGetSymbolAddress((void**)&actB, g_actB);
    cudaGetSymbolAddress((void**)&Wt, g_Wt);

    cudaFuncSetAttribute(sparse_mma_p, cudaFuncAttributeMaxDynamicSharedMemorySize, SP4_SMEM);
    cudaFuncSetAttribute(dense_mma_p, cudaFuncAttributeMaxDynamicSharedMemorySize, DN3_SMEM);

    const int ntiles = (n + TM - 1) / TM;
    const int gridM  = (n + 127) / 128;
    const int gridD  = ntiles < GDMAX ? ntiles : GDMAX;
    const int gridS  = NSEG * PSP;
    const int nb     = (n + 1023) / 1024;

    prep_w_kernel<<<N_WMAT, 256>>>(W_res, W_out, Wf1, Wf2);
    count_scan_kernel<<<nb, 1024>>>(nbr, n);
    scan_bsum_kernel<<<1, 1024>>>(nb);
    emit_pairs_kernel<<<nb, 1024>>>(nbr, n);

    layer_in_kernel<<<gridM, 256>>>(x_feat, actA, W_in, b_in, nbr, n);

    for (int i = 0; i < 3; i++) {
        const __half* W0 = Wt + ((size_t)((i * 2 + 0) * KNBR) << 15);
        const __half* W1 = Wt + ((size_t)((i * 2 + 1) * KNBR) << 15);
        const float* b0 = b_res + (size_t)(i * 2 + 0) * C;
        const float* b1 = b_res + (size_t)(i * 2 + 1) * C;
        sparse_mma_p<<<gridS, 256, SP4_SMEM>>>(actA, W0);
        dense_mma_p<<<gridD, 256, DN3_SMEM>>>(actA, actB, W0 + ((size_t)13 << 15),
                                              b0, nullptr, 1, 1, n, ntiles);
        sparse_mma_p<<<gridS, 256, SP4_SMEM>>>(actB, W1);
        dense_mma_p<<<gridD, 256, DN3_SMEM>>>(actB, actA, W1 + ((size_t)13 << 15),
                                              b1, actA, 0, 1, n, ntiles);
    }

    const __half* Wo = Wt + ((size_t)(6 * KNBR) << 15);
    sparse_mma_p<<<gridS, 256, SP4_SMEM>>>(actA, Wo);
    dense_mma_p<<<gridD, 256, DN3_SMEM>>>(actA, actB, Wo + ((size_t)13 << 15),
                                          b_out, nullptr, 0, 1, n, ntiles);

    dense_mma_p<<<gridD, 256, DN3_SMEM>>>(actB, actA, Wt + ((size_t)189 << 15),
                                          bf1, nullptr, 1, 0, n, ntiles);
    dense_mma_p<<<gridD, 256, DN3_SMEM>>>(actA, actB, Wt + ((size_t)190 << 15),
                                          bf2, nullptr, 1, 0, n, ntiles);

    final_kernel<<<(n + 63) / 64, 256>>>(actB, out, Wf3, bf3, n);
}

// round 16
// speedup vs baseline: 1.1871x; 1.0161x over previous
#include <cuda_runtime.h>
#include <cuda_fp16.h>
#include <cstdint>

#define C      128
#define KNBR   27
#define TM     128
#define NMAX   300000
#define NMAXP  300032                 // padded rows (dense bulk tail overread)
#define N_WMAT 191
#define CAP    16384
#define NSEG   27
#define SCR_ROWS (1 << 21)
#define NBMAX  512
#define PSP    11                     // sparse persistent CTAs per k
#define GDMAX  296                    // dense persistent CTAs, 2/SM

#define ASTG   16384                  // A stage: 128 rows x 128 B (swizzled)
#define BPITCH 528                    // dense B row: 512B + 16B pad
#define BFULL  67584                  // dense: 128 * BPITCH
#define BP_SP  272                    // sparse B row: 256B (hi only) + 16B pad
#define BFULL_SP 34816                // sparse: 128 * BP_SP
#define DN3_SMEM (BFULL + 64 + 2 * ASTG)             // 100416
#define SP5_SMEM (BFULL_SP + 64 + 1024 + 2 * ASTG)   // 68672

#define PLSTR ((size_t)NMAXP * 64)    // plane stride in halfs
#define ACT_OFF(row, cc) ((size_t)(cc) * PLSTR + (size_t)(row) * 64)

// activations: 4 chunk-planes; per row 128 B = [hi32|lo32] halfs, bytes
// swizzled within the row: blk16 ^= (row & 7)
__device__ __half g_actA[(size_t)NMAXP * 256];
__device__ __half g_actB[(size_t)NMAXP * 256];
__device__ __half g_Wt[(size_t)N_WMAT * 32768];
__device__ float         g_scr[(size_t)SCR_ROWS * C];
__device__ unsigned      g_cnt[NSEG];
__device__ int           g_pairg[NSEG * CAP];
__device__ int           g_slot[NSEG * CAP];
__device__ int           g_mbase[NMAX];
__device__ unsigned char g_mcnt[NMAX];
__device__ int           g_bsum[NBMAX];
__device__ int           g_boff[NBMAX];
__device__ int           g_kcnt[NSEG * NBMAX];
__device__ int           g_kbase[NSEG * NBMAX];

// ---------------------------------------------------------------------------
static __device__ __forceinline__ void cp_async16_cg(uint32_t dst, const void* src, bool pred) {
    int sz = pred ? 16 : 0;
    asm volatile("cp.async.cg.shared.global [%0], [%1], 16, %2;"
                 :: "r"(dst), "l"(src), "r"(sz) : "memory");
}
#define CP_COMMIT() asm volatile("cp.async.commit_group;" ::: "memory")
template <int N> static __device__ __forceinline__ void cp_wait() {
    asm volatile("cp.async.wait_group %0;" :: "n"(N) : "memory");
}
static __device__ __forceinline__ uint32_t smem_u32(const void* p) {
    uint32_t a;
    asm("{ .reg .u64 t; cvta.to.shared.u64 t, %1; cvt.u32.u64 %0, t; }"
        : "=r"(a) : "l"(p));
    return a;
}
#define MBAR_INIT(a, c) \
    asm volatile("mbarrier.init.shared.b64 [%0], %1;" :: "r"(a), "r"((uint32_t)(c)) : "memory")
#define MBAR_EXPECT_TX(a, b) \
    asm volatile("mbarrier.arrive.expect_tx.shared.b64 _, [%0], %1;" \
                 :: "r"(a), "r"((uint32_t)(b)) : "memory")
static __device__ __forceinline__ void bulk_g2s(uint32_t dst, const void* src,
                                                uint32_t bytes, uint32_t mbar) {
    asm volatile(
        "cp.async.bulk.shared::cluster.global.mbarrier::complete_tx::bytes "
        "[%0], [%1], %2, [%3];"
        :: "r"(dst), "l"(src), "r"(bytes), "r"(mbar) : "memory");
}
static __device__ __forceinline__ void mbar_wait(uint32_t mbar, uint32_t parity) {
    asm volatile(
        "{\n\t.reg .pred P;\n\t"
        "WL%=:\n\t"
        "mbarrier.try_wait.parity.shared.b64 P, [%0], %1, 0x989680;\n\t"
        "@P bra WD%=;\n\t"
        "bra WL%=;\n\t"
        "WD%=:\n\t}"
        :: "r"(mbar), "r"(parity) : "memory");
}
static __device__ __forceinline__ void mma_f16(float* c, const uint32_t* a,
                                               uint32_t b0, uint32_t b1) {
    asm volatile(
        "mma.sync.aligned.m16n8k16.row.col.f32.f16.f16.f32 "
        "{%0,%1,%2,%3}, {%4,%5,%6,%7}, {%8,%9}, {%0,%1,%2,%3};"
        : "+f"(c[0]), "+f"(c[1]), "+f"(c[2]), "+f"(c[3])
        : "r"(a[0]), "r"(a[1]), "r"(a[2]), "r"(a[3]), "r"(b0), "r"(b1));
}
static __device__ __forceinline__ void ldsm4(uint32_t* r, uint32_t addr) {
    asm volatile("ldmatrix.sync.aligned.m8n8.x4.shared.b16 {%0,%1,%2,%3}, [%4];"
                 : "=r"(r[0]), "=r"(r[1]), "=r"(r[2]), "=r"(r[3]) : "r"(addr));
}
static __device__ __forceinline__ void split2(float v, __half& h, __half& l) {
    h = __float2half_rn(v);
    l = __float2half_rn(v - __half2float(h));
}

// ---------------------------------------------------------------------------
// Compensated inner loop, one 32-ci chunk.
// FULL=true (dense): 3 terms, B row pitch BP with chunk at cc*CCMUL, lo at +64.
// FULL=false (sparse): 2 terms, hi-only B tile.
// A stage: 128 rows x 128 B, per-row swizzle (sw0 / sw1).
// ---------------------------------------------------------------------------
template <bool FULL, int BP, int CCMUL>
static __device__ __forceinline__ void gemm_chunk_p(uint32_t smA, uint32_t smB, int cc,
                                                    int rg, int cg, int lane,
                                                    int sw0, int sw1,
                                                    float acc[2][8][4])
{
    const int arow = lane & 15, asel = (lane >> 4) & 1;
    const int brow = (lane & 7) + ((lane >> 4) & 1) * 8;
    const int bsel = (lane >> 3) & 1;
#pragma unroll
    for (int ks = 0; ks < 2; ks++) {
        uint32_t ar0 = smA + (rg * 32 + arow) * 128;
        uint32_t ar1 = smA + (rg * 32 + 16 + arow) * 128;
        uint32_t baddr = smB + (cg * 64 + brow) * BP + cc * CCMUL + ks * 32 + bsel * 16;
        uint32_t ah[2][4], al[2][4], bf[4][4];
        ldsm4(ah[0], ar0 + 16 * ((2 * ks + asel) ^ sw0));
        ldsm4(ah[1], ar1 + 16 * ((2 * ks + asel) ^ sw1));
        ldsm4(al[0], ar0 + 16 * ((4 + 2 * ks + asel) ^ sw0));
        ldsm4(al[1], ar1 + 16 * ((4 + 2 * ks + asel) ^ sw1));
#pragma unroll
        for (int t = 0; t < 4; t++) ldsm4(bf[t], baddr + t * 16 * BP);
#pragma unroll
        for (int t = 0; t < 4; t++)
#pragma unroll
            for (int h = 0; h < 2; h++) {
                int nt = t * 2 + h;
                mma_f16(acc[0][nt], ah[0], bf[t][2 * h], bf[t][2 * h + 1]);
                mma_f16(acc[1][nt], ah[1], bf[t][2 * h], bf[t][2 * h + 1]);
                mma_f16(acc[0][nt], al[0], bf[t][2 * h], bf[t][2 * h + 1]);
                mma_f16(acc[1][nt], al[1], bf[t][2 * h], bf[t][2 * h + 1]);
            }
        if (FULL) {
#pragma unroll
            for (int t = 0; t < 4; t++) ldsm4(bf[t], baddr + 64 + t * 16 * BP);
#pragma unroll
            for (int t = 0; t < 4; t++)
#pragma unroll
                for (int h = 0; h < 2; h++) {
                    int nt = t * 2 + h;
                    mma_f16(acc[0][nt], ah[0], bf[t][2 * h], bf[t][2 * h + 1]);
                    mma_f16(acc[1][nt], ah[1], bf[t][2 * h], bf[t][2 * h + 1]);
                }
        }
    }
}

// ---------------------------------------------------------------------------
// Merged prepass: blocks [0,191) transpose+split weights; blocks [191,191+nb)
// do the m-count scan + per-k histogram. (Keeps ncu's capture slot on the
// dense GEMM.)
// ---------------------------------------------------------------------------
__global__ __launch_bounds__(1024)
void prep_count_kernel(const float* __restrict__ W_res,
                       const float* __restrict__ W_out,
                       const float* __restrict__ Wf1,
                       const float* __restrict__ Wf2,
                       const int* __restrict__ nbr, int n)
{
    const int tid = threadIdx.x, lane = tid & 31, wid = tid >> 5;

    if (blockIdx.x < N_WMAT) {
        __shared__ float t[32][33];
        const int b = blockIdx.x;
        const float* src;
        if (b < 162)       src = W_res + (size_t)b * C * C;
        else if (b < 189)  src = W_out + (size_t)(b - 162) * C * C;
        else if (b == 189) src = Wf1;
        else               src = Wf2;
        __half* dst = g_Wt + ((size_t)b << 15);

        const int j = lane, i0 = wid;   // 32x32 threads
        for (int tile = 0; tile < 16; tile++) {
            const int tr = tile >> 2, tc = tile & 3;
            __syncthreads();
            t[i0][j] = src[(tr * 32 + i0) * C + tc * 32 + j];
            __syncthreads();
            int co = tc * 32 + i0;
            float w = t[j][i0];
            __half h, l; split2(w, h, l);
            size_t o = (size_t)co * 256 + tr * 64 + j;
            dst[o] = h;
            dst[o + 32] = l;
        }
        return;
    }

    // ---- count/scan part ----
    __shared__ int wsum[32];
    __shared__ int s_wk[NSEG * 32];
    const int cb = blockIdx.x - N_WMAT;
    const int m = cb * 1024 + tid;

    unsigned valid27 = 0;
    if (m < n) {
        const int* np = nbr + (size_t)m * KNBR;
#pragma unroll
        for (int k = 0; k < KNBR; k++)
            if (k != 13 && np[k] >= 0) valid27 |= (1u << k);
    }
    int cnt = __popc(valid27);

#pragma unroll
    for (int k = 0; k < KNBR; k++) {
        if (k == 13) continue;
        unsigned ball = __ballot_sync(0xFFFFFFFFu, (valid27 >> k) & 1u);
        if (lane == 0) s_wk[k * 32 + wid] = __popc(ball);
    }

    int v = cnt;
#pragma unroll
    for (int o = 1; o < 32; o <<= 1) {
        int u = __shfl_up_sync(0xFFFFFFFFu, v, o);
        if (lane >= o) v += u;
    }
    if (lane == 31) wsum[wid] = v;
    __syncthreads();
    if (wid == 0) {
        int w = wsum[lane], iv = w;
#pragma unroll
        for (int o = 1; o < 32; o <<= 1) {
            int u = __shfl_up_sync(0xFFFFFFFFu, iv, o);
            if (lane >= o) iv += u;
        }
        wsum[lane] = iv - w;
    }
    __syncthreads();
    int pre = wsum[wid] + v - cnt;
    if (m < n) {
        g_mcnt[m] = (unsigned char)cnt;
        g_mbase[m] = pre;
    }
    if (tid == 1023) g_bsum[cb] = pre + cnt;

    if (wid < NSEG && wid != 13) {
        int t2 = s_wk[wid * 32 + lane];
#pragma unroll
        for (int o = 16; o > 0; o >>= 1) t2 += __shfl_down_sync(0xFFFFFFFFu, t2, o);
        if (lane == 0) g_kcnt[wid * NBMAX + cb] = t2;
    }
}

__global__ __launch_bounds__(1024)
void scan_bsum_kernel(int nb)
{
    __shared__ int s[512];
    const int tid = threadIdx.x, lane = tid & 31, w = tid >> 5;
    int v = 0;
    if (tid < 512) {
        v = (tid < nb) ? g_bsum[tid] : 0;
        s[tid] = v;
    }
    __syncthreads();
    for (int off = 1; off < 512; off <<= 1) {
        int u = (tid < 512 && tid >= off) ? s[tid - off] : 0;
        __syncthreads();
        if (tid < 512) s[tid] += u;
        __syncthreads();
    }
    if (tid < 512 && tid < nb) g_boff[tid] = s[tid] - v;

    if (w < NSEG && w != 13) {
        int run = 0;
        for (int b0 = 0; b0 < nb; b0 += 32) {
            int b = b0 + lane;
            int x = (b < nb) ? g_kcnt[w * NBMAX + b] : 0;
            int inc = x;
#pragma unroll
            for (int o = 1; o < 32; o <<= 1) {
                int u = __shfl_up_sync(0xFFFFFFFFu, inc, o);
                if (lane >= o) inc += u;
            }
            if (b < nb) g_kbase[w * NBMAX + b] = run + inc - x;
            run += __shfl_sync(0xFFFFFFFFu, inc, 31);
        }
        if (lane == 0) g_cnt[w] = (unsigned)run;
    }
    if (tid == 0) g_cnt[13] = 0;
}

__global__ __launch_bounds__(1024)
void emit_pairs_kernel(const int* __restrict__ nbr, int n)
{
    __shared__ int s_wk[NSEG * 32];
    __shared__ int s_kb[NSEG];
    const int tid = threadIdx.x, lane = tid & 31, wid = tid >> 5;
    const int m = blockIdx.x * 1024 + tid;

    unsigned valid27 = 0;
    if (m < n) {
        const int* np = nbr + (size_t)m * KNBR;
#pragma unroll
        for (int k = 0; k < KNBR; k++)
            if (k != 13 && np[k] >= 0) valid27 |= (1u << k);
    }
#pragma unroll
    for (int k = 0; k < KNBR; k++) {
        if (k == 13) continue;
        unsigned ball = __ballot_sync(0xFFFFFFFFu, (valid27 >> k) & 1u);
        if (lane == 0) s_wk[k * 32 + wid] = __popc(ball);
    }
    if (tid < NSEG) s_kb[tid] = (tid != 13) ? g_kbase[tid * NBMAX + blockIdx.x] : 0;
    __syncthreads();

    if (wid < NSEG && wid != 13) {
        int v = s_wk[wid * 32 + lane], orig = v;
#pragma unroll
        for (int o = 1; o < 32; o <<= 1) {
            int u = __shfl_up_sync(0xFFFFFFFFu, v, o);
            if (lane >= o) v += u;
        }
        s_wk[wid * 32 + lane] = v - orig;
    }
    __syncthreads();

    int base = 0;
    if (m < n) base = g_boff[m >> 10] + g_mbase[m];
    const unsigned lt = (1u << lane) - 1u;
    int j = 0;
#pragma unroll
    for (int k = 0; k < KNBR; k++) {
        if (k == 13) continue;
        bool valid = (valid27 >> k) & 1u;
        unsigned ball = __ballot_sync(0xFFFFFFFFu, valid);
        if (valid) {
            int pos = s_kb[k] + s_wk[k * 32 + wid] + __popc(ball & lt);
            if (pos < CAP && base + j < SCR_ROWS) {
                g_pairg[k * CAP + pos] = nbr[(size_t)m * KNBR + k];
                g_slot[k * CAP + pos] = base + j;
            }
            j++;
        }
    }
    if (m < n) g_mbase[m] = base;
}

// ---------------------------------------------------------------------------
// Phase 1 (persistent, B-stationary hi-only, row-bulk TMA gather, 2-term):
// per-k pair GEMM -> fp32 scratch rows (m-sorted slots)
// ---------------------------------------------------------------------------
__global__ __launch_bounds__(256, 2)
void sparse_mma_p(const __half* __restrict__ in, const __half* __restrict__ WtLayer)
{
    const int k = blockIdx.x % NSEG;
    const int c = blockIdx.x / NSEG;
    unsigned cnt = g_cnt[k];
    if (cnt > CAP) cnt = CAP;
    const int ntk = (int)((cnt + TM - 1) / TM);
    const int mytiles = (ntk - c + PSP - 1) / PSP;
    if (mytiles <= 0) return;
    const int total = 4 * mytiles;

    extern __shared__ char smem[];
    const uint32_t sb = smem_u32(smem);
    const int tid = threadIdx.x, wid = tid >> 5, lane = tid & 31;
    const int lr = lane >> 2, lc = lane & 3;
    const int rg = wid & 3, cg = wid >> 2;
    const int arow = lane & 15;

    const uint32_t MB = sb + BFULL_SP;
    int (*s_g)[TM] = (int(*)[TM])(smem + BFULL_SP + 64);
    const uint32_t ABASE = sb + BFULL_SP + 64 + 1024;
    const __half* Wk = WtLayer + ((size_t)k << 15);

    auto tile_base = [&](int tl) { return (c + tl * PSP) * TM; };
    auto vrows = [&](int tl) {
        int v = (int)cnt - tile_base(tl);
        return v > TM ? TM : v;
    };
    auto load_idx = [&](int tl) {
        if (tid < TM) {
            int p = tile_base(tl) + tid;
            s_g[tl & 1][tid] = (p < (int)cnt) ? g_pairg[k * CAP + p] : -1;
        }
    };
    auto issue_bulks = [&](int q) {
        const int tl = q >> 2, cc = q & 3;
        const uint32_t stA = ABASE + (q & 1) * ASTG;
        if (tid < TM) {
            int g = s_g[tl & 1][tid];
            if (g >= 0) {
                bulk_g2s(stA + tid * 128, in + ACT_OFF(g, cc), 128, MB + (q & 1) * 8);
            } else {
                uint4 z = make_uint4(0, 0, 0, 0);
                uint4* row = (uint4*)(smem + BFULL_SP + 64 + 1024 + (q & 1) * ASTG + tid * 128);
#pragma unroll
                for (int i = 0; i < 8; i++) row[i] = z;
            }
        }
    };

    if (tid == 0) { MBAR_INIT(MB, 1); MBAR_INIT(MB + 8, 1); }

    // B load (once): hi-plane halves only, 128 rows x 256 B
#pragma unroll
    for (int i = 0; i < 8; i++) {
        int u = tid + 256 * i;
        int r = u >> 4, piece = u & 15;
        int cc = piece >> 2, p = piece & 3;
        cp_async16_cg(sb + r * BP_SP + cc * 64 + p * 16,
                      Wk + (size_t)r * 256 + cc * 64 + p * 8, true);
    }
    CP_COMMIT();

    load_idx(0);
    if (tid == 0) {
        int vr0 = vrows(0);
        MBAR_EXPECT_TX(MB, (uint32_t)vr0 * 128);
        MBAR_EXPECT_TX(MB + 8, (uint32_t)vr0 * 128);
    }
    __syncthreads();
    issue_bulks(0);
    issue_bulks(1);
    cp_wait<0>();
    __syncthreads();

    float acc[2][8][4];
#pragma unroll
    for (int mt = 0; mt < 2; mt++)
#pragma unroll
        for (int nt = 0; nt < 8; nt++)
#pragma unroll
            for (int j = 0; j < 4; j++) acc[mt][nt][j] = 0.f;

    int sw0 = 0, sw1 = 0;

    for (int jj = 0; jj < total; jj++) {
        const int tl = jj >> 2, buf = tl & 1;
        mbar_wait(MB + (jj & 1) * 8, (jj >> 1) & 1);
        if ((jj & 3) == 0) {
            sw0 = s_g[buf][rg * 32 + arow] & 7;
            sw1 = s_g[buf][rg * 32 + 16 + arow] & 7;
        }
        gemm_chunk_p<false, BP_SP, 64>(ABASE + (jj & 1) * ASTG, sb, jj & 3,
                                       rg, cg, lane, sw0, sw1, acc);
        if ((jj & 3) == 0 && tl + 1 < mytiles) load_idx(tl + 1);

        if ((jj & 3) == 3) {
            const int base = tile_base(tl);
#pragma unroll
            for (int mt = 0; mt < 2; mt++) {
#pragma unroll
                for (int hf = 0; hf < 2; hf++) {
                    int pr = rg * 32 + mt * 16 + hf * 8 + lr;
                    if (base + pr < (int)cnt) {
                        int slot = g_slot[k * CAP + base + pr];
                        if (slot >= 0) {
                            float* op = g_scr + (size_t)slot * C + cg * 64 + lc * 2;
#pragma unroll
                            for (int nt = 0; nt < 8; nt++)
                                *(float2*)(op + nt * 8) =
                                    make_float2(acc[mt][nt][hf * 2 + 0],
                                                acc[mt][nt][hf * 2 + 1]);
                        }
                    }
                }
            }
#pragma unroll
            for (int mt = 0; mt < 2; mt++)
#pragma unroll
                for (int nt = 0; nt < 8; nt++)
#pragma unroll
                    for (int j = 0; j < 4; j++) acc[mt][nt][j] = 0.f;
        }

        if (jj + 2 < total && tid == 0)
            MBAR_EXPECT_TX(MB + (jj & 1) * 8, (uint32_t)vrows((jj + 2) >> 2) * 128);
        __syncthreads();
        if (jj + 2 < total) issue_bulks(jj + 2);
    }
}

// ---------------------------------------------------------------------------
// Phase 2 (persistent, B-stationary, bulk-copy A, 3-term):
// dense self-term GEMM + fused combine epilogue
// ---------------------------------------------------------------------------
__global__ __launch_bounds__(256, 2)
void dense_mma_p(const __half* __restrict__ in, __half* __restrict__ outAct,
                 const __half* __restrict__ Wk, const float* __restrict__ bias,
                 const __half* __restrict__ resid, int relu, int sparse,
                 int n, int ntiles)
{
    const int mytiles = (ntiles - (int)blockIdx.x + (int)gridDim.x - 1) / (int)gridDim.x;
    if (mytiles <= 0) return;
    const int total = 4 * mytiles;

    extern __shared__ char smem[];
    const uint32_t sb = smem_u32(smem);
    const int tid = threadIdx.x, wid = tid >> 5, lane = tid & 31;
    const int lr = lane >> 2, lc = lane & 3;
    const int rg = wid & 3, cg = wid >> 2;
    const int arow = lane & 15;
    const int swd = arow & 7;
    const uint32_t MB = sb + BFULL;
    const uint32_t ABASE = sb + BFULL + 64;

    if (tid == 0) { MBAR_INIT(MB, 1); MBAR_INIT(MB + 8, 1); }
    __syncthreads();

    auto produceA = [&](int jj) {
        if (tid == 0) {
            const int tl = jj >> 2, cc = jj & 3;
            const int row0 = ((int)blockIdx.x + tl * (int)gridDim.x) * TM;
            uint32_t mb = MB + (jj & 1) * 8;
            MBAR_EXPECT_TX(mb, ASTG);
            bulk_g2s(ABASE + (jj & 1) * ASTG, in + ACT_OFF(row0, cc), ASTG, mb);
        }
    };

    // B load (once): full hi+lo
#pragma unroll
    for (int i = 0; i < 16; i++) {
        int u = tid + 256 * i;
        int r = u >> 5, q = u & 31;
        cp_async16_cg(sb + r * BPITCH + q * 16, Wk + (size_t)r * 256 + q * 8, true);
    }
    CP_COMMIT();

    float acc[2][8][4];
#pragma unroll
    for (int mt = 0; mt < 2; mt++)
#pragma unroll
        for (int nt = 0; nt < 8; nt++)
#pragma unroll
            for (int j = 0; j < 4; j++) acc[mt][nt][j] = 0.f;

    float2 bv[8];
#pragma unroll
    for (int nt = 0; nt < 8; nt++)
        bv[nt] = *(const float2*)(bias + cg * 64 + nt * 8 + lc * 2);

    produceA(0);
    produceA(1);

    for (int jj = 0; jj < total; jj++) {
        mbar_wait(MB + (jj & 1) * 8, (jj >> 1) & 1);
        if (jj == 0) { cp_wait<0>(); __syncthreads(); }
        gemm_chunk_p<true, BPITCH, 128>(ABASE + (jj & 1) * ASTG, sb, jj & 3,
                                        rg, cg, lane, swd, swd, acc);

        if ((jj & 3) == 3) {
            const int row0 = ((int)blockIdx.x + (jj >> 2) * (int)gridDim.x) * TM;
#pragma unroll
            for (int mt = 0; mt < 2; mt++) {
#pragma unroll
                for (int hf = 0; hf < 2; hf++) {
                    int row = row0 + rg * 32 + mt * 16 + hf * 8 + lr;
                    if (row >= n) continue;
                    const int sw = row & 7;
                    float v[8][2];
#pragma unroll
                    for (int nt = 0; nt < 8; nt++) {
                        v[nt][0] = acc[mt][nt][hf * 2 + 0] + bv[nt].x;
                        v[nt][1] = acc[mt][nt][hf * 2 + 1] + bv[nt].y;
                    }
                    if (sparse) {
                        int basem = g_mbase[row];
                        int mc = g_mcnt[row];
                        const float* sp = g_scr + (size_t)basem * C + cg * 64 + lc * 2;
                        for (int j = 0; j < mc; j++) {
#pragma unroll
                            for (int nt = 0; nt < 8; nt++) {
                                float2 sv = *(const float2*)(sp + nt * 8);
                                v[nt][0] += sv.x;
                                v[nt][1] += sv.y;
                            }
                            sp += C;
                        }
                    }
#pragma unroll
                    for (int nt = 0; nt < 8; nt++) {
                        size_t pb = ACT_OFF(row, 2 * cg + (nt >> 2));
                        size_t oh = pb + 8 * ((nt & 3) ^ sw) + lc * 2;
                        size_t ol = pb + 8 * ((4 + (nt & 3)) ^ sw) + lc * 2;
                        float v0 = v[nt][0], v1 = v[nt][1];
                        if (resid) {
                            __half2 rh = *(const __half2*)(resid + oh);
                            __half2 rl = *(const __half2*)(resid + ol);
                            v0 += __half2float(__low2half(rh)) + __half2float(__low2half(rl));
                            v1 += __half2float(__high2half(rh)) + __half2float(__high2half(rl));
                        }
                        if (relu) { v0 = fmaxf(v0, 0.f); v1 = fmaxf(v1, 0.f); }
                        __half h0, l0, h1, l1;
                        split2(v0, h0, l0);
                        split2(v1, h1, l1);
                        *(__half2*)(outAct + oh) = __halves2half2(h0, h1);
                        *(__half2*)(outAct + ol) = __halves2half2(l0, l1);
                    }
                }
            }
#pragma unroll
            for (int mt = 0; mt < 2; mt++)
#pragma unroll
                for (int nt = 0; nt < 8; nt++)
#pragma unroll
                    for (int j = 0; j < 4; j++) acc[mt][nt][j] = 0.f;
        }
        __syncthreads();
        if (jj + 2 < total) produceA(jj + 2);
    }
}

// ---------------------------------------------------------------------------
// Input layer (Cin = 1), sparsity-compacted, swizzled chunk-plane store
// ---------------------------------------------------------------------------
__global__ __launch_bounds__(256)
void layer_in_kernel(const float* __restrict__ x, __half* __restrict__ outAct,
                     const float* __restrict__ Win, const float* __restrict__ bin,
                     const int* __restrict__ nbr, int n)
{
    __shared__ float ws[KNBR][C];
    __shared__ float s_val[128][28];
    __shared__ unsigned char s_kk[128][28];
    __shared__ int s_cnt[128];
    const int tid  = threadIdx.x;
    const int row0 = blockIdx.x * 128;

    for (int f = tid; f < KNBR * C; f += 256) ws[f / C][f & (C - 1)] = Win[f];
    if (tid < 128) {
        int row = row0 + tid;
        int j = 0;
        if (row < n) {
            const int* np = nbr + (size_t)row * KNBR;
#pragma unroll
            for (int k = 0; k < KNBR; k++) {
                int g = np[k];
                if (g >= 0) {
                    s_kk[tid][j] = (unsigned char)k;
                    s_val[tid][j] = x[g];
                    j++;
                }
            }
        }
        s_cnt[tid] = j;
    }
    __syncthreads();

    const int c  = tid & (C - 1);
    const int rg = tid >> 7;
    const float b = bin[c];
    const int cc = c >> 5, ci = c & 31;
    for (int r = rg; r < 128; r += 2) {
        int row = row0 + r;
        if (row >= n) continue;
        float acc = b;
        int cnt = s_cnt[r];
        for (int j = 0; j < cnt; j++)
            acc += s_val[r][j] * ws[s_kk[r][j]][c];
        acc = fmaxf(acc, 0.f);
        __half h, l; split2(acc, h, l);
        const int sw = row & 7;
        size_t pb = ACT_OFF(row, cc);
        outAct[pb + 8 * ((ci >> 3) ^ sw) + (ci & 7)] = h;
        outAct[pb + 8 * ((4 + (ci >> 3)) ^ sw) + (ci & 7)] = l;
    }
}

// ---------------------------------------------------------------------------
// Final layer (reads swizzled act)
// ---------------------------------------------------------------------------
__global__ __launch_bounds__(256)
void final_kernel(const __half* __restrict__ act, float* __restrict__ out,
                  const float* __restrict__ Wf3, const float* __restrict__ bf3, int n)
{
    __shared__ float hs[64][C + 1];
    __shared__ float wl[C * 3];
    __shared__ float bl[3];
    const int tid  = threadIdx.x;
    const int row0 = blockIdx.x * 64;

    for (int flat = tid; flat < 64 * C / 2; flat += 256) {
        int r = flat >> 6, q = flat & 63;
        int row = row0 + r;
        int col = q * 2;
        float v0 = 0.f, v1 = 0.f;
        if (row < n) {
            const int sw = row & 7;
            const int cc = col >> 5, ci = col & 31;
            size_t pb = ACT_OFF(row, cc);
            __half2 rh = *(const __half2*)(act + pb + 8 * ((ci >> 3) ^ sw) + (ci & 7));
            __half2 rl = *(const __half2*)(act + pb + 8 * ((4 + (ci >> 3)) ^ sw) + (ci & 7));
            v0 = __half2float(__low2half(rh)) + __half2float(__low2half(rl));
            v1 = __half2float(__high2half(rh)) + __half2float(__high2half(rl));
        }
        hs[r][col] = v0;
        hs[r][col + 1] = v1;
    }
    for (int flat = tid; flat < C * 3; flat += 256) wl[flat] = Wf3[flat];
    if (tid < 3) bl[tid] = bf3[tid];
    __syncthreads();

    if (tid < 192) {
        int r = tid / 3, j = tid % 3;
        int row = row0 + r;
        if (row < n) {
            float acc = bl[j];
#pragma unroll 4
            for (int ci = 0; ci < C; ci++) acc += hs[r][ci] * wl[ci * 3 + j];
            out[(size_t)row * 3 + j] = acc;
        }
    }
}

// ---------------------------------------------------------------------------
extern "C" void kernel_launch(void* const* d_in, const int* in_sizes, int n_in,
                              void* d_out, int out_size)
{
    const float* x_feat = (const float*)d_in[0];
    const float* W_in   = (const float*)d_in[1];
    const float* b_in   = (const float*)d_in[2];
    const float* W_res  = (const float*)d_in[3];
    const float* b_res  = (const float*)d_in[4];
    const float* W_out  = (const float*)d_in[5];
    const float* b_out  = (const float*)d_in[6];
    const float* Wf1    = (const float*)d_in[7];
    const float* bf1    = (const float*)d_in[8];
    const float* Wf2    = (const float*)d_in[9];
    const float* bf2    = (const float*)d_in[10];
    const float* Wf3    = (const float*)d_in[11];
    const float* bf3    = (const float*)d_in[12];
    const int*   nbr    = (const int*)d_in[13];
    float* out = (float*)d_out;

    const int n = in_sizes[0];

    __half *actA, *actB, *Wt;
    cudaGetSymbolAddress((void**)&actA, g_actA);
    cudaGetSymbolAddress((void**)&actB, g_actB);
    cudaGetSymbolAddress((void**)&Wt, g_Wt);

    cudaFuncSetAttribute(sparse_mma_p, cudaFuncAttributeMaxDynamicSharedMemorySize, SP5_SMEM);
    cudaFuncSetAttribute(dense_mma_p, cudaFuncAttributeMaxDynamicSharedMemorySize, DN3_SMEM);

    const int ntiles = (n + TM - 1) / TM;
    const int gridM  = (n + 127) / 128;
    const int gridD  = ntiles < GDMAX ? ntiles : GDMAX;
    const int gridS  = NSEG * PSP;
    const int nb     = (n + 1023) / 1024;

    prep_count_kernel<<<N_WMAT + nb, 1024>>>(W_res, W_out, Wf1, Wf2, nbr, n);
    scan_bsum_kernel<<<1, 1024>>>(nb);
    emit_pairs_kernel<<<nb, 1024>>>(nbr, n);

    layer_in_kernel<<<gridM, 256>>>(x_feat, actA, W_in, b_in, nbr, n);

    for (int i = 0; i < 3; i++) {
        const __half* W0 = Wt + ((size_t)((i * 2 + 0) * KNBR) << 15);
        const __half* W1 = Wt + ((size_t)((i * 2 + 1) * KNBR) << 15);
        const float* b0 = b_res + (size_t)(i * 2 + 0) * C;
        const float* b1 = b_res + (size_t)(i * 2 + 1) * C;
        sparse_mma_p<<<gridS, 256, SP5_SMEM>>>(actA, W0);
        dense_mma_p<<<gridD, 256, DN3_SMEM>>>(actA, actB, W0 + ((size_t)13 << 15),
                                              b0, nullptr, 1, 1, n, ntiles);
        sparse_mma_p<<<gridS, 256, SP5_SMEM>>>(actB, W1);
        dense_mma_p<<<gridD, 256, DN3_SMEM>>>(actB, actA, W1 + ((size_t)13 << 15),
                                              b1, actA, 0, 1, n, ntiles);
    }

    const __half* Wo = Wt + ((size_t)(6 * KNBR) << 15);
    sparse_mma_p<<<gridS, 256, SP5_SMEM>>>(actA, Wo);
    dense_mma_p<<<gridD, 256, DN3_SMEM>>>(actA, actB, Wo + ((size_t)13 << 15),
                                          b_out, nullptr, 0, 1, n, ntiles);

    dense_mma_p<<<gridD, 256, DN3_SMEM>>>(actB, actA, Wt + ((size_t)189 << 15),
                                          bf1, nullptr, 1, 0, n, ntiles);
    dense_mma_p<<<gridD, 256, DN3_SMEM>>>(actA, actB, Wt + ((size_t)190 << 15),
                                          bf2, nullptr, 1, 0, n, ntiles);

    final_kernel<<<(n + 63) / 64, 256>>>(actB, out, Wf3, bf3, n);
}

// round 17
// speedup vs baseline: 1.2289x; 1.0352x over previous
#include <cuda_runtime.h>
#include <cuda_fp16.h>
#include <cstdint>

#define C      128
#define KNBR   27
#define TM     128
#define NMAX   300000
#define NMAXP  300032                 // padded rows (dense bulk tail overread)
#define N_WMAT 191
#define CAP    16384
#define NSEG   27
#define SCR_ROWS (1 << 21)
#define NBMAX  512
#define PSP    11                     // sparse persistent CTAs per k
#define GDMAX  296                    // dense persistent CTAs, 2/SM

#define ASTG   16384                  // A stage: 128 rows x 128 B (swizzled)
#define BPITCH 528                    // dense B row: 512B + 16B pad
#define BFULL  67584                  // dense: 128 * BPITCH
#define BP_SP  272                    // sparse B row: 256B (hi only) + 16B pad
#define BFULL_SP 34816                // sparse: 128 * BP_SP
#define DN3_SMEM (BFULL + 64 + 2 * ASTG)             // 100416
#define SP5_SMEM (BFULL_SP + 64 + 1024 + 2 * ASTG)   // 68672

#define PLSTR ((size_t)NMAXP * 64)    // plane stride in halfs
#define ACT_OFF(row, cc) ((size_t)(cc) * PLSTR + (size_t)(row) * 64)

// activations: 4 chunk-planes; per row 128 B = [hi32|lo32] halfs, bytes
// swizzled within the row: blk16 ^= (row & 7)
__device__ __half g_actA[(size_t)NMAXP * 256];
__device__ __half g_actB[(size_t)NMAXP * 256];
__device__ __half g_Wt[(size_t)N_WMAT * 32768];
__device__ float         g_scr[(size_t)SCR_ROWS * C];
__device__ unsigned      g_cnt[NSEG];
__device__ int           g_pairg[NSEG * CAP];
__device__ int           g_slot[NSEG * CAP];
__device__ int           g_mbase[NMAX];
__device__ unsigned char g_mcnt[NMAX];
__device__ int           g_bsum[NBMAX];
__device__ int           g_boff[NBMAX];
__device__ int           g_kcnt[NSEG * NBMAX];
__device__ int           g_kbase[NSEG * NBMAX];

// ---------------------------------------------------------------------------
static __device__ __forceinline__ void cp_async16_cg(uint32_t dst, const void* src, bool pred) {
    int sz = pred ? 16 : 0;
    asm volatile("cp.async.cg.shared.global [%0], [%1], 16, %2;"
                 :: "r"(dst), "l"(src), "r"(sz) : "memory");
}
#define CP_COMMIT() asm volatile("cp.async.commit_group;" ::: "memory")
template <int N> static __device__ __forceinline__ void cp_wait() {
    asm volatile("cp.async.wait_group %0;" :: "n"(N) : "memory");
}
static __device__ __forceinline__ uint32_t smem_u32(const void* p) {
    uint32_t a;
    asm("{ .reg .u64 t; cvta.to.shared.u64 t, %1; cvt.u32.u64 %0, t; }"
        : "=r"(a) : "l"(p));
    return a;
}
#define MBAR_INIT(a, c) \
    asm volatile("mbarrier.init.shared.b64 [%0], %1;" :: "r"(a), "r"((uint32_t)(c)) : "memory")
#define MBAR_EXPECT_TX(a, b) \
    asm volatile("mbarrier.arrive.expect_tx.shared.b64 _, [%0], %1;" \
                 :: "r"(a), "r"((uint32_t)(b)) : "memory")
static __device__ __forceinline__ void bulk_g2s(uint32_t dst, const void* src,
                                                uint32_t bytes, uint32_t mbar) {
    asm volatile(
        "cp.async.bulk.shared::cluster.global.mbarrier::complete_tx::bytes "
        "[%0], [%1], %2, [%3];"
        :: "r"(dst), "l"(src), "r"(bytes), "r"(mbar) : "memory");
}
static __device__ __forceinline__ void mbar_wait(uint32_t mbar, uint32_t parity) {
    asm volatile(
        "{\n\t.reg .pred P;\n\t"
        "WL%=:\n\t"
        "mbarrier.try_wait.parity.shared.b64 P, [%0], %1, 0x989680;\n\t"
        "@P bra WD%=;\n\t"
        "bra WL%=;\n\t"
        "WD%=:\n\t}"
        :: "r"(mbar), "r"(parity) : "memory");
}
static __device__ __forceinline__ void mma_f16(float* c, const uint32_t* a,
                                               uint32_t b0, uint32_t b1) {
    asm volatile(
        "mma.sync.aligned.m16n8k16.row.col.f32.f16.f16.f32 "
        "{%0,%1,%2,%3}, {%4,%5,%6,%7}, {%8,%9}, {%0,%1,%2,%3};"
        : "+f"(c[0]), "+f"(c[1]), "+f"(c[2]), "+f"(c[3])
        : "r"(a[0]), "r"(a[1]), "r"(a[2]), "r"(a[3]), "r"(b0), "r"(b1));
}
static __device__ __forceinline__ void ldsm4(uint32_t* r, uint32_t addr) {
    asm volatile("ldmatrix.sync.aligned.m8n8.x4.shared.b16 {%0,%1,%2,%3}, [%4];"
                 : "=r"(r[0]), "=r"(r[1]), "=r"(r[2]), "=r"(r[3]) : "r"(addr));
}
static __device__ __forceinline__ void split2(float v, __half& h, __half& l) {
    h = __float2half_rn(v);
    l = __float2half_rn(v - __half2float(h));
}

// ---------------------------------------------------------------------------
// Compensated inner loop, one 32-ci chunk.
// FULL=true (dense): 3 terms, B row pitch BP with chunk at cc*CCMUL, lo at +64.
// FULL=false (sparse): 2 terms, hi-only B tile.
// A stage: 128 rows x 128 B, per-row swizzle (sw0 / sw1).
// ---------------------------------------------------------------------------
template <bool FULL, int BP, int CCMUL>
static __device__ __forceinline__ void gemm_chunk_p(uint32_t smA, uint32_t smB, int cc,
                                                    int rg, int cg, int lane,
                                                    int sw0, int sw1,
                                                    float acc[2][8][4])
{
    const int arow = lane & 15, asel = (lane >> 4) & 1;
    const int brow = (lane & 7) + ((lane >> 4) & 1) * 8;
    const int bsel = (lane >> 3) & 1;
#pragma unroll
    for (int ks = 0; ks < 2; ks++) {
        uint32_t ar0 = smA + (rg * 32 + arow) * 128;
        uint32_t ar1 = smA + (rg * 32 + 16 + arow) * 128;
        uint32_t baddr = smB + (cg * 64 + brow) * BP + cc * CCMUL + ks * 32 + bsel * 16;
        uint32_t ah[2][4], al[2][4], bf[4][4];
        ldsm4(ah[0], ar0 + 16 * ((2 * ks + asel) ^ sw0));
        ldsm4(ah[1], ar1 + 16 * ((2 * ks + asel) ^ sw1));
        ldsm4(al[0], ar0 + 16 * ((4 + 2 * ks + asel) ^ sw0));
        ldsm4(al[1], ar1 + 16 * ((4 + 2 * ks + asel) ^ sw1));
#pragma unroll
        for (int t = 0; t < 4; t++) ldsm4(bf[t], baddr + t * 16 * BP);
#pragma unroll
        for (int t = 0; t < 4; t++)
#pragma unroll
            for (int h = 0; h < 2; h++) {
                int nt = t * 2 + h;
                mma_f16(acc[0][nt], ah[0], bf[t][2 * h], bf[t][2 * h + 1]);
                mma_f16(acc[1][nt], ah[1], bf[t][2 * h], bf[t][2 * h + 1]);
                mma_f16(acc[0][nt], al[0], bf[t][2 * h], bf[t][2 * h + 1]);
                mma_f16(acc[1][nt], al[1], bf[t][2 * h], bf[t][2 * h + 1]);
            }
        if (FULL) {
#pragma unroll
            for (int t = 0; t < 4; t++) ldsm4(bf[t], baddr + 64 + t * 16 * BP);
#pragma unroll
            for (int t = 0; t < 4; t++)
#pragma unroll
                for (int h = 0; h < 2; h++) {
                    int nt = t * 2 + h;
                    mma_f16(acc[0][nt], ah[0], bf[t][2 * h], bf[t][2 * h + 1]);
                    mma_f16(acc[1][nt], ah[1], bf[t][2 * h], bf[t][2 * h + 1]);
                }
        }
    }
}

// ---------------------------------------------------------------------------
// Merged prepass: blocks [0,191) transpose+split weights; blocks [191,191+nb)
// do the m-count scan + per-k histogram.
// ---------------------------------------------------------------------------
__global__ __launch_bounds__(1024)
void prep_count_kernel(const float* __restrict__ W_res,
                       const float* __restrict__ W_out,
                       const float* __restrict__ Wf1,
                       const float* __restrict__ Wf2,
                       const int* __restrict__ nbr, int n)
{
    const int tid = threadIdx.x, lane = tid & 31, wid = tid >> 5;

    if (blockIdx.x < N_WMAT) {
        __shared__ float t[32][33];
        const int b = blockIdx.x;
        const float* src;
        if (b < 162)       src = W_res + (size_t)b * C * C;
        else if (b < 189)  src = W_out + (size_t)(b - 162) * C * C;
        else if (b == 189) src = Wf1;
        else               src = Wf2;
        __half* dst = g_Wt + ((size_t)b << 15);

        const int j = lane, i0 = wid;   // 32x32 threads
        for (int tile = 0; tile < 16; tile++) {
            const int tr = tile >> 2, tc = tile & 3;
            __syncthreads();
            t[i0][j] = src[(tr * 32 + i0) * C + tc * 32 + j];
            __syncthreads();
            int co = tc * 32 + i0;
            float w = t[j][i0];
            __half h, l; split2(w, h, l);
            size_t o = (size_t)co * 256 + tr * 64 + j;
            dst[o] = h;
            dst[o + 32] = l;
        }
        return;
    }

    // ---- count/scan part ----
    __shared__ int wsum[32];
    __shared__ int s_wk[NSEG * 32];
    const int cb = blockIdx.x - N_WMAT;
    const int m = cb * 1024 + tid;

    unsigned valid27 = 0;
    if (m < n) {
        const int* np = nbr + (size_t)m * KNBR;
#pragma unroll
        for (int k = 0; k < KNBR; k++)
            if (k != 13 && np[k] >= 0) valid27 |= (1u << k);
    }
    int cnt = __popc(valid27);

#pragma unroll
    for (int k = 0; k < KNBR; k++) {
        if (k == 13) continue;
        unsigned ball = __ballot_sync(0xFFFFFFFFu, (valid27 >> k) & 1u);
        if (lane == 0) s_wk[k * 32 + wid] = __popc(ball);
    }

    int v = cnt;
#pragma unroll
    for (int o = 1; o < 32; o <<= 1) {
        int u = __shfl_up_sync(0xFFFFFFFFu, v, o);
        if (lane >= o) v += u;
    }
    if (lane == 31) wsum[wid] = v;
    __syncthreads();
    if (wid == 0) {
        int w = wsum[lane], iv = w;
#pragma unroll
        for (int o = 1; o < 32; o <<= 1) {
            int u = __shfl_up_sync(0xFFFFFFFFu, iv, o);
            if (lane >= o) iv += u;
        }
        wsum[lane] = iv - w;
    }
    __syncthreads();
    int pre = wsum[wid] + v - cnt;
    if (m < n) {
        g_mcnt[m] = (unsigned char)cnt;
        g_mbase[m] = pre;
    }
    if (tid == 1023) g_bsum[cb] = pre + cnt;

    if (wid < NSEG && wid != 13) {
        int t2 = s_wk[wid * 32 + lane];
#pragma unroll
        for (int o = 16; o > 0; o >>= 1) t2 += __shfl_down_sync(0xFFFFFFFFu, t2, o);
        if (lane == 0) g_kcnt[wid * NBMAX + cb] = t2;
    }
}

__global__ __launch_bounds__(1024)
void scan_bsum_kernel(int nb)
{
    __shared__ int s[512];
    const int tid = threadIdx.x, lane = tid & 31, w = tid >> 5;
    int v = 0;
    if (tid < 512) {
        v = (tid < nb) ? g_bsum[tid] : 0;
        s[tid] = v;
    }
    __syncthreads();
    for (int off = 1; off < 512; off <<= 1) {
        int u = (tid < 512 && tid >= off) ? s[tid - off] : 0;
        __syncthreads();
        if (tid < 512) s[tid] += u;
        __syncthreads();
    }
    if (tid < 512 && tid < nb) g_boff[tid] = s[tid] - v;

    if (w < NSEG && w != 13) {
        int run = 0;
        for (int b0 = 0; b0 < nb; b0 += 32) {
            int b = b0 + lane;
            int x = (b < nb) ? g_kcnt[w * NBMAX + b] : 0;
            int inc = x;
#pragma unroll
            for (int o = 1; o < 32; o <<= 1) {
                int u = __shfl_up_sync(0xFFFFFFFFu, inc, o);
                if (lane >= o) inc += u;
            }
            if (b < nb) g_kbase[w * NBMAX + b] = run + inc - x;
            run += __shfl_sync(0xFFFFFFFFu, inc, 31);
        }
        if (lane == 0) g_cnt[w] = (unsigned)run;
    }
    if (tid == 0) g_cnt[13] = 0;
}

__global__ __launch_bounds__(1024)
void emit_pairs_kernel(const int* __restrict__ nbr, int n)
{
    __shared__ int s_wk[NSEG * 32];
    __shared__ int s_kb[NSEG];
    const int tid = threadIdx.x, lane = tid & 31, wid = tid >> 5;
    const int m = blockIdx.x * 1024 + tid;

    unsigned valid27 = 0;
    if (m < n) {
        const int* np = nbr + (size_t)m * KNBR;
#pragma unroll
        for (int k = 0; k < KNBR; k++)
            if (k != 13 && np[k] >= 0) valid27 |= (1u << k);
    }
#pragma unroll
    for (int k = 0; k < KNBR; k++) {
        if (k == 13) continue;
        unsigned ball = __ballot_sync(0xFFFFFFFFu, (valid27 >> k) & 1u);
        if (lane == 0) s_wk[k * 32 + wid] = __popc(ball);
    }
    if (tid < NSEG) s_kb[tid] = (tid != 13) ? g_kbase[tid * NBMAX + blockIdx.x] : 0;
    __syncthreads();

    if (wid < NSEG && wid != 13) {
        int v = s_wk[wid * 32 + lane], orig = v;
#pragma unroll
        for (int o = 1; o < 32; o <<= 1) {
            int u = __shfl_up_sync(0xFFFFFFFFu, v, o);
            if (lane >= o) v += u;
        }
        s_wk[wid * 32 + lane] = v - orig;
    }
    __syncthreads();

    int base = 0;
    if (m < n) base = g_boff[m >> 10] + g_mbase[m];
    const unsigned lt = (1u << lane) - 1u;
    int j = 0;
#pragma unroll
    for (int k = 0; k < KNBR; k++) {
        if (k == 13) continue;
        bool valid = (valid27 >> k) & 1u;
        unsigned ball = __ballot_sync(0xFFFFFFFFu, valid);
        if (valid) {
            int pos = s_kb[k] + s_wk[k * 32 + wid] + __popc(ball & lt);
            if (pos < CAP && base + j < SCR_ROWS) {
                g_pairg[k * CAP + pos] = nbr[(size_t)m * KNBR + k];
                g_slot[k * CAP + pos] = base + j;
            }
            j++;
        }
    }
    if (m < n) g_mbase[m] = base;
}

// ---------------------------------------------------------------------------
// Phase 1 (persistent, B-stationary hi-only, row-bulk TMA gather, 2-term):
// per-k pair GEMM -> fp32 scratch rows (m-sorted slots)
// ---------------------------------------------------------------------------
__global__ __launch_bounds__(256, 2)
void sparse_mma_p(const __half* __restrict__ in, const __half* __restrict__ WtLayer)
{
    const int k = blockIdx.x % NSEG;
    const int c = blockIdx.x / NSEG;
    unsigned cnt = g_cnt[k];
    if (cnt > CAP) cnt = CAP;
    const int ntk = (int)((cnt + TM - 1) / TM);
    const int mytiles = (ntk - c + PSP - 1) / PSP;
    if (mytiles <= 0) return;
    const int total = 4 * mytiles;

    extern __shared__ char smem[];
    const uint32_t sb = smem_u32(smem);
    const int tid = threadIdx.x, wid = tid >> 5, lane = tid & 31;
    const int lr = lane >> 2, lc = lane & 3;
    const int rg = wid & 3, cg = wid >> 2;
    const int arow = lane & 15;

    const uint32_t MB = sb + BFULL_SP;
    int (*s_g)[TM] = (int(*)[TM])(smem + BFULL_SP + 64);
    const uint32_t ABASE = sb + BFULL_SP + 64 + 1024;
    const __half* Wk = WtLayer + ((size_t)k << 15);

    auto tile_base = [&](int tl) { return (c + tl * PSP) * TM; };
    auto vrows = [&](int tl) {
        int v = (int)cnt - tile_base(tl);
        return v > TM ? TM : v;
    };
    auto load_idx = [&](int tl) {
        if (tid < TM) {
            int p = tile_base(tl) + tid;
            s_g[tl & 1][tid] = (p < (int)cnt) ? g_pairg[k * CAP + p] : -1;
        }
    };
    auto issue_bulks = [&](int q) {
        const int tl = q >> 2, cc = q & 3;
        const uint32_t stA = ABASE + (q & 1) * ASTG;
        if (tid < TM) {
            int g = s_g[tl & 1][tid];
            if (g >= 0) {
                bulk_g2s(stA + tid * 128, in + ACT_OFF(g, cc), 128, MB + (q & 1) * 8);
            } else {
                uint4 z = make_uint4(0, 0, 0, 0);
                uint4* row = (uint4*)(smem + BFULL_SP + 64 + 1024 + (q & 1) * ASTG + tid * 128);
#pragma unroll
                for (int i = 0; i < 8; i++) row[i] = z;
            }
        }
    };

    if (tid == 0) { MBAR_INIT(MB, 1); MBAR_INIT(MB + 8, 1); }

    // B load (once): hi-plane halves only, 128 rows x 256 B
#pragma unroll
    for (int i = 0; i < 8; i++) {
        int u = tid + 256 * i;
        int r = u >> 4, piece = u & 15;
        int cc = piece >> 2, p = piece & 3;
        cp_async16_cg(sb + r * BP_SP + cc * 64 + p * 16,
                      Wk + (size_t)r * 256 + cc * 64 + p * 8, true);
    }
    CP_COMMIT();

    load_idx(0);
    if (tid == 0) {
        int vr0 = vrows(0);
        MBAR_EXPECT_TX(MB, (uint32_t)vr0 * 128);
        MBAR_EXPECT_TX(MB + 8, (uint32_t)vr0 * 128);
    }
    __syncthreads();
    issue_bulks(0);
    issue_bulks(1);
    cp_wait<0>();
    __syncthreads();

    float acc[2][8][4];
#pragma unroll
    for (int mt = 0; mt < 2; mt++)
#pragma unroll
        for (int nt = 0; nt < 8; nt++)
#pragma unroll
            for (int j = 0; j < 4; j++) acc[mt][nt][j] = 0.f;

    int sw0 = 0, sw1 = 0;

    for (int jj = 0; jj < total; jj++) {
        const int tl = jj >> 2, buf = tl & 1;
        mbar_wait(MB + (jj & 1) * 8, (jj >> 1) & 1);
        if ((jj & 3) == 0) {
            sw0 = s_g[buf][rg * 32 + arow] & 7;
            sw1 = s_g[buf][rg * 32 + 16 + arow] & 7;
        }
        gemm_chunk_p<false, BP_SP, 64>(ABASE + (jj & 1) * ASTG, sb, jj & 3,
                                       rg, cg, lane, sw0, sw1, acc);
        if ((jj & 3) == 0 && tl + 1 < mytiles) load_idx(tl + 1);

        if ((jj & 3) == 3) {
            const int base = tile_base(tl);
#pragma unroll
            for (int mt = 0; mt < 2; mt++) {
#pragma unroll
                for (int hf = 0; hf < 2; hf++) {
                    int pr = rg * 32 + mt * 16 + hf * 8 + lr;
                    if (base + pr < (int)cnt) {
                        int slot = g_slot[k * CAP + base + pr];
                        if (slot >= 0) {
                            float* op = g_scr + (size_t)slot * C + cg * 64 + lc * 2;
#pragma unroll
                            for (int nt = 0; nt < 8; nt++)
                                *(float2*)(op + nt * 8) =
                                    make_float2(acc[mt][nt][hf * 2 + 0],
                                                acc[mt][nt][hf * 2 + 1]);
                        }
                    }
                }
            }
#pragma unroll
            for (int mt = 0; mt < 2; mt++)
#pragma unroll
                for (int nt = 0; nt < 8; nt++)
#pragma unroll
                    for (int j = 0; j < 4; j++) acc[mt][nt][j] = 0.f;
        }

        if (jj + 2 < total && tid == 0)
            MBAR_EXPECT_TX(MB + (jj & 1) * 8, (uint32_t)vrows((jj + 2) >> 2) * 128);
        __syncthreads();
        if (jj + 2 < total) issue_bulks(jj + 2);
    }
}

// ---------------------------------------------------------------------------
// Phase 2 (persistent, B-stationary, bulk-copy A, 3-term):
// dense self-term GEMM + fused combine epilogue
// ---------------------------------------------------------------------------
__global__ __launch_bounds__(256, 2)
void dense_mma_p(const __half* __restrict__ in, __half* __restrict__ outAct,
                 const __half* __restrict__ Wk, const float* __restrict__ bias,
                 const __half* __restrict__ resid, int relu, int sparse,
                 int n, int ntiles)
{
    const int mytiles = (ntiles - (int)blockIdx.x + (int)gridDim.x - 1) / (int)gridDim.x;
    if (mytiles <= 0) return;
    const int total = 4 * mytiles;

    extern __shared__ char smem[];
    const uint32_t sb = smem_u32(smem);
    const int tid = threadIdx.x, wid = tid >> 5, lane = tid & 31;
    const int lr = lane >> 2, lc = lane & 3;
    const int rg = wid & 3, cg = wid >> 2;
    const int arow = lane & 15;
    const int swd = arow & 7;
    const uint32_t MB = sb + BFULL;
    const uint32_t ABASE = sb + BFULL + 64;

    if (tid == 0) { MBAR_INIT(MB, 1); MBAR_INIT(MB + 8, 1); }
    __syncthreads();

    auto produceA = [&](int jj) {
        if (tid == 0) {
            const int tl = jj >> 2, cc = jj & 3;
            const int row0 = ((int)blockIdx.x + tl * (int)gridDim.x) * TM;
            uint32_t mb = MB + (jj & 1) * 8;
            MBAR_EXPECT_TX(mb, ASTG);
            bulk_g2s(ABASE + (jj & 1) * ASTG, in + ACT_OFF(row0, cc), ASTG, mb);
        }
    };

    // B load (once): full hi+lo
#pragma unroll
    for (int i = 0; i < 16; i++) {
        int u = tid + 256 * i;
        int r = u >> 5, q = u & 31;
        cp_async16_cg(sb + r * BPITCH + q * 16, Wk + (size_t)r * 256 + q * 8, true);
    }
    CP_COMMIT();

    float acc[2][8][4];
#pragma unroll
    for (int mt = 0; mt < 2; mt++)
#pragma unroll
        for (int nt = 0; nt < 8; nt++)
#pragma unroll
            for (int j = 0; j < 4; j++) acc[mt][nt][j] = 0.f;

    float2 bv[8];
#pragma unroll
    for (int nt = 0; nt < 8; nt++)
        bv[nt] = *(const float2*)(bias + cg * 64 + nt * 8 + lc * 2);

    produceA(0);
    produceA(1);

    for (int jj = 0; jj < total; jj++) {
        mbar_wait(MB + (jj & 1) * 8, (jj >> 1) & 1);
        if (jj == 0) { cp_wait<0>(); __syncthreads(); }
        gemm_chunk_p<true, BPITCH, 128>(ABASE + (jj & 1) * ASTG, sb, jj & 3,
                                        rg, cg, lane, swd, swd, acc);

        if ((jj & 3) == 3) {
            const int row0 = ((int)blockIdx.x + (jj >> 2) * (int)gridDim.x) * TM;
#pragma unroll
            for (int mt = 0; mt < 2; mt++) {
#pragma unroll
                for (int hf = 0; hf < 2; hf++) {
                    int row = row0 + rg * 32 + mt * 16 + hf * 8 + lr;
                    if (row >= n) continue;
                    const int sw = row & 7;
                    float v[8][2];
#pragma unroll
                    for (int nt = 0; nt < 8; nt++) {
                        v[nt][0] = acc[mt][nt][hf * 2 + 0] + bv[nt].x;
                        v[nt][1] = acc[mt][nt][hf * 2 + 1] + bv[nt].y;
                    }
                    if (sparse) {
                        int basem = g_mbase[row];
                        int mc = g_mcnt[row];
                        const float* sp = g_scr + (size_t)basem * C + cg * 64 + lc * 2;
                        for (int j = 0; j < mc; j++) {
#pragma unroll
                            for (int nt = 0; nt < 8; nt++) {
                                float2 sv = *(const float2*)(sp + nt * 8);
                                v[nt][0] += sv.x;
                                v[nt][1] += sv.y;
                            }
                            sp += C;
                        }
                    }
#pragma unroll
                    for (int nt = 0; nt < 8; nt++) {
                        size_t pb = ACT_OFF(row, 2 * cg + (nt >> 2));
                        size_t oh = pb + 8 * ((nt & 3) ^ sw) + lc * 2;
                        size_t ol = pb + 8 * ((4 + (nt & 3)) ^ sw) + lc * 2;
                        float v0 = v[nt][0], v1 = v[nt][1];
                        if (resid) {
                            __half2 rh = *(const __half2*)(resid + oh);
                            __half2 rl = *(const __half2*)(resid + ol);
                            v0 += __half2float(__low2half(rh)) + __half2float(__low2half(rl));
                            v1 += __half2float(__high2half(rh)) + __half2float(__high2half(rl));
                        }
                        if (relu) { v0 = fmaxf(v0, 0.f); v1 = fmaxf(v1, 0.f); }
                        __half h0, l0, h1, l1;
                        split2(v0, h0, l0);
                        split2(v1, h1, l1);
                        *(__half2*)(outAct + oh) = __halves2half2(h0, h1);
                        *(__half2*)(outAct + ol) = __halves2half2(l0, l1);
                    }
                }
            }
#pragma unroll
            for (int mt = 0; mt < 2; mt++)
#pragma unroll
                for (int nt = 0; nt < 8; nt++)
#pragma unroll
                    for (int j = 0; j < 4; j++) acc[mt][nt][j] = 0.f;
        }
        __syncthreads();
        if (jj + 2 < total) produceA(jj + 2);
    }
}

// ---------------------------------------------------------------------------
// Input layer (Cin = 1), sparsity-compacted, 4 channels per lane (float4 W),
// swizzled chunk-plane store. Summation order (ascending k) unchanged.
// ---------------------------------------------------------------------------
__global__ __launch_bounds__(256)
void layer_in_kernel(const float* __restrict__ x, __half* __restrict__ outAct,
                     const float* __restrict__ Win, const float* __restrict__ bin,
                     const int* __restrict__ nbr, int n)
{
    __shared__ float ws[KNBR][C];
    __shared__ float s_val[128][28];
    __shared__ unsigned char s_kk[128][28];
    __shared__ int s_cnt[128];
    const int tid  = threadIdx.x, lane = tid & 31, wid = tid >> 5;
    const int row0 = blockIdx.x * 128;

    for (int f = tid; f < KNBR * C; f += 256) ws[f / C][f & (C - 1)] = Win[f];
    if (tid < 128) {
        int row = row0 + tid;
        int j = 0;
        if (row < n) {
            const int* np = nbr + (size_t)row * KNBR;
#pragma unroll
            for (int k = 0; k < KNBR; k++) {
                int g = np[k];
                if (g >= 0) {
                    s_kk[tid][j] = (unsigned char)k;
                    s_val[tid][j] = x[g];
                    j++;
                }
            }
        }
        s_cnt[tid] = j;
    }
    __syncthreads();

    // warp wid owns rows [wid*16, wid*16+16); lane owns channels 4*lane..+3
    const int c = lane * 4;
    const int cc = c >> 5, ci = c & 31;
    const int blk_h = ci >> 3, blk_l = 4 + (ci >> 3);
    const int within = ci & 7;                 // 0 or 4
    const float4 bv = *(const float4*)(bin + c);

    for (int rr = 0; rr < 16; rr++) {
        const int r = wid * 16 + rr;
        const int row = row0 + r;
        if (row >= n) continue;
        float4 a = bv;
        const int cnt = s_cnt[r];
        for (int j = 0; j < cnt; j++) {
            float val = s_val[r][j];
            int k = s_kk[r][j];
            float4 wv = *(const float4*)(&ws[k][c]);
            a.x += val * wv.x;
            a.y += val * wv.y;
            a.z += val * wv.z;
            a.w += val * wv.w;
        }
        a.x = fmaxf(a.x, 0.f); a.y = fmaxf(a.y, 0.f);
        a.z = fmaxf(a.z, 0.f); a.w = fmaxf(a.w, 0.f);
        __half h0, l0, h1, l1, h2, l2, h3, l3;
        split2(a.x, h0, l0); split2(a.y, h1, l1);
        split2(a.z, h2, l2); split2(a.w, h3, l3);
        const int sw = row & 7;
        size_t pb = ACT_OFF(row, cc);
        __half2* ph = (__half2*)(outAct + pb + 8 * (blk_h ^ sw) + within);
        __half2* pl = (__half2*)(outAct + pb + 8 * (blk_l ^ sw) + within);
        ph[0] = __halves2half2(h0, h1);
        ph[1] = __halves2half2(h2, h3);
        pl[0] = __halves2half2(l0, l1);
        pl[1] = __halves2half2(l2, l3);
    }
}

// ---------------------------------------------------------------------------
// Final layer (reads swizzled act)
// ---------------------------------------------------------------------------
__global__ __launch_bounds__(256)
void final_kernel(const __half* __restrict__ act, float* __restrict__ out,
                  const float* __restrict__ Wf3, const float* __restrict__ bf3, int n)
{
    __shared__ float hs[64][C + 1];
    __shared__ float wl[C * 3];
    __shared__ float bl[3];
    const int tid  = threadIdx.x;
    const int row0 = blockIdx.x * 64;

    for (int flat = tid; flat < 64 * C / 2; flat += 256) {
        int r = flat >> 6, q = flat & 63;
        int row = row0 + r;
        int col = q * 2;
        float v0 = 0.f, v1 = 0.f;
        if (row < n) {
            const int sw = row & 7;
            const int cc = col >> 5, ci = col & 31;
            size_t pb = ACT_OFF(row, cc);
            __half2 rh = *(const __half2*)(act + pb + 8 * ((ci >> 3) ^ sw) + (ci & 7));
            __half2 rl = *(const __half2*)(act + pb + 8 * ((4 + (ci >> 3)) ^ sw) + (ci & 7));
            v0 = __half2float(__low2half(rh)) + __half2float(__low2half(rl));
            v1 = __half2float(__high2half(rh)) + __half2float(__high2half(rl));
        }
        hs[r][col] = v0;
        hs[r][col + 1] = v1;
    }
    for (int flat = tid; flat < C * 3; flat += 256) wl[flat] = Wf3[flat];
    if (tid < 3) bl[tid] = bf3[tid];
    __syncthreads();

    if (tid < 192) {
        int r = tid / 3, j = tid % 3;
        int row = row0 + r;
        if (row < n) {
            float acc = bl[j];
#pragma unroll 4
            for (int ci = 0; ci < C; ci++) acc += hs[r][ci] * wl[ci * 3 + j];
            out[(size_t)row * 3 + j] = acc;
        }
    }
}

// ---------------------------------------------------------------------------
extern "C" void kernel_launch(void* const* d_in, const int* in_sizes, int n_in,
                              void* d_out, int out_size)
{
    const float* x_feat = (const float*)d_in[0];
    const float* W_in   = (const float*)d_in[1];
    const float* b_in   = (const float*)d_in[2];
    const float* W_res  = (const float*)d_in[3];
    const float* b_res  = (const float*)d_in[4];
    const float* W_out  = (const float*)d_in[5];
    const float* b_out  = (const float*)d_in[6];
    const float* Wf1    = (const float*)d_in[7];
    const float* bf1    = (const float*)d_in[8];
    const float* Wf2    = (const float*)d_in[9];
    const float* bf2    = (const float*)d_in[10];
    const float* Wf3    = (const float*)d_in[11];
    const float* bf3    = (const float*)d_in[12];
    const int*   nbr    = (const int*)d_in[13];
    float* out = (float*)d_out;

    const int n = in_sizes[0];

    __half *actA, *actB, *Wt;
    cudaGetSymbolAddress((void**)&actA, g_actA);
    cudaGetSymbolAddress((void**)&actB, g_actB);
    cudaGetSymbolAddress((void**)&Wt, g_Wt);

    cudaFuncSetAttribute(sparse_mma_p, cudaFuncAttributeMaxDynamicSharedMemorySize, SP5_SMEM);
    cudaFuncSetAttribute(dense_mma_p, cudaFuncAttributeMaxDynamicSharedMemorySize, DN3_SMEM);

    const int ntiles = (n + TM - 1) / TM;
    const int gridM  = (n + 127) / 128;
    const int gridD  = ntiles < GDMAX ? ntiles : GDMAX;
    const int gridS  = NSEG * PSP;
    const int nb     = (n + 1023) / 1024;

    prep_count_kernel<<<N_WMAT + nb, 1024>>>(W_res, W_out, Wf1, Wf2, nbr, n);
    scan_bsum_kernel<<<1, 1024>>>(nb);
    emit_pairs_kernel<<<nb, 1024>>>(nbr, n);

    layer_in_kernel<<<gridM, 256>>>(x_feat, actA, W_in, b_in, nbr, n);

    for (int i = 0; i < 3; i++) {
        const __half* W0 = Wt + ((size_t)((i * 2 + 0) * KNBR) << 15);
        const __half* W1 = Wt + ((size_t)((i * 2 + 1) * KNBR) << 15);
        const float* b0 = b_res + (size_t)(i * 2 + 0) * C;
        const float* b1 = b_res + (size_t)(i * 2 + 1) * C;
        sparse_mma_p<<<gridS, 256, SP5_SMEM>>>(actA, W0);
        dense_mma_p<<<gridD, 256, DN3_SMEM>>>(actA, actB, W0 + ((size_t)13 << 15),
                                              b0, nullptr, 1, 1, n, ntiles);
        sparse_mma_p<<<gridS, 256, SP5_SMEM>>>(actB, W1);
        dense_mma_p<<<gridD, 256, DN3_SMEM>>>(actB, actA, W1 + ((size_t)13 << 15),
                                              b1, actA, 0, 1, n, ntiles);
    }

    const __half* Wo = Wt + ((size_t)(6 * KNBR) << 15);
    sparse_mma_p<<<gridS, 256, SP5_SMEM>>>(actA, Wo);
    dense_mma_p<<<gridD, 256, DN3_SMEM>>>(actA, actB, Wo + ((size_t)13 << 15),
                                          b_out, nullptr, 0, 1, n, ntiles);

    dense_mma_p<<<gridD, 256, DN3_SMEM>>>(actB, actA, Wt + ((size_t)189 << 15),
                                          bf1, nullptr, 1, 0, n, ntiles);
    dense_mma_p<<<gridD, 256, DN3_SMEM>>>(actA, actB, Wt + ((size_t)190 << 15),
                                          bf2, nullptr, 1, 0, n, ntiles);

    final_kernel<<<(n + 63) / 64, 256>>>(actB, out, Wf3, bf3, n);
}